// round 8
// baseline (speedup 1.0000x reference)
#include <cuda_runtime.h>
#include <cuda_bf16.h>
#include <math.h>
#include <stdint.h>

// ---------------- problem constants ----------------
#define BATCH 128
#define CH    3
#define HIM   224
#define PGRID 14
#define NP    196
#define PATCH 16
#define IN_D  768
#define DMODEL 256
#define NHEAD 8
#define DH    32
#define NLAYER 4
#define SEQ   197
#define OUTC  1000
#define LNEPS 1e-5f

typedef __nv_bfloat16 bf16;

// ---------------- scratch (device globals) ----------------
__device__ bf16  g_patches_b[BATCH * NP * IN_D];
__device__ float g_X [BATCH * SEQ * DMODEL];
__device__ bf16  g_x1b[BATCH * SEQ * DMODEL];
__device__ bf16  g_qb [BATCH * SEQ * DMODEL];             // [n,h,s,e]
__device__ bf16  g_kb [BATCH * SEQ * DMODEL];
__device__ bf16  g_vb [BATCH * SEQ * DMODEL];
__device__ bf16  g_ob [BATCH * SEQ * DMODEL];             // [n,s,d]
__device__ bf16  g_h1b[BATCH * SEQ * 4 * DMODEL];
__device__ float g_pe[SEQ * DMODEL];
__device__ bf16  g_wmapb [DMODEL * IN_D];
__device__ bf16  g_wlastb[NLAYER * DMODEL * DMODEL];
__device__ bf16  g_wmlp1b[NLAYER * 4 * DMODEL * DMODEL];
__device__ bf16  g_wmlp2b[NLAYER * 4 * DMODEL * DMODEL];
__device__ bf16  g_wqb[NLAYER * NHEAD * DH * DH];
__device__ bf16  g_wkb[NLAYER * NHEAD * DH * DH];
__device__ bf16  g_wvb[NLAYER * NHEAD * DH * DH];

// ---------------- fp32 -> bf16 convert ----------------
__global__ void cvt_kernel(const float* __restrict__ src, bf16* __restrict__ dst, int n)
{
    int i = (blockIdx.x * 256 + threadIdx.x) * 4;
    if (i >= n) return;
    float4 v = *(const float4*)(src + i);
    __nv_bfloat162 p0 = __floats2bfloat162_rn(v.x, v.y);
    __nv_bfloat162 p1 = __floats2bfloat162_rn(v.z, v.w);
    uint2 o;
    o.x = *reinterpret_cast<uint32_t*>(&p0);
    o.y = *reinterpret_cast<uint32_t*>(&p1);
    *reinterpret_cast<uint2*>(dst + i) = o;
}

// ---------------- patch extraction (writes bf16) ----------------
__global__ void patch_kernel(const float* __restrict__ img, bf16* __restrict__ out)
{
    int idx = blockIdx.x * 256 + threadIdx.x;
    if (idx >= BATCH * NP * IN_D) return;
    int i = idx % IN_D;
    int p = (idx / IN_D) % NP;
    int n = idx / (IN_D * NP);
    int c   = i >> 8;
    int r   = (i >> 4) & 15;
    int col = i & 15;
    int py = p / PGRID, px = p % PGRID;
    out[idx] = __float2bfloat16(
        img[(((size_t)n * CH + c) * HIM + py * PATCH + r) * HIM + px * PATCH + col]);
}

// ---------------- positional encoding (fp64) ----------------
__global__ void pe_kernel(float* __restrict__ pe)
{
    int i = blockIdx.x * 256 + threadIdx.x;
    if (i >= SEQ * DMODEL) return;
    int s = i / DMODEL, d = i % DMODEL;
    double expo = (double)(2 * (d / 2)) / (double)DMODEL;
    double ang  = (double)s / pow(10000.0, expo);
    pe[i] = (float)((d & 1) ? cos(ang) : sin(ang));
}

// ---------------- cls rows: X[n][0][:] = cls + pe[0] ------------------------
__global__ void cls_kernel(const float* __restrict__ cls,
                           const float* __restrict__ pe,
                           float* __restrict__ X)
{
    int i = blockIdx.x * 256 + threadIdx.x;
    if (i >= BATCH * DMODEL) return;
    int d = i % DMODEL;
    int n = i / DMODEL;
    X[(size_t)n * SEQ * DMODEL + d] = cls[d] + pe[d];
}

// ---------------- bf16 MMA / ldmatrix helpers -------------------------------
__device__ __forceinline__ void mma_bf16(float* c, const uint32_t* a, const uint32_t* b)
{
    asm volatile(
        "mma.sync.aligned.m16n8k16.row.col.f32.bf16.bf16.f32 "
        "{%0,%1,%2,%3}, {%4,%5,%6,%7}, {%8,%9}, {%0,%1,%2,%3};"
        : "+f"(c[0]), "+f"(c[1]), "+f"(c[2]), "+f"(c[3])
        : "r"(a[0]), "r"(a[1]), "r"(a[2]), "r"(a[3]), "r"(b[0]), "r"(b[1]));
}

#define LDSM4(r0, r1, r2, r3, addr) \
    asm volatile("ldmatrix.sync.aligned.m8n8.x4.shared.b16 {%0,%1,%2,%3}, [%4];" \
                 : "=r"(r0), "=r"(r1), "=r"(r2), "=r"(r3) : "r"(addr))

#define CP16(dst, src) asm volatile("cp.async.cg.shared.global [%0], [%1], 16;\n" :: "r"(dst), "l"(src))
#define CP_COMMIT()    asm volatile("cp.async.commit_group;\n" ::)
#define CP_WAIT1()     asm volatile("cp.async.wait_group 1;\n" ::)
#define CP_WAIT0()     asm volatile("cp.async.wait_group 0;\n" ::)

// ---------------- bf16 tensor-core GEMM, 128x128 tile, ldmatrix -------------
// (round-6 proven config: 8 warps 4m x 2n, 2 CTA/SM, 4 warps/SMSP)
#define STR 36                      // u32 stride per 64-bf16 row (pad 4) = 144B
#define ABUF (128 * STR)            // u32
#define GEMM_SMEM (4 * ABUF * 4)    // A0,A1,B0,B1

template<int ACT, bool HASRES, bool OUTBF, bool ADDPE>
__global__ void __launch_bounds__(256) gemm_bf(const bf16* __restrict__ A,
                                               const bf16* __restrict__ W,
                                               const float* __restrict__ bias,
                                               const float* __restrict__ res,
                                               const float* __restrict__ pe,
                                               void* __restrict__ Cout,
                                               int M, int N, int K)
{
    extern __shared__ uint32_t sm_[];
    const uint32_t smem_byte = (uint32_t)__cvta_generic_to_shared(sm_);

    const int t    = threadIdx.x;
    const int warp = t >> 5, lane = t & 31;
    const int g    = lane >> 2, q4 = lane & 3;
    const int warp_m = (warp >> 1) * 32;
    const int warp_n = (warp & 1) * 64;
    const int row0 = blockIdx.y * 128, col0 = blockIdx.x * 128;

    float acc[2][8][4];
#pragma unroll
    for (int mi = 0; mi < 2; mi++)
#pragma unroll
        for (int ni = 0; ni < 8; ni++)
#pragma unroll
            for (int e = 0; e < 4; e++) acc[mi][ni][e] = 0.f;

    auto stage = [&](int k0, int buf) {
        uint32_t abase = smem_byte + buf * (ABUF * 4);
        uint32_t bbase = smem_byte + (2 + buf) * (ABUF * 4);
#pragma unroll
        for (int i = 0; i < 4; i++) {
            int c = t + i * 256;
            int r = c >> 3, co = c & 7;
            CP16(abase + (r * STR + co * 4) * 4, A + (size_t)(row0 + r) * K + k0 + co * 8);
            CP16(bbase + (r * STR + co * 4) * 4, W + (size_t)(col0 + r) * K + k0 + co * 8);
        }
        CP_COMMIT();
    };

    uint32_t a_addr[2][2], b_addr[2][4];
    {
        int ar = warp_m + (lane & 15);
        int ab = (lane >> 4) * 16;
        int br = warp_n + ((lane >> 4) & 1) * 8 + (lane & 7);
        int bb = ((lane >> 3) & 1) * 16;
#pragma unroll
        for (int buf = 0; buf < 2; buf++) {
            uint32_t abase = smem_byte + buf * (ABUF * 4);
            uint32_t bbase = smem_byte + (2 + buf) * (ABUF * 4);
#pragma unroll
            for (int mi = 0; mi < 2; mi++)
                a_addr[buf][mi] = abase + (ar + mi * 16) * (STR * 4) + ab;
#pragma unroll
            for (int nj = 0; nj < 4; nj++)
                b_addr[buf][nj] = bbase + (br + nj * 16) * (STR * 4) + bb;
        }
    }

    const int KT = K >> 6;
    stage(0, 0);

    for (int kt = 0; kt < KT; kt++) {
        const int cur = kt & 1;
        if (kt + 1 < KT) { stage((kt + 1) << 6, cur ^ 1); CP_WAIT1(); }
        else             { CP_WAIT0(); }
        __syncthreads();

#pragma unroll
        for (int ks = 0; ks < 4; ks++) {
            const uint32_t kb = ks * 32;
            uint32_t af[2][4];
            LDSM4(af[0][0], af[0][1], af[0][2], af[0][3], a_addr[cur][0] + kb);
            LDSM4(af[1][0], af[1][1], af[1][2], af[1][3], a_addr[cur][1] + kb);
            uint32_t bf_[8][2];
#pragma unroll
            for (int nj = 0; nj < 4; nj++)
                LDSM4(bf_[2 * nj][0], bf_[2 * nj][1], bf_[2 * nj + 1][0], bf_[2 * nj + 1][1],
                      b_addr[cur][nj] + kb);
#pragma unroll
            for (int mi = 0; mi < 2; mi++)
#pragma unroll
                for (int ni = 0; ni < 8; ni++)
                    mma_bf16(acc[mi][ni], af[mi], bf_[ni]);
        }
        __syncthreads();
    }

    // epilogue
#pragma unroll
    for (int mi = 0; mi < 2; mi++) {
        int ra = row0 + warp_m + mi * 16 + g;
        int rb = ra + 8;
        size_t orow_a, orow_b;
        if (ADDPE) {
            orow_a = (size_t)(ra / NP) * SEQ + (ra % NP) + 1;
            orow_b = (size_t)(rb / NP) * SEQ + (rb % NP) + 1;
        } else {
            orow_a = ra; orow_b = rb;
        }
        int pes_a = ADDPE ? ((ra % NP) + 1) : 0;
        int pes_b = ADDPE ? ((rb % NP) + 1) : 0;
#pragma unroll
        for (int ni = 0; ni < 8; ni++) {
            int col = col0 + warp_n + ni * 8 + q4 * 2;
            float b0 = bias[col], b1 = bias[col + 1];
            float v00 = acc[mi][ni][0] + b0, v01 = acc[mi][ni][1] + b1;
            float v10 = acc[mi][ni][2] + b0, v11 = acc[mi][ni][3] + b1;
            if (ACT == 1) {
                v00 = 0.5f * v00 * (1.0f + erff(v00 * 0.70710678118654752f));
                v01 = 0.5f * v01 * (1.0f + erff(v01 * 0.70710678118654752f));
                v10 = 0.5f * v10 * (1.0f + erff(v10 * 0.70710678118654752f));
                v11 = 0.5f * v11 * (1.0f + erff(v11 * 0.70710678118654752f));
            }
            if (HASRES) {
                float2 r0 = *(const float2*)(res + orow_a * N + col);
                float2 r1 = *(const float2*)(res + orow_b * N + col);
                v00 += r0.x; v01 += r0.y; v10 += r1.x; v11 += r1.y;
            }
            if (ADDPE) {
                float2 p0 = *(const float2*)(pe + (size_t)pes_a * DMODEL + col);
                float2 p1 = *(const float2*)(pe + (size_t)pes_b * DMODEL + col);
                v00 += p0.x; v01 += p0.y; v10 += p1.x; v11 += p1.y;
            }
            if (OUTBF) {
                bf16* C = (bf16*)Cout;
                __nv_bfloat162 p0 = __floats2bfloat162_rn(v00, v01);
                __nv_bfloat162 p1 = __floats2bfloat162_rn(v10, v11);
                *reinterpret_cast<uint32_t*>(C + orow_a * N + col) = *reinterpret_cast<uint32_t*>(&p0);
                *reinterpret_cast<uint32_t*>(C + orow_b * N + col) = *reinterpret_cast<uint32_t*>(&p1);
            } else {
                float* C = (float*)Cout;
                *(float2*)(C + orow_a * N + col) = make_float2(v00, v01);
                *(float2*)(C + orow_b * N + col) = make_float2(v10, v11);
            }
        }
    }
}

// ---------------- LayerNorm: warp per row, bf16 out (LN2 only) --------------
__global__ void ln_kernel(const float* __restrict__ x,
                          const float* __restrict__ g,
                          const float* __restrict__ b,
                          bf16* __restrict__ y)
{
    const int row  = blockIdx.x * 8 + (threadIdx.x >> 5);
    const int lane = threadIdx.x & 31;
    const float4* xp = (const float4*)(x + (size_t)row * DMODEL);
    float4 u = xp[lane * 2], w = xp[lane * 2 + 1];

    float s = u.x + u.y + u.z + u.w + w.x + w.y + w.z + w.w;
#pragma unroll
    for (int off = 16; off; off >>= 1) s += __shfl_xor_sync(0xffffffffu, s, off);
    float mu = s * (1.f / DMODEL);

    float d0 = u.x - mu, d1 = u.y - mu, d2 = u.z - mu, d3 = u.w - mu;
    float d4 = w.x - mu, d5 = w.y - mu, d6 = w.z - mu, d7 = w.w - mu;
    float s2 = d0*d0 + d1*d1 + d2*d2 + d3*d3 + d4*d4 + d5*d5 + d6*d6 + d7*d7;
#pragma unroll
    for (int off = 16; off; off >>= 1) s2 += __shfl_xor_sync(0xffffffffu, s2, off);
    float inv = rsqrtf(s2 * (1.f / DMODEL) + LNEPS);

    const float4* gp = (const float4*)g;
    const float4* bp = (const float4*)b;
    float4 g0 = gp[lane * 2], g1 = gp[lane * 2 + 1];
    float4 b0 = bp[lane * 2], b1 = bp[lane * 2 + 1];

    __nv_bfloat162 p0 = __floats2bfloat162_rn(d0 * inv * g0.x + b0.x, d1 * inv * g0.y + b0.y);
    __nv_bfloat162 p1 = __floats2bfloat162_rn(d2 * inv * g0.z + b0.z, d3 * inv * g0.w + b0.w);
    __nv_bfloat162 p2 = __floats2bfloat162_rn(d4 * inv * g1.x + b1.x, d5 * inv * g1.y + b1.y);
    __nv_bfloat162 p3 = __floats2bfloat162_rn(d6 * inv * g1.z + b1.z, d7 * inv * g1.w + b1.w);
    uint4 o;
    o.x = *reinterpret_cast<uint32_t*>(&p0);
    o.y = *reinterpret_cast<uint32_t*>(&p1);
    o.z = *reinterpret_cast<uint32_t*>(&p2);
    o.w = *reinterpret_cast<uint32_t*>(&p3);
    *reinterpret_cast<uint4*>(y + (size_t)row * DMODEL + lane * 8) = o;
}

// ---------------- fused LN1 + QKV projection ---------------------------------
// grid (BATCH, ceil(SEQ/8)), 256 threads = 8 warps (warp = head for projection,
// warp = row for LN). Weights staged transposed [h][d][e] in bf16 smem.
#define QKV_SMEM (8 * DMODEL * 4 + 3 * NHEAD * DH * DH * 2)   // 8KB + 48KB

__global__ void __launch_bounds__(256) lnqkv_kernel(
    const float* __restrict__ X,
    const float* __restrict__ g, const float* __restrict__ b,
    const bf16* __restrict__ wqb, const float* __restrict__ bq,
    const bf16* __restrict__ wkb, const float* __restrict__ bk,
    const bf16* __restrict__ wvb, const float* __restrict__ bv,
    bf16* __restrict__ q, bf16* __restrict__ k, bf16* __restrict__ v)
{
    extern __shared__ uint8_t qsm[];
    float* xn = (float*)qsm;                               // [8][256] fp32
    bf16* wsq = (bf16*)(qsm + 8 * DMODEL * 4);             // [h][d][e]
    bf16* wsk = wsq + NHEAD * DH * DH;
    bf16* wsv = wsk + NHEAD * DH * DH;

    const int n = blockIdx.x;
    const int t = threadIdx.x, warp = t >> 5, lane = t & 31;

    // stage weights transposed (e fastest for conflict-free reads)
    for (int i = t; i < NHEAD * DH * DH; i += 256) {
        int h = i >> 10, e = (i >> 5) & 31, d = i & 31;
        int o = h * 1024 + d * 32 + e;
        wsq[o] = wqb[i]; wsk[o] = wkb[i]; wsv[o] = wvb[i];
    }

    // LN: warp per row
    const int s = blockIdx.y * 8 + warp;
    if (s < SEQ) {
        const float4* xp = (const float4*)(X + ((size_t)n * SEQ + s) * DMODEL);
        float4 u = xp[lane * 2], w2 = xp[lane * 2 + 1];
        float sm = u.x + u.y + u.z + u.w + w2.x + w2.y + w2.z + w2.w;
#pragma unroll
        for (int off = 16; off; off >>= 1) sm += __shfl_xor_sync(0xffffffffu, sm, off);
        float mu = sm * (1.f / DMODEL);
        float d0 = u.x - mu, d1 = u.y - mu, d2 = u.z - mu, d3 = u.w - mu;
        float d4 = w2.x - mu, d5 = w2.y - mu, d6 = w2.z - mu, d7 = w2.w - mu;
        float s2 = d0*d0 + d1*d1 + d2*d2 + d3*d3 + d4*d4 + d5*d5 + d6*d6 + d7*d7;
#pragma unroll
        for (int off = 16; off; off >>= 1) s2 += __shfl_xor_sync(0xffffffffu, s2, off);
        float inv = rsqrtf(s2 * (1.f / DMODEL) + LNEPS);
        const float4* gp = (const float4*)g;
        const float4* bp = (const float4*)b;
        float4 g0 = gp[lane * 2], g1 = gp[lane * 2 + 1];
        float4 b0 = bp[lane * 2], b1 = bp[lane * 2 + 1];
        float* xr = xn + warp * DMODEL + lane * 8;
        xr[0] = d0 * inv * g0.x + b0.x; xr[1] = d1 * inv * g0.y + b0.y;
        xr[2] = d2 * inv * g0.z + b0.z; xr[3] = d3 * inv * g0.w + b0.w;
        xr[4] = d4 * inv * g1.x + b1.x; xr[5] = d5 * inv * g1.y + b1.y;
        xr[6] = d6 * inv * g1.z + b1.z; xr[7] = d7 * inv * g1.w + b1.w;
    }
    __syncthreads();

    // projection: thread = (head = warp, e = lane), loop 8 rows
    const int h = warp, e = lane;
    const float bqv = bq[h * DH + e], bkv = bk[h * DH + e], bvv = bv[h * DH + e];
    const bf16* wq_h = wsq + h * 1024;
    const bf16* wk_h = wsk + h * 1024;
    const bf16* wv_h = wsv + h * 1024;

#pragma unroll
    for (int r = 0; r < 8; r++) {
        int sr = blockIdx.y * 8 + r;
        if (sr >= SEQ) break;
        const float* xr = xn + r * DMODEL + h * DH;
        float aq = bqv, ak = bkv, av = bvv;
#pragma unroll
        for (int d = 0; d < 32; d++) {
            float xd = xr[d];
            aq += xd * __bfloat162float(wq_h[d * 32 + e]);
            ak += xd * __bfloat162float(wk_h[d * 32 + e]);
            av += xd * __bfloat162float(wv_h[d * 32 + e]);
        }
        size_t oidx = (((size_t)n * NHEAD + h) * SEQ + sr) * DH + e;
        q[oidx] = __float2bfloat16(aq);
        k[oidx] = __float2bfloat16(ak);
        v[oidx] = __float2bfloat16(av);
    }
}

// ---------------- tensor-core flash attention per (n,h) ---------------------
#define SPAD 224
#define NKT  7
#define KSTR 20
#define VSTR 116

__global__ void __launch_bounds__(224) attn_tc(const bf16* __restrict__ q,
                                               const bf16* __restrict__ k,
                                               const bf16* __restrict__ v,
                                               bf16* __restrict__ o)
{
    __shared__ uint32_t Ks[SPAD * KSTR];
    __shared__ uint32_t VT[32 * VSTR];

    const int nh = blockIdx.x;
    const int n = nh / NHEAD, h = nh % NHEAD;
    const int t = threadIdx.x, warp = t >> 5, lane = t & 31;
    const int g = lane >> 2, q4 = lane & 3;
    const size_t base = (size_t)nh * SEQ * DH;
    const uint32_t* q32 = (const uint32_t*)(q + base);
    const uint32_t* k32 = (const uint32_t*)(k + base);
    const uint32_t* v32 = (const uint32_t*)(v + base);

    for (int i = t; i < SPAD * 16; i += 224) {
        int r = i >> 4, c = i & 15;
        Ks[r * KSTR + c] = (r < SEQ) ? k32[r * 16 + c] : 0u;
    }
    // V transpose staging, vectorized u32 loads
    bf16* VT16 = (bf16*)VT;
    for (int i = t; i < SPAD * 16; i += 224) {
        int tt = i >> 4, c = i & 15;
        uint32_t val = (tt < SEQ) ? v32[tt * 16 + c] : 0u;
        __nv_bfloat162 pr = *reinterpret_cast<__nv_bfloat162*>(&val);
        VT16[(2 * c)     * (VSTR * 2) + tt] = pr.x;
        VT16[(2 * c + 1) * (VSTR * 2) + tt] = pr.y;
    }
    __syncthreads();

    const int qbase = warp * 32;
    uint32_t qf[2][2][4];
#pragma unroll
    for (int mi = 0; mi < 2; mi++) {
        int r0 = qbase + mi * 16 + g, r1 = r0 + 8;
        bool v0 = r0 < SEQ, v1 = r1 < SEQ;
#pragma unroll
        for (int ks = 0; ks < 2; ks++) {
            qf[mi][ks][0] = v0 ? q32[r0 * 16 + ks * 8 + q4]     : 0u;
            qf[mi][ks][1] = v1 ? q32[r1 * 16 + ks * 8 + q4]     : 0u;
            qf[mi][ks][2] = v0 ? q32[r0 * 16 + ks * 8 + q4 + 4] : 0u;
            qf[mi][ks][3] = v1 ? q32[r1 * 16 + ks * 8 + q4 + 4] : 0u;
        }
    }

    float Oa[2][4][4];
#pragma unroll
    for (int mi = 0; mi < 2; mi++)
#pragma unroll
        for (int ne = 0; ne < 4; ne++)
#pragma unroll
            for (int e = 0; e < 4; e++) Oa[mi][ne][e] = 0.f;
    float m_[2][2] = {{-1e30f, -1e30f}, {-1e30f, -1e30f}};
    float l_[2][2] = {{0.f, 0.f}, {0.f, 0.f}};
    const float scale = 0.17677669529663689f;

    for (int kt = 0; kt < NKT; kt++) {
        float sc[2][4][4];
#pragma unroll
        for (int mi = 0; mi < 2; mi++)
#pragma unroll
            for (int ni = 0; ni < 4; ni++)
#pragma unroll
                for (int e = 0; e < 4; e++) sc[mi][ni][e] = 0.f;

        uint32_t kf[2][4][2];
#pragma unroll
        for (int ks = 0; ks < 2; ks++)
#pragma unroll
            for (int ni = 0; ni < 4; ni++) {
                int r = kt * 32 + ni * 8 + g;
                kf[ks][ni][0] = Ks[r * KSTR + ks * 8 + q4];
                kf[ks][ni][1] = Ks[r * KSTR + ks * 8 + q4 + 4];
            }
#pragma unroll
        for (int mi = 0; mi < 2; mi++)
#pragma unroll
            for (int ni = 0; ni < 4; ni++)
#pragma unroll
                for (int ks = 0; ks < 2; ks++)
                    mma_bf16(sc[mi][ni], qf[mi][ks], kf[ks][ni]);

#pragma unroll
        for (int mi = 0; mi < 2; mi++) {
#pragma unroll
            for (int hf = 0; hf < 2; hf++) {
                float mx = -1e30f;
#pragma unroll
                for (int ni = 0; ni < 4; ni++) {
                    int col = kt * 32 + ni * 8 + q4 * 2;
                    float s0 = (col     < SEQ) ? sc[mi][ni][hf * 2]     * scale : -1e30f;
                    float s1 = (col + 1 < SEQ) ? sc[mi][ni][hf * 2 + 1] * scale : -1e30f;
                    sc[mi][ni][hf * 2]     = s0;
                    sc[mi][ni][hf * 2 + 1] = s1;
                    mx = fmaxf(mx, fmaxf(s0, s1));
                }
                mx = fmaxf(mx, __shfl_xor_sync(0xffffffffu, mx, 1));
                mx = fmaxf(mx, __shfl_xor_sync(0xffffffffu, mx, 2));
                float mnew = fmaxf(m_[mi][hf], mx);
                float f = __expf(m_[mi][hf] - mnew);
                m_[mi][hf] = mnew;
                float rs = 0.f;
#pragma unroll
                for (int ni = 0; ni < 4; ni++) {
                    float p0 = __expf(sc[mi][ni][hf * 2]     - mnew);
                    float p1 = __expf(sc[mi][ni][hf * 2 + 1] - mnew);
                    sc[mi][ni][hf * 2]     = p0;
                    sc[mi][ni][hf * 2 + 1] = p1;
                    rs += p0 + p1;
                }
                rs += __shfl_xor_sync(0xffffffffu, rs, 1);
                rs += __shfl_xor_sync(0xffffffffu, rs, 2);
                l_[mi][hf] = l_[mi][hf] * f + rs;
#pragma unroll
                for (int ne = 0; ne < 4; ne++) {
                    Oa[mi][ne][hf * 2]     *= f;
                    Oa[mi][ne][hf * 2 + 1] *= f;
                }
            }
        }

        uint32_t pa[2][2][4];
#pragma unroll
        for (int mi = 0; mi < 2; mi++)
#pragma unroll
            for (int ks = 0; ks < 2; ks++) {
                __nv_bfloat162 t0 = __floats2bfloat162_rn(sc[mi][2 * ks][0],     sc[mi][2 * ks][1]);
                __nv_bfloat162 t1 = __floats2bfloat162_rn(sc[mi][2 * ks][2],     sc[mi][2 * ks][3]);
                __nv_bfloat162 t2 = __floats2bfloat162_rn(sc[mi][2 * ks + 1][0], sc[mi][2 * ks + 1][1]);
                __nv_bfloat162 t3 = __floats2bfloat162_rn(sc[mi][2 * ks + 1][2], sc[mi][2 * ks + 1][3]);
                pa[mi][ks][0] = *reinterpret_cast<uint32_t*>(&t0);
                pa[mi][ks][1] = *reinterpret_cast<uint32_t*>(&t1);
                pa[mi][ks][2] = *reinterpret_cast<uint32_t*>(&t2);
                pa[mi][ks][3] = *reinterpret_cast<uint32_t*>(&t3);
            }

        uint32_t vf[2][4][2];
#pragma unroll
        for (int ks = 0; ks < 2; ks++)
#pragma unroll
            for (int ne = 0; ne < 4; ne++) {
                int r = ne * 8 + g;
                int cu = kt * 16 + ks * 8 + q4;
                vf[ks][ne][0] = VT[r * VSTR + cu];
                vf[ks][ne][1] = VT[r * VSTR + cu + 4];
            }
#pragma unroll
        for (int mi = 0; mi < 2; mi++)
#pragma unroll
            for (int ne = 0; ne < 4; ne++)
#pragma unroll
                for (int ks = 0; ks < 2; ks++)
                    mma_bf16(Oa[mi][ne], pa[mi][ks], vf[ks][ne]);
    }

#pragma unroll
    for (int mi = 0; mi < 2; mi++) {
#pragma unroll
        for (int hf = 0; hf < 2; hf++) {
            int row = qbase + mi * 16 + hf * 8 + g;
            if (row >= SEQ) continue;
            float inv = 1.f / l_[mi][hf];
            bf16* op = o + ((size_t)n * SEQ + row) * DMODEL + h * DH;
#pragma unroll
            for (int ne = 0; ne < 4; ne++) {
                __nv_bfloat162 p = __floats2bfloat162_rn(Oa[mi][ne][hf * 2] * inv,
                                                         Oa[mi][ne][hf * 2 + 1] * inv);
                *reinterpret_cast<uint32_t*>(op + ne * 8 + q4 * 2) = *reinterpret_cast<uint32_t*>(&p);
            }
        }
    }
}

// ---------------- classification head ---------------------------------------
__global__ void head_kernel(const float* __restrict__ X, const float* __restrict__ w_out,
                            const float* __restrict__ b_out, float* __restrict__ out)
{
    __shared__ float cls_s[DMODEL];
    __shared__ float logits[OUTC];
    __shared__ float red[8];
    const int n = blockIdx.x;
    const int t = threadIdx.x, wid = t >> 5, lane = t & 31;

    cls_s[t] = X[(size_t)n * SEQ * DMODEL + t];
    __syncthreads();

    for (int j = wid; j < OUTC; j += 8) {
        float acc = 0.f;
#pragma unroll
        for (int k = lane; k < DMODEL; k += 32) acc += cls_s[k] * w_out[(size_t)j * DMODEL + k];
#pragma unroll
        for (int off = 16; off; off >>= 1) acc += __shfl_xor_sync(0xffffffffu, acc, off);
        if (lane == 0) logits[j] = acc + b_out[j];
    }
    __syncthreads();

    float mx = -1e30f;
    for (int j = t; j < OUTC; j += 256) mx = fmaxf(mx, logits[j]);
#pragma unroll
    for (int off = 16; off; off >>= 1) mx = fmaxf(mx, __shfl_xor_sync(0xffffffffu, mx, off));
    if (lane == 0) red[wid] = mx;
    __syncthreads();
    float bm = -1e30f;
#pragma unroll
    for (int i = 0; i < 8; i++) bm = fmaxf(bm, red[i]);
    __syncthreads();

    float sum = 0.f;
    for (int j = t; j < OUTC; j += 256) {
        float e = __expf(logits[j] - bm);
        logits[j] = e;
        sum += e;
    }
#pragma unroll
    for (int off = 16; off; off >>= 1) sum += __shfl_xor_sync(0xffffffffu, sum, off);
    if (lane == 0) red[wid] = sum;
    __syncthreads();
    float bs = 0.f;
#pragma unroll
    for (int i = 0; i < 8; i++) bs += red[i];
    float inv = 1.f / bs;
    __syncthreads();
    for (int j = t; j < OUTC; j += 256) out[(size_t)n * OUTC + j] = logits[j] * inv;
}

// ---------------- launcher ----------------
extern "C" void kernel_launch(void* const* d_in, const int* in_sizes, int n_in,
                              void* d_out, int out_size)
{
    const float* images  = (const float*)d_in[0];
    const float* w_map   = (const float*)d_in[1];
    const float* b_map   = (const float*)d_in[2];
    const float* cls_tok = (const float*)d_in[3];
    const float* norm1_g = (const float*)d_in[4];
    const float* norm1_b = (const float*)d_in[5];
    const float* wq      = (const float*)d_in[6];
    const float* bq      = (const float*)d_in[7];
    const float* wk      = (const float*)d_in[8];
    const float* bk      = (const float*)d_in[9];
    const float* wv      = (const float*)d_in[10];
    const float* bv      = (const float*)d_in[11];
    const float* w_last  = (const float*)d_in[12];
    const float* b_last  = (const float*)d_in[13];
    const float* norm2_g = (const float*)d_in[14];
    const float* norm2_b = (const float*)d_in[15];
    const float* w_mlp1  = (const float*)d_in[16];
    const float* b_mlp1  = (const float*)d_in[17];
    const float* w_mlp2  = (const float*)d_in[18];
    const float* b_mlp2  = (const float*)d_in[19];
    const float* w_out   = (const float*)d_in[20];
    const float* b_out   = (const float*)d_in[21];
    float* out = (float*)d_out;

    bf16 *patches, *x1b, *qb, *kb, *vb, *ob, *h1b;
    bf16 *wmapb, *wlastb, *wmlp1b, *wmlp2b, *wqb, *wkb, *wvb;
    float *X, *pe;
    cudaGetSymbolAddress((void**)&patches, g_patches_b);
    cudaGetSymbolAddress((void**)&X,   g_X);
    cudaGetSymbolAddress((void**)&x1b, g_x1b);
    cudaGetSymbolAddress((void**)&qb,  g_qb);
    cudaGetSymbolAddress((void**)&kb,  g_kb);
    cudaGetSymbolAddress((void**)&vb,  g_vb);
    cudaGetSymbolAddress((void**)&ob,  g_ob);
    cudaGetSymbolAddress((void**)&h1b, g_h1b);
    cudaGetSymbolAddress((void**)&pe,  g_pe);
    cudaGetSymbolAddress((void**)&wmapb,  g_wmapb);
    cudaGetSymbolAddress((void**)&wlastb, g_wlastb);
    cudaGetSymbolAddress((void**)&wmlp1b, g_wmlp1b);
    cudaGetSymbolAddress((void**)&wmlp2b, g_wmlp2b);
    cudaGetSymbolAddress((void**)&wqb, g_wqb);
    cudaGetSymbolAddress((void**)&wkb, g_wkb);
    cudaGetSymbolAddress((void**)&wvb, g_wvb);

    cudaFuncSetAttribute(gemm_bf<0, false, false, true >, cudaFuncAttributeMaxDynamicSharedMemorySize, GEMM_SMEM);
    cudaFuncSetAttribute(gemm_bf<0, true,  false, false>, cudaFuncAttributeMaxDynamicSharedMemorySize, GEMM_SMEM);
    cudaFuncSetAttribute(gemm_bf<1, false, true,  false>, cudaFuncAttributeMaxDynamicSharedMemorySize, GEMM_SMEM);
    cudaFuncSetAttribute(lnqkv_kernel, cudaFuncAttributeMaxDynamicSharedMemorySize, QKV_SMEM);

    // 0) weight conversion to bf16
    {
        int n1 = DMODEL * IN_D;
        cvt_kernel<<<(n1 / 4 + 255) / 256, 256>>>(w_map, wmapb, n1);
        int n2 = NLAYER * DMODEL * DMODEL;
        cvt_kernel<<<(n2 / 4 + 255) / 256, 256>>>(w_last, wlastb, n2);
        int n3 = NLAYER * 4 * DMODEL * DMODEL;
        cvt_kernel<<<(n3 / 4 + 255) / 256, 256>>>(w_mlp1, wmlp1b, n3);
        cvt_kernel<<<(n3 / 4 + 255) / 256, 256>>>(w_mlp2, wmlp2b, n3);
        int n4 = NLAYER * NHEAD * DH * DH;
        cvt_kernel<<<(n4 / 4 + 255) / 256, 256>>>(wq, wqb, n4);
        cvt_kernel<<<(n4 / 4 + 255) / 256, 256>>>(wk, wkb, n4);
        cvt_kernel<<<(n4 / 4 + 255) / 256, 256>>>(wv, wvb, n4);
    }

    // 1) patches + PE table
    {
        int tot = BATCH * NP * IN_D;
        patch_kernel<<<(tot + 255) / 256, 256>>>(images, patches);
        int pt = SEQ * DMODEL;
        pe_kernel<<<(pt + 255) / 256, 256>>>(pe);
    }

    // 2) patch-embed GEMM fused with assemble: X[n][p+1][:] = patches@w_map^T + b + pe
    gemm_bf<0, false, false, true><<<dim3(DMODEL / 128, (BATCH * NP) / 128), 256, GEMM_SMEM>>>(
        patches, wmapb, b_map, nullptr, pe, X, BATCH * NP, DMODEL, IN_D);

    // 2b) cls rows
    cls_kernel<<<(BATCH * DMODEL + 255) / 256, 256>>>(cls_tok, pe, X);

    const int MROWS = BATCH * SEQ;   // 25216 = 128*197

    for (int l = 0; l < NLAYER; l++) {
        // fused LN1 + QKV
        lnqkv_kernel<<<dim3(BATCH, (SEQ + 7) / 8), 256, QKV_SMEM>>>(
            X, norm1_g + l * DMODEL, norm1_b + l * DMODEL,
            wqb + (size_t)l * NHEAD * DH * DH, bq + (size_t)l * NHEAD * DH,
            wkb + (size_t)l * NHEAD * DH * DH, bk + (size_t)l * NHEAD * DH,
            wvb + (size_t)l * NHEAD * DH * DH, bv + (size_t)l * NHEAD * DH,
            qb, kb, vb);

        attn_tc<<<BATCH * NHEAD, 224>>>(qb, kb, vb, ob);

        // o-proj + residual: X = X + o @ w_last^T + b_last (25216,256,256)
        gemm_bf<0, true, false, false><<<dim3(DMODEL / 128, MROWS / 128), 256, GEMM_SMEM>>>(
            ob, wlastb + (size_t)l * DMODEL * DMODEL, b_last + l * DMODEL, X, nullptr, X,
            MROWS, DMODEL, DMODEL);

        ln_kernel<<<MROWS / 8, 256>>>(X, norm2_g + l * DMODEL, norm2_b + l * DMODEL, x1b);

        // MLP1 + GELU -> bf16 h1 (25216,1024,256)
        gemm_bf<1, false, true, false><<<dim3((4 * DMODEL) / 128, MROWS / 128), 256, GEMM_SMEM>>>(
            x1b, wmlp1b + (size_t)l * 4 * DMODEL * DMODEL, b_mlp1 + l * 4 * DMODEL,
            nullptr, nullptr, h1b, MROWS, 4 * DMODEL, DMODEL);

        // MLP2 + residual: X = X + h1 @ w_mlp2^T + b2 (25216,256,1024)
        gemm_bf<0, true, false, false><<<dim3(DMODEL / 128, MROWS / 128), 256, GEMM_SMEM>>>(
            h1b, wmlp2b + (size_t)l * 4 * DMODEL * DMODEL, b_mlp2 + l * DMODEL, X, nullptr, X,
            MROWS, DMODEL, 4 * DMODEL);
    }

    head_kernel<<<BATCH, 256>>>(X, w_out, b_out, out);
}

// round 9
// speedup vs baseline: 1.1194x; 1.1194x over previous
#include <cuda_runtime.h>
#include <cuda_bf16.h>
#include <math.h>
#include <stdint.h>

// ---------------- problem constants ----------------
#define BATCH 128
#define CH    3
#define HIM   224
#define PGRID 14
#define NP    196
#define PATCH 16
#define IN_D  768
#define DMODEL 256
#define NHEAD 8
#define DH    32
#define NLAYER 4
#define SEQ   197
#define OUTC  1000
#define LNEPS 1e-5f

typedef __nv_bfloat16 bf16;

// ---------------- scratch (device globals) ----------------
__device__ bf16  g_patches_b[BATCH * NP * IN_D];
__device__ float g_X [BATCH * SEQ * DMODEL];
__device__ bf16  g_x1b[BATCH * SEQ * DMODEL];
__device__ bf16  g_qb [BATCH * SEQ * DMODEL];             // [n,h,s,e]
__device__ bf16  g_kb [BATCH * SEQ * DMODEL];
__device__ bf16  g_vb [BATCH * SEQ * DMODEL];
__device__ bf16  g_ob [BATCH * SEQ * DMODEL];             // [n,s,d]
__device__ bf16  g_h1b[BATCH * SEQ * 4 * DMODEL];
__device__ float g_pe[SEQ * DMODEL];
__device__ bf16  g_wmapb [DMODEL * IN_D];
__device__ bf16  g_wlastb[NLAYER * DMODEL * DMODEL];
__device__ bf16  g_wmlp1b[NLAYER * 4 * DMODEL * DMODEL];
__device__ bf16  g_wmlp2b[NLAYER * 4 * DMODEL * DMODEL];

// ---------------- fp32 -> bf16 convert ----------------
__global__ void cvt_kernel(const float* __restrict__ src, bf16* __restrict__ dst, int n)
{
    int i = (blockIdx.x * 256 + threadIdx.x) * 4;
    if (i >= n) return;
    float4 v = *(const float4*)(src + i);
    __nv_bfloat162 p0 = __floats2bfloat162_rn(v.x, v.y);
    __nv_bfloat162 p1 = __floats2bfloat162_rn(v.z, v.w);
    uint2 o;
    o.x = *reinterpret_cast<uint32_t*>(&p0);
    o.y = *reinterpret_cast<uint32_t*>(&p1);
    *reinterpret_cast<uint2*>(dst + i) = o;
}

// ---------------- patch extraction (writes bf16) ----------------
__global__ void patch_kernel(const float* __restrict__ img, bf16* __restrict__ out)
{
    int idx = blockIdx.x * 256 + threadIdx.x;
    if (idx >= BATCH * NP * IN_D) return;
    int i = idx % IN_D;
    int p = (idx / IN_D) % NP;
    int n = idx / (IN_D * NP);
    int c   = i >> 8;
    int r   = (i >> 4) & 15;
    int col = i & 15;
    int py = p / PGRID, px = p % PGRID;
    out[idx] = __float2bfloat16(
        img[(((size_t)n * CH + c) * HIM + py * PATCH + r) * HIM + px * PATCH + col]);
}

// ---------------- positional encoding (fp64) ----------------
__global__ void pe_kernel(float* __restrict__ pe)
{
    int i = blockIdx.x * 256 + threadIdx.x;
    if (i >= SEQ * DMODEL) return;
    int s = i / DMODEL, d = i % DMODEL;
    double expo = (double)(2 * (d / 2)) / (double)DMODEL;
    double ang  = (double)s / pow(10000.0, expo);
    pe[i] = (float)((d & 1) ? cos(ang) : sin(ang));
}

// ---------------- cls rows: X[n][0][:] = cls + pe[0] ------------------------
__global__ void cls_kernel(const float* __restrict__ cls,
                           const float* __restrict__ pe,
                           float* __restrict__ X)
{
    int i = blockIdx.x * 256 + threadIdx.x;
    if (i >= BATCH * DMODEL) return;
    int d = i % DMODEL;
    int n = i / DMODEL;
    X[(size_t)n * SEQ * DMODEL + d] = cls[d] + pe[d];
}

// ---------------- bf16 MMA / ldmatrix helpers -------------------------------
__device__ __forceinline__ void mma_bf16(float* c, const uint32_t* a, const uint32_t* b)
{
    asm volatile(
        "mma.sync.aligned.m16n8k16.row.col.f32.bf16.bf16.f32 "
        "{%0,%1,%2,%3}, {%4,%5,%6,%7}, {%8,%9}, {%0,%1,%2,%3};"
        : "+f"(c[0]), "+f"(c[1]), "+f"(c[2]), "+f"(c[3])
        : "r"(a[0]), "r"(a[1]), "r"(a[2]), "r"(a[3]), "r"(b[0]), "r"(b[1]));
}

#define LDSM4(r0, r1, r2, r3, addr) \
    asm volatile("ldmatrix.sync.aligned.m8n8.x4.shared.b16 {%0,%1,%2,%3}, [%4];" \
                 : "=r"(r0), "=r"(r1), "=r"(r2), "=r"(r3) : "r"(addr))

#define CP16(dst, src) asm volatile("cp.async.cg.shared.global [%0], [%1], 16;\n" :: "r"(dst), "l"(src))
#define CP_COMMIT()    asm volatile("cp.async.commit_group;\n" ::)
#define CP_WAIT1()     asm volatile("cp.async.wait_group 1;\n" ::)
#define CP_WAIT0()     asm volatile("cp.async.wait_group 0;\n" ::)

// ---------------- bf16 tensor-core GEMM, 128x128 tile, 3-stage pipeline -----
// C = act(A @ W^T + bias) (+res) (+pe-remap). 8 warps (4m x 2n), one sync/iter.
// Requires M%128==0, N%128==0, K%64==0, K>=192.
#define STR 36                        // u32 stride per 64-bf16 row (pad 4) = 144B
#define ABUF (128 * STR)              // u32, one A (or B) stage buffer
#define NSTAGE 3
#define GEMM_SMEM (NSTAGE * 2 * ABUF * 4)   // 110592 B

template<int ACT, bool HASRES, bool OUTBF, bool ADDPE>
__global__ void __launch_bounds__(256) gemm_bf(const bf16* __restrict__ A,
                                               const bf16* __restrict__ W,
                                               const float* __restrict__ bias,
                                               const float* __restrict__ res,
                                               const float* __restrict__ pe,
                                               void* __restrict__ Cout,
                                               int M, int N, int K)
{
    extern __shared__ uint32_t sm_[];
    const uint32_t smem_byte = (uint32_t)__cvta_generic_to_shared(sm_);

    const int t    = threadIdx.x;
    const int warp = t >> 5, lane = t & 31;
    const int g    = lane >> 2, q4 = lane & 3;
    const int warp_m = (warp >> 1) * 32;
    const int warp_n = (warp & 1) * 64;
    const int row0 = blockIdx.y * 128, col0 = blockIdx.x * 128;

    float acc[2][8][4];
#pragma unroll
    for (int mi = 0; mi < 2; mi++)
#pragma unroll
        for (int ni = 0; ni < 8; ni++)
#pragma unroll
            for (int e = 0; e < 4; e++) acc[mi][ni][e] = 0.f;

    // buffer bi: A at bi*(2*ABUF), B at bi*(2*ABUF)+ABUF (u32 offsets)
    auto stage = [&](int k0, int bi) {
        uint32_t abase = smem_byte + bi * (2 * ABUF * 4);
        uint32_t bbase = abase + ABUF * 4;
#pragma unroll
        for (int i = 0; i < 4; i++) {
            int c = t + i * 256;
            int r = c >> 3, co = c & 7;
            CP16(abase + (r * STR + co * 4) * 4, A + (size_t)(row0 + r) * K + k0 + co * 8);
            CP16(bbase + (r * STR + co * 4) * 4, W + (size_t)(col0 + r) * K + k0 + co * 8);
        }
        CP_COMMIT();
    };

    uint32_t a_addr[NSTAGE][2], b_addr[NSTAGE][4];
    {
        int ar = warp_m + (lane & 15);
        int ab = (lane >> 4) * 16;
        int br = warp_n + ((lane >> 4) & 1) * 8 + (lane & 7);
        int bb = ((lane >> 3) & 1) * 16;
#pragma unroll
        for (int bi = 0; bi < NSTAGE; bi++) {
            uint32_t abase = smem_byte + bi * (2 * ABUF * 4);
            uint32_t bbase = abase + ABUF * 4;
#pragma unroll
            for (int mi = 0; mi < 2; mi++)
                a_addr[bi][mi] = abase + (ar + mi * 16) * (STR * 4) + ab;
#pragma unroll
            for (int nj = 0; nj < 4; nj++)
                b_addr[bi][nj] = bbase + (br + nj * 16) * (STR * 4) + bb;
        }
    }

    const int KT = K >> 6;
    stage(0, 0);
    stage(64, 1);

    for (int kt = 0; kt < KT; kt++) {
        const int cur = kt % NSTAGE;
        if (kt + 1 < KT) CP_WAIT1(); else CP_WAIT0();
        __syncthreads();
        if (kt + 2 < KT) stage((kt + 2) << 6, (kt + 2) % NSTAGE);

#pragma unroll
        for (int ks = 0; ks < 4; ks++) {
            const uint32_t kb = ks * 32;
            uint32_t af[2][4];
            LDSM4(af[0][0], af[0][1], af[0][2], af[0][3], a_addr[cur][0] + kb);
            LDSM4(af[1][0], af[1][1], af[1][2], af[1][3], a_addr[cur][1] + kb);
            uint32_t bf_[8][2];
#pragma unroll
            for (int nj = 0; nj < 4; nj++)
                LDSM4(bf_[2 * nj][0], bf_[2 * nj][1], bf_[2 * nj + 1][0], bf_[2 * nj + 1][1],
                      b_addr[cur][nj] + kb);
#pragma unroll
            for (int mi = 0; mi < 2; mi++)
#pragma unroll
                for (int ni = 0; ni < 8; ni++)
                    mma_bf16(acc[mi][ni], af[mi], bf_[ni]);
        }
    }

    // epilogue
#pragma unroll
    for (int mi = 0; mi < 2; mi++) {
        int ra = row0 + warp_m + mi * 16 + g;
        int rb = ra + 8;
        size_t orow_a, orow_b;
        if (ADDPE) {
            orow_a = (size_t)(ra / NP) * SEQ + (ra % NP) + 1;
            orow_b = (size_t)(rb / NP) * SEQ + (rb % NP) + 1;
        } else {
            orow_a = ra; orow_b = rb;
        }
        int pes_a = ADDPE ? ((ra % NP) + 1) : 0;
        int pes_b = ADDPE ? ((rb % NP) + 1) : 0;
#pragma unroll
        for (int ni = 0; ni < 8; ni++) {
            int col = col0 + warp_n + ni * 8 + q4 * 2;
            float b0 = bias[col], b1 = bias[col + 1];
            float v00 = acc[mi][ni][0] + b0, v01 = acc[mi][ni][1] + b1;
            float v10 = acc[mi][ni][2] + b0, v11 = acc[mi][ni][3] + b1;
            if (ACT == 1) {
                v00 = 0.5f * v00 * (1.0f + erff(v00 * 0.70710678118654752f));
                v01 = 0.5f * v01 * (1.0f + erff(v01 * 0.70710678118654752f));
                v10 = 0.5f * v10 * (1.0f + erff(v10 * 0.70710678118654752f));
                v11 = 0.5f * v11 * (1.0f + erff(v11 * 0.70710678118654752f));
            }
            if (HASRES) {
                float2 r0 = *(const float2*)(res + orow_a * N + col);
                float2 r1 = *(const float2*)(res + orow_b * N + col);
                v00 += r0.x; v01 += r0.y; v10 += r1.x; v11 += r1.y;
            }
            if (ADDPE) {
                float2 p0 = *(const float2*)(pe + (size_t)pes_a * DMODEL + col);
                float2 p1 = *(const float2*)(pe + (size_t)pes_b * DMODEL + col);
                v00 += p0.x; v01 += p0.y; v10 += p1.x; v11 += p1.y;
            }
            if (OUTBF) {
                bf16* C = (bf16*)Cout;
                __nv_bfloat162 p0 = __floats2bfloat162_rn(v00, v01);
                __nv_bfloat162 p1 = __floats2bfloat162_rn(v10, v11);
                *reinterpret_cast<uint32_t*>(C + orow_a * N + col) = *reinterpret_cast<uint32_t*>(&p0);
                *reinterpret_cast<uint32_t*>(C + orow_b * N + col) = *reinterpret_cast<uint32_t*>(&p1);
            } else {
                float* C = (float*)Cout;
                *(float2*)(C + orow_a * N + col) = make_float2(v00, v01);
                *(float2*)(C + orow_b * N + col) = make_float2(v10, v11);
            }
        }
    }
}

// ---------------- LayerNorm: warp per row, bf16 out -------------------------
__global__ void ln_kernel(const float* __restrict__ x,
                          const float* __restrict__ g,
                          const float* __restrict__ b,
                          bf16* __restrict__ y)
{
    const int row  = blockIdx.x * 8 + (threadIdx.x >> 5);
    const int lane = threadIdx.x & 31;
    const float4* xp = (const float4*)(x + (size_t)row * DMODEL);
    float4 u = xp[lane * 2], w = xp[lane * 2 + 1];

    float s = u.x + u.y + u.z + u.w + w.x + w.y + w.z + w.w;
#pragma unroll
    for (int off = 16; off; off >>= 1) s += __shfl_xor_sync(0xffffffffu, s, off);
    float mu = s * (1.f / DMODEL);

    float d0 = u.x - mu, d1 = u.y - mu, d2 = u.z - mu, d3 = u.w - mu;
    float d4 = w.x - mu, d5 = w.y - mu, d6 = w.z - mu, d7 = w.w - mu;
    float s2 = d0*d0 + d1*d1 + d2*d2 + d3*d3 + d4*d4 + d5*d5 + d6*d6 + d7*d7;
#pragma unroll
    for (int off = 16; off; off >>= 1) s2 += __shfl_xor_sync(0xffffffffu, s2, off);
    float inv = rsqrtf(s2 * (1.f / DMODEL) + LNEPS);

    const float4* gp = (const float4*)g;
    const float4* bp = (const float4*)b;
    float4 g0 = gp[lane * 2], g1 = gp[lane * 2 + 1];
    float4 b0 = bp[lane * 2], b1 = bp[lane * 2 + 1];

    __nv_bfloat162 p0 = __floats2bfloat162_rn(d0 * inv * g0.x + b0.x, d1 * inv * g0.y + b0.y);
    __nv_bfloat162 p1 = __floats2bfloat162_rn(d2 * inv * g0.z + b0.z, d3 * inv * g0.w + b0.w);
    __nv_bfloat162 p2 = __floats2bfloat162_rn(d4 * inv * g1.x + b1.x, d5 * inv * g1.y + b1.y);
    __nv_bfloat162 p3 = __floats2bfloat162_rn(d6 * inv * g1.z + b1.z, d7 * inv * g1.w + b1.w);
    uint4 o;
    o.x = *reinterpret_cast<uint32_t*>(&p0);
    o.y = *reinterpret_cast<uint32_t*>(&p1);
    o.z = *reinterpret_cast<uint32_t*>(&p2);
    o.w = *reinterpret_cast<uint32_t*>(&p3);
    *reinterpret_cast<uint4*>(y + (size_t)row * DMODEL + lane * 8) = o;
}

// ---------------- fused per-head QKV projection (bf16 io) -------------------
__global__ void qkv_kernel(const bf16* __restrict__ x1,
                           const float* __restrict__ wq, const float* __restrict__ bq,
                           const float* __restrict__ wk, const float* __restrict__ bk,
                           const float* __restrict__ wv, const float* __restrict__ bv,
                           bf16* __restrict__ q, bf16* __restrict__ k, bf16* __restrict__ v)
{
    __shared__ float wqs[32 * 33], wks[32 * 33], wvs[32 * 33];
    __shared__ float bqs[32], bks[32], bvs[32];
    __shared__ float xr[8][32];
    const int nh = blockIdx.x;
    const int n = nh / NHEAD, h = nh % NHEAD;
    const int t = threadIdx.x;
    const float* wqg = wq + (size_t)h * DH * DH;
    const float* wkg = wk + (size_t)h * DH * DH;
    const float* wvg = wv + (size_t)h * DH * DH;

    for (int i = t; i < DH * DH; i += 256) {
        int e = i >> 5, d = i & 31;
        wqs[e * 33 + d] = wqg[i];
        wks[e * 33 + d] = wkg[i];
        wvs[e * 33 + d] = wvg[i];
    }
    if (t < 32) { bqs[t] = bq[h * DH + t]; bks[t] = bk[h * DH + t]; bvs[t] = bv[h * DH + t]; }

    const int sl = t >> 5, lane = t & 31;
    const int s = blockIdx.y * 8 + sl;
    if (s < SEQ) xr[sl][lane] = __bfloat162float(x1[((size_t)n * SEQ + s) * DMODEL + h * DH + lane]);
    __syncthreads();
    if (s >= SEQ) return;

    float aq = bqs[lane], ak = bks[lane], av = bvs[lane];
#pragma unroll
    for (int d = 0; d < 32; d++) {
        float xv = xr[sl][d];
        aq += xv * wqs[lane * 33 + d];
        ak += xv * wks[lane * 33 + d];
        av += xv * wvs[lane * 33 + d];
    }
    size_t oidx = ((size_t)nh * SEQ + s) * DH + lane;
    q[oidx] = __float2bfloat16(aq);
    k[oidx] = __float2bfloat16(ak);
    v[oidx] = __float2bfloat16(av);
}

// ---------------- tensor-core flash attention per (n,h) ---------------------
#define SPAD 224
#define NKT  7
#define KSTR 20
#define VSTR 116

__global__ void __launch_bounds__(224) attn_tc(const bf16* __restrict__ q,
                                               const bf16* __restrict__ k,
                                               const bf16* __restrict__ v,
                                               bf16* __restrict__ o)
{
    __shared__ uint32_t Ks[SPAD * KSTR];
    __shared__ uint32_t VT[32 * VSTR];

    const int nh = blockIdx.x;
    const int n = nh / NHEAD, h = nh % NHEAD;
    const int t = threadIdx.x, warp = t >> 5, lane = t & 31;
    const int g = lane >> 2, q4 = lane & 3;
    const size_t base = (size_t)nh * SEQ * DH;
    const uint32_t* q32 = (const uint32_t*)(q + base);
    const uint32_t* k32 = (const uint32_t*)(k + base);
    const uint32_t* v32 = (const uint32_t*)(v + base);

    for (int i = t; i < SPAD * 16; i += 224) {
        int r = i >> 4, c = i & 15;
        Ks[r * KSTR + c] = (r < SEQ) ? k32[r * 16 + c] : 0u;
    }
    // V transpose staging (vectorized u32 loads)
    bf16* VT16 = (bf16*)VT;
    for (int i = t; i < SPAD * 16; i += 224) {
        int tt = i >> 4, c = i & 15;
        uint32_t val = (tt < SEQ) ? v32[tt * 16 + c] : 0u;
        __nv_bfloat162 pr = *reinterpret_cast<__nv_bfloat162*>(&val);
        VT16[(2 * c)     * (VSTR * 2) + tt] = pr.x;
        VT16[(2 * c + 1) * (VSTR * 2) + tt] = pr.y;
    }
    __syncthreads();

    const int qbase = warp * 32;
    uint32_t qf[2][2][4];
#pragma unroll
    for (int mi = 0; mi < 2; mi++) {
        int r0 = qbase + mi * 16 + g, r1 = r0 + 8;
        bool v0 = r0 < SEQ, v1 = r1 < SEQ;
#pragma unroll
        for (int ks = 0; ks < 2; ks++) {
            qf[mi][ks][0] = v0 ? q32[r0 * 16 + ks * 8 + q4]     : 0u;
            qf[mi][ks][1] = v1 ? q32[r1 * 16 + ks * 8 + q4]     : 0u;
            qf[mi][ks][2] = v0 ? q32[r0 * 16 + ks * 8 + q4 + 4] : 0u;
            qf[mi][ks][3] = v1 ? q32[r1 * 16 + ks * 8 + q4 + 4] : 0u;
        }
    }

    float Oa[2][4][4];
#pragma unroll
    for (int mi = 0; mi < 2; mi++)
#pragma unroll
        for (int ne = 0; ne < 4; ne++)
#pragma unroll
            for (int e = 0; e < 4; e++) Oa[mi][ne][e] = 0.f;
    float m_[2][2] = {{-1e30f, -1e30f}, {-1e30f, -1e30f}};
    float l_[2][2] = {{0.f, 0.f}, {0.f, 0.f}};
    const float scale = 0.17677669529663689f;

    for (int kt = 0; kt < NKT; kt++) {
        float sc[2][4][4];
#pragma unroll
        for (int mi = 0; mi < 2; mi++)
#pragma unroll
            for (int ni = 0; ni < 4; ni++)
#pragma unroll
                for (int e = 0; e < 4; e++) sc[mi][ni][e] = 0.f;

        uint32_t kf[2][4][2];
#pragma unroll
        for (int ks = 0; ks < 2; ks++)
#pragma unroll
            for (int ni = 0; ni < 4; ni++) {
                int r = kt * 32 + ni * 8 + g;
                kf[ks][ni][0] = Ks[r * KSTR + ks * 8 + q4];
                kf[ks][ni][1] = Ks[r * KSTR + ks * 8 + q4 + 4];
            }
#pragma unroll
        for (int mi = 0; mi < 2; mi++)
#pragma unroll
            for (int ni = 0; ni < 4; ni++)
#pragma unroll
                for (int ks = 0; ks < 2; ks++)
                    mma_bf16(sc[mi][ni], qf[mi][ks], kf[ks][ni]);

#pragma unroll
        for (int mi = 0; mi < 2; mi++) {
#pragma unroll
            for (int hf = 0; hf < 2; hf++) {
                float mx = -1e30f;
#pragma unroll
                for (int ni = 0; ni < 4; ni++) {
                    int col = kt * 32 + ni * 8 + q4 * 2;
                    float s0 = (col     < SEQ) ? sc[mi][ni][hf * 2]     * scale : -1e30f;
                    float s1 = (col + 1 < SEQ) ? sc[mi][ni][hf * 2 + 1] * scale : -1e30f;
                    sc[mi][ni][hf * 2]     = s0;
                    sc[mi][ni][hf * 2 + 1] = s1;
                    mx = fmaxf(mx, fmaxf(s0, s1));
                }
                mx = fmaxf(mx, __shfl_xor_sync(0xffffffffu, mx, 1));
                mx = fmaxf(mx, __shfl_xor_sync(0xffffffffu, mx, 2));
                float mnew = fmaxf(m_[mi][hf], mx);
                float f = __expf(m_[mi][hf] - mnew);
                m_[mi][hf] = mnew;
                float rs = 0.f;
#pragma unroll
                for (int ni = 0; ni < 4; ni++) {
                    float p0 = __expf(sc[mi][ni][hf * 2]     - mnew);
                    float p1 = __expf(sc[mi][ni][hf * 2 + 1] - mnew);
                    sc[mi][ni][hf * 2]     = p0;
                    sc[mi][ni][hf * 2 + 1] = p1;
                    rs += p0 + p1;
                }
                rs += __shfl_xor_sync(0xffffffffu, rs, 1);
                rs += __shfl_xor_sync(0xffffffffu, rs, 2);
                l_[mi][hf] = l_[mi][hf] * f + rs;
#pragma unroll
                for (int ne = 0; ne < 4; ne++) {
                    Oa[mi][ne][hf * 2]     *= f;
                    Oa[mi][ne][hf * 2 + 1] *= f;
                }
            }
        }

        uint32_t pa[2][2][4];
#pragma unroll
        for (int mi = 0; mi < 2; mi++)
#pragma unroll
            for (int ks = 0; ks < 2; ks++) {
                __nv_bfloat162 t0 = __floats2bfloat162_rn(sc[mi][2 * ks][0],     sc[mi][2 * ks][1]);
                __nv_bfloat162 t1 = __floats2bfloat162_rn(sc[mi][2 * ks][2],     sc[mi][2 * ks][3]);
                __nv_bfloat162 t2 = __floats2bfloat162_rn(sc[mi][2 * ks + 1][0], sc[mi][2 * ks + 1][1]);
                __nv_bfloat162 t3 = __floats2bfloat162_rn(sc[mi][2 * ks + 1][2], sc[mi][2 * ks + 1][3]);
                pa[mi][ks][0] = *reinterpret_cast<uint32_t*>(&t0);
                pa[mi][ks][1] = *reinterpret_cast<uint32_t*>(&t1);
                pa[mi][ks][2] = *reinterpret_cast<uint32_t*>(&t2);
                pa[mi][ks][3] = *reinterpret_cast<uint32_t*>(&t3);
            }

        uint32_t vf[2][4][2];
#pragma unroll
        for (int ks = 0; ks < 2; ks++)
#pragma unroll
            for (int ne = 0; ne < 4; ne++) {
                int r = ne * 8 + g;
                int cu = kt * 16 + ks * 8 + q4;
                vf[ks][ne][0] = VT[r * VSTR + cu];
                vf[ks][ne][1] = VT[r * VSTR + cu + 4];
            }
#pragma unroll
        for (int mi = 0; mi < 2; mi++)
#pragma unroll
            for (int ne = 0; ne < 4; ne++)
#pragma unroll
                for (int ks = 0; ks < 2; ks++)
                    mma_bf16(Oa[mi][ne], pa[mi][ks], vf[ks][ne]);
    }

#pragma unroll
    for (int mi = 0; mi < 2; mi++) {
#pragma unroll
        for (int hf = 0; hf < 2; hf++) {
            int row = qbase + mi * 16 + hf * 8 + g;
            if (row >= SEQ) continue;
            float inv = 1.f / l_[mi][hf];
            bf16* op = o + ((size_t)n * SEQ + row) * DMODEL + h * DH;
#pragma unroll
            for (int ne = 0; ne < 4; ne++) {
                __nv_bfloat162 p = __floats2bfloat162_rn(Oa[mi][ne][hf * 2] * inv,
                                                         Oa[mi][ne][hf * 2 + 1] * inv);
                *reinterpret_cast<uint32_t*>(op + ne * 8 + q4 * 2) = *reinterpret_cast<uint32_t*>(&p);
            }
        }
    }
}

// ---------------- classification head ---------------------------------------
__global__ void head_kernel(const float* __restrict__ X, const float* __restrict__ w_out,
                            const float* __restrict__ b_out, float* __restrict__ out)
{
    __shared__ float cls_s[DMODEL];
    __shared__ float logits[OUTC];
    __shared__ float red[8];
    const int n = blockIdx.x;
    const int t = threadIdx.x, wid = t >> 5, lane = t & 31;

    cls_s[t] = X[(size_t)n * SEQ * DMODEL + t];
    __syncthreads();

    for (int j = wid; j < OUTC; j += 8) {
        float acc = 0.f;
#pragma unroll
        for (int k = lane; k < DMODEL; k += 32) acc += cls_s[k] * w_out[(size_t)j * DMODEL + k];
#pragma unroll
        for (int off = 16; off; off >>= 1) acc += __shfl_xor_sync(0xffffffffu, acc, off);
        if (lane == 0) logits[j] = acc + b_out[j];
    }
    __syncthreads();

    float mx = -1e30f;
    for (int j = t; j < OUTC; j += 256) mx = fmaxf(mx, logits[j]);
#pragma unroll
    for (int off = 16; off; off >>= 1) mx = fmaxf(mx, __shfl_xor_sync(0xffffffffu, mx, off));
    if (lane == 0) red[wid] = mx;
    __syncthreads();
    float bm = -1e30f;
#pragma unroll
    for (int i = 0; i < 8; i++) bm = fmaxf(bm, red[i]);
    __syncthreads();

    float sum = 0.f;
    for (int j = t; j < OUTC; j += 256) {
        float e = __expf(logits[j] - bm);
        logits[j] = e;
        sum += e;
    }
#pragma unroll
    for (int off = 16; off; off >>= 1) sum += __shfl_xor_sync(0xffffffffu, sum, off);
    if (lane == 0) red[wid] = sum;
    __syncthreads();
    float bs = 0.f;
#pragma unroll
    for (int i = 0; i < 8; i++) bs += red[i];
    float inv = 1.f / bs;
    __syncthreads();
    for (int j = t; j < OUTC; j += 256) out[(size_t)n * OUTC + j] = logits[j] * inv;
}

// ---------------- launcher ----------------
extern "C" void kernel_launch(void* const* d_in, const int* in_sizes, int n_in,
                              void* d_out, int out_size)
{
    const float* images  = (const float*)d_in[0];
    const float* w_map   = (const float*)d_in[1];
    const float* b_map   = (const float*)d_in[2];
    const float* cls_tok = (const float*)d_in[3];
    const float* norm1_g = (const float*)d_in[4];
    const float* norm1_b = (const float*)d_in[5];
    const float* wq      = (const float*)d_in[6];
    const float* bq      = (const float*)d_in[7];
    const float* wk      = (const float*)d_in[8];
    const float* bk      = (const float*)d_in[9];
    const float* wv      = (const float*)d_in[10];
    const float* bv      = (const float*)d_in[11];
    const float* w_last  = (const float*)d_in[12];
    const float* b_last  = (const float*)d_in[13];
    const float* norm2_g = (const float*)d_in[14];
    const float* norm2_b = (const float*)d_in[15];
    const float* w_mlp1  = (const float*)d_in[16];
    const float* b_mlp1  = (const float*)d_in[17];
    const float* w_mlp2  = (const float*)d_in[18];
    const float* b_mlp2  = (const float*)d_in[19];
    const float* w_out   = (const float*)d_in[20];
    const float* b_out   = (const float*)d_in[21];
    float* out = (float*)d_out;

    bf16 *patches, *x1b, *qb, *kb, *vb, *ob, *h1b;
    bf16 *wmapb, *wlastb, *wmlp1b, *wmlp2b;
    float *X, *pe;
    cudaGetSymbolAddress((void**)&patches, g_patches_b);
    cudaGetSymbolAddress((void**)&X,   g_X);
    cudaGetSymbolAddress((void**)&x1b, g_x1b);
    cudaGetSymbolAddress((void**)&qb,  g_qb);
    cudaGetSymbolAddress((void**)&kb,  g_kb);
    cudaGetSymbolAddress((void**)&vb,  g_vb);
    cudaGetSymbolAddress((void**)&ob,  g_ob);
    cudaGetSymbolAddress((void**)&h1b, g_h1b);
    cudaGetSymbolAddress((void**)&pe,  g_pe);
    cudaGetSymbolAddress((void**)&wmapb,  g_wmapb);
    cudaGetSymbolAddress((void**)&wlastb, g_wlastb);
    cudaGetSymbolAddress((void**)&wmlp1b, g_wmlp1b);
    cudaGetSymbolAddress((void**)&wmlp2b, g_wmlp2b);

    cudaFuncSetAttribute(gemm_bf<0, false, false, true >, cudaFuncAttributeMaxDynamicSharedMemorySize, GEMM_SMEM);
    cudaFuncSetAttribute(gemm_bf<0, true,  false, false>, cudaFuncAttributeMaxDynamicSharedMemorySize, GEMM_SMEM);
    cudaFuncSetAttribute(gemm_bf<1, false, true,  false>, cudaFuncAttributeMaxDynamicSharedMemorySize, GEMM_SMEM);

    // 0) weight conversion to bf16
    {
        int n1 = DMODEL * IN_D;
        cvt_kernel<<<(n1 / 4 + 255) / 256, 256>>>(w_map, wmapb, n1);
        int n2 = NLAYER * DMODEL * DMODEL;
        cvt_kernel<<<(n2 / 4 + 255) / 256, 256>>>(w_last, wlastb, n2);
        int n3 = NLAYER * 4 * DMODEL * DMODEL;
        cvt_kernel<<<(n3 / 4 + 255) / 256, 256>>>(w_mlp1, wmlp1b, n3);
        cvt_kernel<<<(n3 / 4 + 255) / 256, 256>>>(w_mlp2, wmlp2b, n3);
    }

    // 1) patches + PE table
    {
        int tot = BATCH * NP * IN_D;
        patch_kernel<<<(tot + 255) / 256, 256>>>(images, patches);
        int pt = SEQ * DMODEL;
        pe_kernel<<<(pt + 255) / 256, 256>>>(pe);
    }

    // 2) patch-embed GEMM fused with assemble: X[n][p+1][:] = patches@w_map^T + b + pe
    gemm_bf<0, false, false, true><<<dim3(DMODEL / 128, (BATCH * NP) / 128), 256, GEMM_SMEM>>>(
        patches, wmapb, b_map, nullptr, pe, X, BATCH * NP, DMODEL, IN_D);

    // 2b) cls rows
    cls_kernel<<<(BATCH * DMODEL + 255) / 256, 256>>>(cls_tok, pe, X);

    const int MROWS = BATCH * SEQ;   // 25216 = 128*197

    for (int l = 0; l < NLAYER; l++) {
        ln_kernel<<<MROWS / 8, 256>>>(X, norm1_g + l * DMODEL, norm1_b + l * DMODEL, x1b);

        qkv_kernel<<<dim3(BATCH * NHEAD, (SEQ + 7) / 8), 256>>>(
            x1b,
            wq + (size_t)l * NHEAD * DH * DH, bq + (size_t)l * NHEAD * DH,
            wk + (size_t)l * NHEAD * DH * DH, bk + (size_t)l * NHEAD * DH,
            wv + (size_t)l * NHEAD * DH * DH, bv + (size_t)l * NHEAD * DH,
            qb, kb, vb);

        attn_tc<<<BATCH * NHEAD, 224>>>(qb, kb, vb, ob);

        // o-proj + residual: X = X + o @ w_last^T + b_last (25216,256,256)
        gemm_bf<0, true, false, false><<<dim3(DMODEL / 128, MROWS / 128), 256, GEMM_SMEM>>>(
            ob, wlastb + (size_t)l * DMODEL * DMODEL, b_last + l * DMODEL, X, nullptr, X,
            MROWS, DMODEL, DMODEL);

        ln_kernel<<<MROWS / 8, 256>>>(X, norm2_g + l * DMODEL, norm2_b + l * DMODEL, x1b);

        // MLP1 + GELU -> bf16 h1 (25216,1024,256)
        gemm_bf<1, false, true, false><<<dim3((4 * DMODEL) / 128, MROWS / 128), 256, GEMM_SMEM>>>(
            x1b, wmlp1b + (size_t)l * 4 * DMODEL * DMODEL, b_mlp1 + l * 4 * DMODEL,
            nullptr, nullptr, h1b, MROWS, 4 * DMODEL, DMODEL);

        // MLP2 + residual: X = X + h1 @ w_mlp2^T + b2 (25216,256,1024)
        gemm_bf<0, true, false, false><<<dim3(DMODEL / 128, MROWS / 128), 256, GEMM_SMEM>>>(
            h1b, wmlp2b + (size_t)l * 4 * DMODEL * DMODEL, b_mlp2 + l * DMODEL, X, nullptr, X,
            MROWS, DMODEL, 4 * DMODEL);
    }

    head_kernel<<<BATCH, 256>>>(X, w_out, b_out, out);
}

// round 10
// speedup vs baseline: 1.2493x; 1.1161x over previous
#include <cuda_runtime.h>
#include <cuda_bf16.h>
#include <math.h>
#include <stdint.h>

// ---------------- problem constants ----------------
#define BATCH 128
#define CH    3
#define HIM   224
#define PGRID 14
#define NP    196
#define PATCH 16
#define IN_D  768
#define DMODEL 256
#define NHEAD 8
#define DH    32
#define NLAYER 4
#define SEQ   197
#define OUTC  1000
#define LNEPS 1e-5f

typedef __nv_bfloat16 bf16;

// ---------------- scratch (device globals) ----------------
__device__ bf16  g_patches_b[BATCH * NP * IN_D];
__device__ float g_X [BATCH * SEQ * DMODEL];
__device__ bf16  g_x1b[BATCH * SEQ * DMODEL];
__device__ bf16  g_qb [BATCH * SEQ * DMODEL];             // [n,h,s,e]
__device__ bf16  g_kb [BATCH * SEQ * DMODEL];
__device__ bf16  g_vb [BATCH * SEQ * DMODEL];
__device__ bf16  g_ob [BATCH * SEQ * DMODEL];             // [n,s,d]
__device__ bf16  g_h1b[BATCH * SEQ * 4 * DMODEL];
__device__ float g_pe[SEQ * DMODEL];
__device__ bf16  g_wmapb [DMODEL * IN_D];
__device__ bf16  g_wlastb[NLAYER * DMODEL * DMODEL];
__device__ bf16  g_wmlp1b[NLAYER * 4 * DMODEL * DMODEL];
__device__ bf16  g_wmlp2b[NLAYER * 4 * DMODEL * DMODEL];

// ---------------- fp32 -> bf16 convert, all weights in one launch ----------
__device__ __forceinline__ void cvt4(const float* __restrict__ s, bf16* __restrict__ d, int i)
{
    float4 v = *(const float4*)(s + i);
    __nv_bfloat162 p0 = __floats2bfloat162_rn(v.x, v.y);
    __nv_bfloat162 p1 = __floats2bfloat162_rn(v.z, v.w);
    uint2 o;
    o.x = *reinterpret_cast<uint32_t*>(&p0);
    o.y = *reinterpret_cast<uint32_t*>(&p1);
    *reinterpret_cast<uint2*>(d + i) = o;
}

__global__ void cvt_all_kernel(const float* __restrict__ s0, bf16* __restrict__ d0, int n0,
                               const float* __restrict__ s1, bf16* __restrict__ d1, int n1,
                               const float* __restrict__ s2, bf16* __restrict__ d2, int n2,
                               const float* __restrict__ s3, bf16* __restrict__ d3, int n3)
{
    int i = (blockIdx.x * 256 + threadIdx.x) * 4;
    if (i < n0) { cvt4(s0, d0, i); return; }
    i -= n0;
    if (i < n1) { cvt4(s1, d1, i); return; }
    i -= n1;
    if (i < n2) { cvt4(s2, d2, i); return; }
    i -= n2;
    if (i < n3) { cvt4(s3, d3, i); return; }
}

// ---------------- patch extraction (writes bf16) ----------------
__global__ void patch_kernel(const float* __restrict__ img, bf16* __restrict__ out)
{
    int idx = blockIdx.x * 256 + threadIdx.x;
    if (idx >= BATCH * NP * IN_D) return;
    int i = idx % IN_D;
    int p = (idx / IN_D) % NP;
    int n = idx / (IN_D * NP);
    int c   = i >> 8;
    int r   = (i >> 4) & 15;
    int col = i & 15;
    int py = p / PGRID, px = p % PGRID;
    out[idx] = __float2bfloat16(
        img[(((size_t)n * CH + c) * HIM + py * PATCH + r) * HIM + px * PATCH + col]);
}

// ---------------- positional encoding (fp64) ----------------
__global__ void pe_kernel(float* __restrict__ pe)
{
    int i = blockIdx.x * 256 + threadIdx.x;
    if (i >= SEQ * DMODEL) return;
    int s = i / DMODEL, d = i % DMODEL;
    double expo = (double)(2 * (d / 2)) / (double)DMODEL;
    double ang  = (double)s / pow(10000.0, expo);
    pe[i] = (float)((d & 1) ? cos(ang) : sin(ang));
}

// ---------------- cls rows: X[n][0][:] = cls + pe[0] ------------------------
__global__ void cls_kernel(const float* __restrict__ cls,
                           const float* __restrict__ pe,
                           float* __restrict__ X)
{
    int i = blockIdx.x * 256 + threadIdx.x;
    if (i >= BATCH * DMODEL) return;
    int d = i % DMODEL;
    int n = i / DMODEL;
    X[(size_t)n * SEQ * DMODEL + d] = cls[d] + pe[d];
}

// ---------------- bf16 MMA / ldmatrix helpers -------------------------------
__device__ __forceinline__ void mma_bf16(float* c, const uint32_t* a, const uint32_t* b)
{
    asm volatile(
        "mma.sync.aligned.m16n8k16.row.col.f32.bf16.bf16.f32 "
        "{%0,%1,%2,%3}, {%4,%5,%6,%7}, {%8,%9}, {%0,%1,%2,%3};"
        : "+f"(c[0]), "+f"(c[1]), "+f"(c[2]), "+f"(c[3])
        : "r"(a[0]), "r"(a[1]), "r"(a[2]), "r"(a[3]), "r"(b[0]), "r"(b[1]));
}

#define LDSM4(r0, r1, r2, r3, addr) \
    asm volatile("ldmatrix.sync.aligned.m8n8.x4.shared.b16 {%0,%1,%2,%3}, [%4];" \
                 : "=r"(r0), "=r"(r1), "=r"(r2), "=r"(r3) : "r"(addr))

#define CP16(dst, src) asm volatile("cp.async.cg.shared.global [%0], [%1], 16;\n" :: "r"(dst), "l"(src))
#define CP_COMMIT()    asm volatile("cp.async.commit_group;\n" ::)
#define CP_WAIT1()     asm volatile("cp.async.wait_group 1;\n" ::)
#define CP_WAIT0()     asm volatile("cp.async.wait_group 0;\n" ::)

// ---------------- bf16 tensor-core GEMM, 128x128 tile (round-6 proven) ------
// 8 warps (4m x 2n), 2-stage cp.async, 73.7KB smem -> 3 CTA/SM.
#define STR 36                      // u32 stride per 64-bf16 row (pad 4) = 144B
#define ABUF (128 * STR)            // u32
#define GEMM_SMEM (4 * ABUF * 4)    // A0,A1,B0,B1 = 73728 B

template<int ACT, bool HASRES, bool OUTBF, bool ADDPE>
__global__ void __launch_bounds__(256) gemm_bf(const bf16* __restrict__ A,
                                               const bf16* __restrict__ W,
                                               const float* __restrict__ bias,
                                               const float* __restrict__ res,
                                               const float* __restrict__ pe,
                                               void* __restrict__ Cout,
                                               int M, int N, int K)
{
    extern __shared__ uint32_t sm_[];
    const uint32_t smem_byte = (uint32_t)__cvta_generic_to_shared(sm_);

    const int t    = threadIdx.x;
    const int warp = t >> 5, lane = t & 31;
    const int g    = lane >> 2, q4 = lane & 3;
    const int warp_m = (warp >> 1) * 32;
    const int warp_n = (warp & 1) * 64;
    const int row0 = blockIdx.y * 128, col0 = blockIdx.x * 128;

    float acc[2][8][4];
#pragma unroll
    for (int mi = 0; mi < 2; mi++)
#pragma unroll
        for (int ni = 0; ni < 8; ni++)
#pragma unroll
            for (int e = 0; e < 4; e++) acc[mi][ni][e] = 0.f;

    auto stage = [&](int k0, int buf) {
        uint32_t abase = smem_byte + buf * (ABUF * 4);
        uint32_t bbase = smem_byte + (2 + buf) * (ABUF * 4);
#pragma unroll
        for (int i = 0; i < 4; i++) {
            int c = t + i * 256;
            int r = c >> 3, co = c & 7;
            CP16(abase + (r * STR + co * 4) * 4, A + (size_t)(row0 + r) * K + k0 + co * 8);
            CP16(bbase + (r * STR + co * 4) * 4, W + (size_t)(col0 + r) * K + k0 + co * 8);
        }
        CP_COMMIT();
    };

    uint32_t a_addr[2][2], b_addr[2][4];
    {
        int ar = warp_m + (lane & 15);
        int ab = (lane >> 4) * 16;
        int br = warp_n + ((lane >> 4) & 1) * 8 + (lane & 7);
        int bb = ((lane >> 3) & 1) * 16;
#pragma unroll
        for (int buf = 0; buf < 2; buf++) {
            uint32_t abase = smem_byte + buf * (ABUF * 4);
            uint32_t bbase = smem_byte + (2 + buf) * (ABUF * 4);
#pragma unroll
            for (int mi = 0; mi < 2; mi++)
                a_addr[buf][mi] = abase + (ar + mi * 16) * (STR * 4) + ab;
#pragma unroll
            for (int nj = 0; nj < 4; nj++)
                b_addr[buf][nj] = bbase + (br + nj * 16) * (STR * 4) + bb;
        }
    }

    const int KT = K >> 6;
    stage(0, 0);

    for (int kt = 0; kt < KT; kt++) {
        const int cur = kt & 1;
        if (kt + 1 < KT) { stage((kt + 1) << 6, cur ^ 1); CP_WAIT1(); }
        else             { CP_WAIT0(); }
        __syncthreads();

#pragma unroll
        for (int ks = 0; ks < 4; ks++) {
            const uint32_t kb = ks * 32;
            uint32_t af[2][4];
            LDSM4(af[0][0], af[0][1], af[0][2], af[0][3], a_addr[cur][0] + kb);
            LDSM4(af[1][0], af[1][1], af[1][2], af[1][3], a_addr[cur][1] + kb);
            uint32_t bf_[8][2];
#pragma unroll
            for (int nj = 0; nj < 4; nj++)
                LDSM4(bf_[2 * nj][0], bf_[2 * nj][1], bf_[2 * nj + 1][0], bf_[2 * nj + 1][1],
                      b_addr[cur][nj] + kb);
#pragma unroll
            for (int mi = 0; mi < 2; mi++)
#pragma unroll
                for (int ni = 0; ni < 8; ni++)
                    mma_bf16(acc[mi][ni], af[mi], bf_[ni]);
        }
        __syncthreads();
    }

    // epilogue
#pragma unroll
    for (int mi = 0; mi < 2; mi++) {
        int ra = row0 + warp_m + mi * 16 + g;
        int rb = ra + 8;
        size_t orow_a, orow_b;
        if (ADDPE) {
            orow_a = (size_t)(ra / NP) * SEQ + (ra % NP) + 1;
            orow_b = (size_t)(rb / NP) * SEQ + (rb % NP) + 1;
        } else {
            orow_a = ra; orow_b = rb;
        }
        int pes_a = ADDPE ? ((ra % NP) + 1) : 0;
        int pes_b = ADDPE ? ((rb % NP) + 1) : 0;
#pragma unroll
        for (int ni = 0; ni < 8; ni++) {
            int col = col0 + warp_n + ni * 8 + q4 * 2;
            float b0 = bias[col], b1 = bias[col + 1];
            float v00 = acc[mi][ni][0] + b0, v01 = acc[mi][ni][1] + b1;
            float v10 = acc[mi][ni][2] + b0, v11 = acc[mi][ni][3] + b1;
            if (ACT == 1) {
                v00 = 0.5f * v00 * (1.0f + erff(v00 * 0.70710678118654752f));
                v01 = 0.5f * v01 * (1.0f + erff(v01 * 0.70710678118654752f));
                v10 = 0.5f * v10 * (1.0f + erff(v10 * 0.70710678118654752f));
                v11 = 0.5f * v11 * (1.0f + erff(v11 * 0.70710678118654752f));
            }
            if (HASRES) {
                float2 r0 = *(const float2*)(res + orow_a * N + col);
                float2 r1 = *(const float2*)(res + orow_b * N + col);
                v00 += r0.x; v01 += r0.y; v10 += r1.x; v11 += r1.y;
            }
            if (ADDPE) {
                float2 p0 = *(const float2*)(pe + (size_t)pes_a * DMODEL + col);
                float2 p1 = *(const float2*)(pe + (size_t)pes_b * DMODEL + col);
                v00 += p0.x; v01 += p0.y; v10 += p1.x; v11 += p1.y;
            }
            if (OUTBF) {
                bf16* C = (bf16*)Cout;
                __nv_bfloat162 p0 = __floats2bfloat162_rn(v00, v01);
                __nv_bfloat162 p1 = __floats2bfloat162_rn(v10, v11);
                *reinterpret_cast<uint32_t*>(C + orow_a * N + col) = *reinterpret_cast<uint32_t*>(&p0);
                *reinterpret_cast<uint32_t*>(C + orow_b * N + col) = *reinterpret_cast<uint32_t*>(&p1);
            } else {
                float* C = (float*)Cout;
                *(float2*)(C + orow_a * N + col) = make_float2(v00, v01);
                *(float2*)(C + orow_b * N + col) = make_float2(v10, v11);
            }
        }
    }
}

// ---------------- LayerNorm: warp per row, bf16 out -------------------------
__global__ void ln_kernel(const float* __restrict__ x,
                          const float* __restrict__ g,
                          const float* __restrict__ b,
                          bf16* __restrict__ y)
{
    const int row  = blockIdx.x * 8 + (threadIdx.x >> 5);
    const int lane = threadIdx.x & 31;
    const float4* xp = (const float4*)(x + (size_t)row * DMODEL);
    float4 u = xp[lane * 2], w = xp[lane * 2 + 1];

    float s = u.x + u.y + u.z + u.w + w.x + w.y + w.z + w.w;
#pragma unroll
    for (int off = 16; off; off >>= 1) s += __shfl_xor_sync(0xffffffffu, s, off);
    float mu = s * (1.f / DMODEL);

    float d0 = u.x - mu, d1 = u.y - mu, d2 = u.z - mu, d3 = u.w - mu;
    float d4 = w.x - mu, d5 = w.y - mu, d6 = w.z - mu, d7 = w.w - mu;
    float s2 = d0*d0 + d1*d1 + d2*d2 + d3*d3 + d4*d4 + d5*d5 + d6*d6 + d7*d7;
#pragma unroll
    for (int off = 16; off; off >>= 1) s2 += __shfl_xor_sync(0xffffffffu, s2, off);
    float inv = rsqrtf(s2 * (1.f / DMODEL) + LNEPS);

    const float4* gp = (const float4*)g;
    const float4* bp = (const float4*)b;
    float4 g0 = gp[lane * 2], g1 = gp[lane * 2 + 1];
    float4 b0 = bp[lane * 2], b1 = bp[lane * 2 + 1];

    __nv_bfloat162 p0 = __floats2bfloat162_rn(d0 * inv * g0.x + b0.x, d1 * inv * g0.y + b0.y);
    __nv_bfloat162 p1 = __floats2bfloat162_rn(d2 * inv * g0.z + b0.z, d3 * inv * g0.w + b0.w);
    __nv_bfloat162 p2 = __floats2bfloat162_rn(d4 * inv * g1.x + b1.x, d5 * inv * g1.y + b1.y);
    __nv_bfloat162 p3 = __floats2bfloat162_rn(d6 * inv * g1.z + b1.z, d7 * inv * g1.w + b1.w);
    uint4 o;
    o.x = *reinterpret_cast<uint32_t*>(&p0);
    o.y = *reinterpret_cast<uint32_t*>(&p1);
    o.z = *reinterpret_cast<uint32_t*>(&p2);
    o.w = *reinterpret_cast<uint32_t*>(&p3);
    *reinterpret_cast<uint4*>(y + (size_t)row * DMODEL + lane * 8) = o;
}

// ---------------- fused per-head QKV projection, 32 rows/block ---------------
// grid (B*H, ceil(S/32)), block 256. Weights staged once per 32 rows.
__global__ void qkv_kernel(const bf16* __restrict__ x1,
                           const float* __restrict__ wq, const float* __restrict__ bq,
                           const float* __restrict__ wk, const float* __restrict__ bk,
                           const float* __restrict__ wv, const float* __restrict__ bv,
                           bf16* __restrict__ q, bf16* __restrict__ k, bf16* __restrict__ v)
{
    __shared__ float wqs[32 * 33], wks[32 * 33], wvs[32 * 33];
    __shared__ float bqs[32], bks[32], bvs[32];
    __shared__ float xr[32 * 33];
    const int nh = blockIdx.x;
    const int n = nh / NHEAD, h = nh % NHEAD;
    const int t = threadIdx.x;
    const float* wqg = wq + (size_t)h * DH * DH;
    const float* wkg = wk + (size_t)h * DH * DH;
    const float* wvg = wv + (size_t)h * DH * DH;

    for (int i = t; i < DH * DH; i += 256) {
        int e = i >> 5, d = i & 31;
        wqs[e * 33 + d] = wqg[i];
        wks[e * 33 + d] = wkg[i];
        wvs[e * 33 + d] = wvg[i];
    }
    if (t < 32) { bqs[t] = bq[h * DH + t]; bks[t] = bk[h * DH + t]; bvs[t] = bv[h * DH + t]; }

    // stage 32 rows of x1 for this head
    const int s0 = blockIdx.y * 32;
    for (int i = t; i < 32 * 32; i += 256) {
        int r = i >> 5, d = i & 31;
        int s = s0 + r;
        xr[r * 33 + d] = (s < SEQ)
            ? __bfloat162float(x1[((size_t)n * SEQ + s) * DMODEL + h * DH + d])
            : 0.f;
    }
    __syncthreads();

    // thread = (row-group = warp, e = lane); each warp does 4 rows
    const int wr = (t >> 5) * 4, lane = t & 31;
    const float bqv = bqs[lane], bkv = bks[lane], bvv = bvs[lane];
#pragma unroll
    for (int r = 0; r < 4; r++) {
        int s = s0 + wr + r;
        if (s >= SEQ) break;
        const float* xp = xr + (wr + r) * 33;
        float aq = bqv, ak = bkv, av = bvv;
#pragma unroll
        for (int d = 0; d < 32; d++) {
            float xv = xp[d];
            aq += xv * wqs[lane * 33 + d];
            ak += xv * wks[lane * 33 + d];
            av += xv * wvs[lane * 33 + d];
        }
        size_t oidx = ((size_t)nh * SEQ + s) * DH + lane;
        q[oidx] = __float2bfloat16(aq);
        k[oidx] = __float2bfloat16(ak);
        v[oidx] = __float2bfloat16(av);
    }
}

// ---------------- tensor-core flash attention per (n,h) ---------------------
#define SPAD 224
#define NKT  7
#define KSTR 20
#define VSTR 116

__global__ void __launch_bounds__(224) attn_tc(const bf16* __restrict__ q,
                                               const bf16* __restrict__ k,
                                               const bf16* __restrict__ v,
                                               bf16* __restrict__ o)
{
    __shared__ uint32_t Ks[SPAD * KSTR];
    __shared__ uint32_t VT[32 * VSTR];

    const int nh = blockIdx.x;
    const int n = nh / NHEAD, h = nh % NHEAD;
    const int t = threadIdx.x, warp = t >> 5, lane = t & 31;
    const int g = lane >> 2, q4 = lane & 3;
    const size_t base = (size_t)nh * SEQ * DH;
    const uint32_t* q32 = (const uint32_t*)(q + base);
    const uint32_t* k32 = (const uint32_t*)(k + base);
    const uint32_t* v32 = (const uint32_t*)(v + base);

    for (int i = t; i < SPAD * 16; i += 224) {
        int r = i >> 4, c = i & 15;
        Ks[r * KSTR + c] = (r < SEQ) ? k32[r * 16 + c] : 0u;
    }
    // V transpose staging (vectorized u32 loads)
    bf16* VT16 = (bf16*)VT;
    for (int i = t; i < SPAD * 16; i += 224) {
        int tt = i >> 4, c = i & 15;
        uint32_t val = (tt < SEQ) ? v32[tt * 16 + c] : 0u;
        __nv_bfloat162 pr = *reinterpret_cast<__nv_bfloat162*>(&val);
        VT16[(2 * c)     * (VSTR * 2) + tt] = pr.x;
        VT16[(2 * c + 1) * (VSTR * 2) + tt] = pr.y;
    }
    __syncthreads();

    const int qbase = warp * 32;
    uint32_t qf[2][2][4];
#pragma unroll
    for (int mi = 0; mi < 2; mi++) {
        int r0 = qbase + mi * 16 + g, r1 = r0 + 8;
        bool v0 = r0 < SEQ, v1 = r1 < SEQ;
#pragma unroll
        for (int ks = 0; ks < 2; ks++) {
            qf[mi][ks][0] = v0 ? q32[r0 * 16 + ks * 8 + q4]     : 0u;
            qf[mi][ks][1] = v1 ? q32[r1 * 16 + ks * 8 + q4]     : 0u;
            qf[mi][ks][2] = v0 ? q32[r0 * 16 + ks * 8 + q4 + 4] : 0u;
            qf[mi][ks][3] = v1 ? q32[r1 * 16 + ks * 8 + q4 + 4] : 0u;
        }
    }

    float Oa[2][4][4];
#pragma unroll
    for (int mi = 0; mi < 2; mi++)
#pragma unroll
        for (int ne = 0; ne < 4; ne++)
#pragma unroll
            for (int e = 0; e < 4; e++) Oa[mi][ne][e] = 0.f;
    float m_[2][2] = {{-1e30f, -1e30f}, {-1e30f, -1e30f}};
    float l_[2][2] = {{0.f, 0.f}, {0.f, 0.f}};
    const float scale = 0.17677669529663689f;

    for (int kt = 0; kt < NKT; kt++) {
        float sc[2][4][4];
#pragma unroll
        for (int mi = 0; mi < 2; mi++)
#pragma unroll
            for (int ni = 0; ni < 4; ni++)
#pragma unroll
                for (int e = 0; e < 4; e++) sc[mi][ni][e] = 0.f;

        uint32_t kf[2][4][2];
#pragma unroll
        for (int ks = 0; ks < 2; ks++)
#pragma unroll
            for (int ni = 0; ni < 4; ni++) {
                int r = kt * 32 + ni * 8 + g;
                kf[ks][ni][0] = Ks[r * KSTR + ks * 8 + q4];
                kf[ks][ni][1] = Ks[r * KSTR + ks * 8 + q4 + 4];
            }
#pragma unroll
        for (int mi = 0; mi < 2; mi++)
#pragma unroll
            for (int ni = 0; ni < 4; ni++)
#pragma unroll
                for (int ks = 0; ks < 2; ks++)
                    mma_bf16(sc[mi][ni], qf[mi][ks], kf[ks][ni]);

#pragma unroll
        for (int mi = 0; mi < 2; mi++) {
#pragma unroll
            for (int hf = 0; hf < 2; hf++) {
                float mx = -1e30f;
#pragma unroll
                for (int ni = 0; ni < 4; ni++) {
                    int col = kt * 32 + ni * 8 + q4 * 2;
                    float s0 = (col     < SEQ) ? sc[mi][ni][hf * 2]     * scale : -1e30f;
                    float s1 = (col + 1 < SEQ) ? sc[mi][ni][hf * 2 + 1] * scale : -1e30f;
                    sc[mi][ni][hf * 2]     = s0;
                    sc[mi][ni][hf * 2 + 1] = s1;
                    mx = fmaxf(mx, fmaxf(s0, s1));
                }
                mx = fmaxf(mx, __shfl_xor_sync(0xffffffffu, mx, 1));
                mx = fmaxf(mx, __shfl_xor_sync(0xffffffffu, mx, 2));
                float mnew = fmaxf(m_[mi][hf], mx);
                float f = __expf(m_[mi][hf] - mnew);
                m_[mi][hf] = mnew;
                float rs = 0.f;
#pragma unroll
                for (int ni = 0; ni < 4; ni++) {
                    float p0 = __expf(sc[mi][ni][hf * 2]     - mnew);
                    float p1 = __expf(sc[mi][ni][hf * 2 + 1] - mnew);
                    sc[mi][ni][hf * 2]     = p0;
                    sc[mi][ni][hf * 2 + 1] = p1;
                    rs += p0 + p1;
                }
                rs += __shfl_xor_sync(0xffffffffu, rs, 1);
                rs += __shfl_xor_sync(0xffffffffu, rs, 2);
                l_[mi][hf] = l_[mi][hf] * f + rs;
#pragma unroll
                for (int ne = 0; ne < 4; ne++) {
                    Oa[mi][ne][hf * 2]     *= f;
                    Oa[mi][ne][hf * 2 + 1] *= f;
                }
            }
        }

        uint32_t pa[2][2][4];
#pragma unroll
        for (int mi = 0; mi < 2; mi++)
#pragma unroll
            for (int ks = 0; ks < 2; ks++) {
                __nv_bfloat162 t0 = __floats2bfloat162_rn(sc[mi][2 * ks][0],     sc[mi][2 * ks][1]);
                __nv_bfloat162 t1 = __floats2bfloat162_rn(sc[mi][2 * ks][2],     sc[mi][2 * ks][3]);
                __nv_bfloat162 t2 = __floats2bfloat162_rn(sc[mi][2 * ks + 1][0], sc[mi][2 * ks + 1][1]);
                __nv_bfloat162 t3 = __floats2bfloat162_rn(sc[mi][2 * ks + 1][2], sc[mi][2 * ks + 1][3]);
                pa[mi][ks][0] = *reinterpret_cast<uint32_t*>(&t0);
                pa[mi][ks][1] = *reinterpret_cast<uint32_t*>(&t1);
                pa[mi][ks][2] = *reinterpret_cast<uint32_t*>(&t2);
                pa[mi][ks][3] = *reinterpret_cast<uint32_t*>(&t3);
            }

        uint32_t vf[2][4][2];
#pragma unroll
        for (int ks = 0; ks < 2; ks++)
#pragma unroll
            for (int ne = 0; ne < 4; ne++) {
                int r = ne * 8 + g;
                int cu = kt * 16 + ks * 8 + q4;
                vf[ks][ne][0] = VT[r * VSTR + cu];
                vf[ks][ne][1] = VT[r * VSTR + cu + 4];
            }
#pragma unroll
        for (int mi = 0; mi < 2; mi++)
#pragma unroll
            for (int ne = 0; ne < 4; ne++)
#pragma unroll
                for (int ks = 0; ks < 2; ks++)
                    mma_bf16(Oa[mi][ne], pa[mi][ks], vf[ks][ne]);
    }

#pragma unroll
    for (int mi = 0; mi < 2; mi++) {
#pragma unroll
        for (int hf = 0; hf < 2; hf++) {
            int row = qbase + mi * 16 + hf * 8 + g;
            if (row >= SEQ) continue;
            float inv = 1.f / l_[mi][hf];
            bf16* op = o + ((size_t)n * SEQ + row) * DMODEL + h * DH;
#pragma unroll
            for (int ne = 0; ne < 4; ne++) {
                __nv_bfloat162 p = __floats2bfloat162_rn(Oa[mi][ne][hf * 2] * inv,
                                                         Oa[mi][ne][hf * 2 + 1] * inv);
                *reinterpret_cast<uint32_t*>(op + ne * 8 + q4 * 2) = *reinterpret_cast<uint32_t*>(&p);
            }
        }
    }
}

// ---------------- classification head ---------------------------------------
__global__ void head_kernel(const float* __restrict__ X, const float* __restrict__ w_out,
                            const float* __restrict__ b_out, float* __restrict__ out)
{
    __shared__ float cls_s[DMODEL];
    __shared__ float logits[OUTC];
    __shared__ float red[8];
    const int n = blockIdx.x;
    const int t = threadIdx.x, wid = t >> 5, lane = t & 31;

    cls_s[t] = X[(size_t)n * SEQ * DMODEL + t];
    __syncthreads();

    for (int j = wid; j < OUTC; j += 8) {
        float acc = 0.f;
#pragma unroll
        for (int k = lane; k < DMODEL; k += 32) acc += cls_s[k] * w_out[(size_t)j * DMODEL + k];
#pragma unroll
        for (int off = 16; off; off >>= 1) acc += __shfl_xor_sync(0xffffffffu, acc, off);
        if (lane == 0) logits[j] = acc + b_out[j];
    }
    __syncthreads();

    float mx = -1e30f;
    for (int j = t; j < OUTC; j += 256) mx = fmaxf(mx, logits[j]);
#pragma unroll
    for (int off = 16; off; off >>= 1) mx = fmaxf(mx, __shfl_xor_sync(0xffffffffu, mx, off));
    if (lane == 0) red[wid] = mx;
    __syncthreads();
    float bm = -1e30f;
#pragma unroll
    for (int i = 0; i < 8; i++) bm = fmaxf(bm, red[i]);
    __syncthreads();

    float sum = 0.f;
    for (int j = t; j < OUTC; j += 256) {
        float e = __expf(logits[j] - bm);
        logits[j] = e;
        sum += e;
    }
#pragma unroll
    for (int off = 16; off; off >>= 1) sum += __shfl_xor_sync(0xffffffffu, sum, off);
    if (lane == 0) red[wid] = sum;
    __syncthreads();
    float bs = 0.f;
#pragma unroll
    for (int i = 0; i < 8; i++) bs += red[i];
    float inv = 1.f / bs;
    __syncthreads();
    for (int j = t; j < OUTC; j += 256) out[(size_t)n * OUTC + j] = logits[j] * inv;
}

// ---------------- launcher ----------------
extern "C" void kernel_launch(void* const* d_in, const int* in_sizes, int n_in,
                              void* d_out, int out_size)
{
    const float* images  = (const float*)d_in[0];
    const float* w_map   = (const float*)d_in[1];
    const float* b_map   = (const float*)d_in[2];
    const float* cls_tok = (const float*)d_in[3];
    const float* norm1_g = (const float*)d_in[4];
    const float* norm1_b = (const float*)d_in[5];
    const float* wq      = (const float*)d_in[6];
    const float* bq      = (const float*)d_in[7];
    const float* wk      = (const float*)d_in[8];
    const float* bk      = (const float*)d_in[9];
    const float* wv      = (const float*)d_in[10];
    const float* bv      = (const float*)d_in[11];
    const float* w_last  = (const float*)d_in[12];
    const float* b_last  = (const float*)d_in[13];
    const float* norm2_g = (const float*)d_in[14];
    const float* norm2_b = (const float*)d_in[15];
    const float* w_mlp1  = (const float*)d_in[16];
    const float* b_mlp1  = (const float*)d_in[17];
    const float* w_mlp2  = (const float*)d_in[18];
    const float* b_mlp2  = (const float*)d_in[19];
    const float* w_out   = (const float*)d_in[20];
    const float* b_out   = (const float*)d_in[21];
    float* out = (float*)d_out;

    bf16 *patches, *x1b, *qb, *kb, *vb, *ob, *h1b;
    bf16 *wmapb, *wlastb, *wmlp1b, *wmlp2b;
    float *X, *pe;
    cudaGetSymbolAddress((void**)&patches, g_patches_b);
    cudaGetSymbolAddress((void**)&X,   g_X);
    cudaGetSymbolAddress((void**)&x1b, g_x1b);
    cudaGetSymbolAddress((void**)&qb,  g_qb);
    cudaGetSymbolAddress((void**)&kb,  g_kb);
    cudaGetSymbolAddress((void**)&vb,  g_vb);
    cudaGetSymbolAddress((void**)&ob,  g_ob);
    cudaGetSymbolAddress((void**)&h1b, g_h1b);
    cudaGetSymbolAddress((void**)&pe,  g_pe);
    cudaGetSymbolAddress((void**)&wmapb,  g_wmapb);
    cudaGetSymbolAddress((void**)&wlastb, g_wlastb);
    cudaGetSymbolAddress((void**)&wmlp1b, g_wmlp1b);
    cudaGetSymbolAddress((void**)&wmlp2b, g_wmlp2b);

    cudaFuncSetAttribute(gemm_bf<0, false, false, true >, cudaFuncAttributeMaxDynamicSharedMemorySize, GEMM_SMEM);
    cudaFuncSetAttribute(gemm_bf<0, true,  false, false>, cudaFuncAttributeMaxDynamicSharedMemorySize, GEMM_SMEM);
    cudaFuncSetAttribute(gemm_bf<1, false, true,  false>, cudaFuncAttributeMaxDynamicSharedMemorySize, GEMM_SMEM);

    // 0) weight conversion to bf16, single launch
    {
        int n0 = DMODEL * IN_D;
        int n1 = NLAYER * DMODEL * DMODEL;
        int n3 = NLAYER * 4 * DMODEL * DMODEL;
        int totf4 = (n0 + n1 + 2 * n3) / 4;
        cvt_all_kernel<<<(totf4 + 255) / 256, 256>>>(
            w_map, wmapb, n0, w_last, wlastb, n1,
            w_mlp1, wmlp1b, n3, w_mlp2, wmlp2b, n3);
    }

    // 1) patches + PE table
    {
        int tot = BATCH * NP * IN_D;
        patch_kernel<<<(tot + 255) / 256, 256>>>(images, patches);
        int pt = SEQ * DMODEL;
        pe_kernel<<<(pt + 255) / 256, 256>>>(pe);
    }

    // 2) patch-embed GEMM fused with assemble: X[n][p+1][:] = patches@w_map^T + b + pe
    gemm_bf<0, false, false, true><<<dim3(DMODEL / 128, (BATCH * NP) / 128), 256, GEMM_SMEM>>>(
        patches, wmapb, b_map, nullptr, pe, X, BATCH * NP, DMODEL, IN_D);

    // 2b) cls rows
    cls_kernel<<<(BATCH * DMODEL + 255) / 256, 256>>>(cls_tok, pe, X);

    const int MROWS = BATCH * SEQ;   // 25216 = 128*197

    for (int l = 0; l < NLAYER; l++) {
        ln_kernel<<<MROWS / 8, 256>>>(X, norm1_g + l * DMODEL, norm1_b + l * DMODEL, x1b);

        qkv_kernel<<<dim3(BATCH * NHEAD, (SEQ + 31) / 32), 256>>>(
            x1b,
            wq + (size_t)l * NHEAD * DH * DH, bq + (size_t)l * NHEAD * DH,
            wk + (size_t)l * NHEAD * DH * DH, bk + (size_t)l * NHEAD * DH,
            wv + (size_t)l * NHEAD * DH * DH, bv + (size_t)l * NHEAD * DH,
            qb, kb, vb);

        attn_tc<<<BATCH * NHEAD, 224>>>(qb, kb, vb, ob);

        // o-proj + residual: X = X + o @ w_last^T + b_last (25216,256,256)
        gemm_bf<0, true, false, false><<<dim3(DMODEL / 128, MROWS / 128), 256, GEMM_SMEM>>>(
            ob, wlastb + (size_t)l * DMODEL * DMODEL, b_last + l * DMODEL, X, nullptr, X,
            MROWS, DMODEL, DMODEL);

        ln_kernel<<<MROWS / 8, 256>>>(X, norm2_g + l * DMODEL, norm2_b + l * DMODEL, x1b);

        // MLP1 + GELU -> bf16 h1 (25216,1024,256)
        gemm_bf<1, false, true, false><<<dim3((4 * DMODEL) / 128, MROWS / 128), 256, GEMM_SMEM>>>(
            x1b, wmlp1b + (size_t)l * 4 * DMODEL * DMODEL, b_mlp1 + l * 4 * DMODEL,
            nullptr, nullptr, h1b, MROWS, 4 * DMODEL, DMODEL);

        // MLP2 + residual: X = X + h1 @ w_mlp2^T + b2 (25216,256,1024)
        gemm_bf<0, true, false, false><<<dim3(DMODEL / 128, MROWS / 128), 256, GEMM_SMEM>>>(
            h1b, wmlp2b + (size_t)l * 4 * DMODEL * DMODEL, b_mlp2 + l * DMODEL, X, nullptr, X,
            MROWS, DMODEL, 4 * DMODEL);
    }

    head_kernel<<<BATCH, 256>>>(X, w_out, b_out, out);
}

// round 11
// speedup vs baseline: 1.2879x; 1.0309x over previous
#include <cuda_runtime.h>
#include <cuda_bf16.h>
#include <math.h>
#include <stdint.h>

// ---------------- problem constants ----------------
#define BATCH 128
#define CH    3
#define HIM   224
#define PGRID 14
#define NP    196
#define PATCH 16
#define IN_D  768
#define DMODEL 256
#define NHEAD 8
#define DH    32
#define NLAYER 4
#define SEQ   197
#define OUTC  1000
#define LNEPS 1e-5f

typedef __nv_bfloat16 bf16;

// ---------------- scratch (device globals) ----------------
__device__ bf16  g_patches_b[BATCH * NP * IN_D];
__device__ float g_X [BATCH * SEQ * DMODEL];
__device__ bf16  g_x1b[BATCH * SEQ * DMODEL];
__device__ bf16  g_qb [BATCH * SEQ * DMODEL];             // [n,h,s,e] (pre-scaled)
__device__ bf16  g_kb [BATCH * SEQ * DMODEL];
__device__ bf16  g_vb [BATCH * SEQ * DMODEL];
__device__ bf16  g_ob [BATCH * SEQ * DMODEL];             // [n,s,d]
__device__ bf16  g_h1b[BATCH * SEQ * 4 * DMODEL];
__device__ float g_pe[SEQ * DMODEL];
__device__ bf16  g_wmapb [DMODEL * IN_D];
__device__ bf16  g_wlastb[NLAYER * DMODEL * DMODEL];
__device__ bf16  g_wmlp1b[NLAYER * 4 * DMODEL * DMODEL];
__device__ bf16  g_wmlp2b[NLAYER * 4 * DMODEL * DMODEL];

// ---------------- fp32 -> bf16 convert, all weights in one launch ----------
__device__ __forceinline__ void cvt4(const float* __restrict__ s, bf16* __restrict__ d, int i)
{
    float4 v = *(const float4*)(s + i);
    __nv_bfloat162 p0 = __floats2bfloat162_rn(v.x, v.y);
    __nv_bfloat162 p1 = __floats2bfloat162_rn(v.z, v.w);
    uint2 o;
    o.x = *reinterpret_cast<uint32_t*>(&p0);
    o.y = *reinterpret_cast<uint32_t*>(&p1);
    *reinterpret_cast<uint2*>(d + i) = o;
}

__global__ void cvt_all_kernel(const float* __restrict__ s0, bf16* __restrict__ d0, int n0,
                               const float* __restrict__ s1, bf16* __restrict__ d1, int n1,
                               const float* __restrict__ s2, bf16* __restrict__ d2, int n2,
                               const float* __restrict__ s3, bf16* __restrict__ d3, int n3)
{
    int i = (blockIdx.x * 256 + threadIdx.x) * 4;
    if (i < n0) { cvt4(s0, d0, i); return; }
    i -= n0;
    if (i < n1) { cvt4(s1, d1, i); return; }
    i -= n1;
    if (i < n2) { cvt4(s2, d2, i); return; }
    i -= n2;
    if (i < n3) { cvt4(s3, d3, i); return; }
}

// ---------------- patch extraction (float4 gather, writes bf16) ------------
__global__ void patch_kernel(const float* __restrict__ img, bf16* __restrict__ out)
{
    int tid = blockIdx.x * 256 + threadIdx.x;
    int idx = tid * 4;
    if (idx >= BATCH * NP * IN_D) return;
    int i = idx % IN_D;
    int p = (idx / IN_D) % NP;
    int n = idx / (IN_D * NP);
    int c   = i >> 8;
    int r   = (i >> 4) & 15;
    int col = i & 15;               // 0,4,8,12
    int py = p / PGRID, px = p % PGRID;
    float4 v = *(const float4*)(img + (((size_t)n * CH + c) * HIM + py * PATCH + r) * HIM
                                    + px * PATCH + col);
    __nv_bfloat162 p0 = __floats2bfloat162_rn(v.x, v.y);
    __nv_bfloat162 p1 = __floats2bfloat162_rn(v.z, v.w);
    uint2 o;
    o.x = *reinterpret_cast<uint32_t*>(&p0);
    o.y = *reinterpret_cast<uint32_t*>(&p1);
    *reinterpret_cast<uint2*>(out + idx) = o;
}

// ---------------- positional encoding (fp64) ----------------
__global__ void pe_kernel(float* __restrict__ pe)
{
    int i = blockIdx.x * 256 + threadIdx.x;
    if (i >= SEQ * DMODEL) return;
    int s = i / DMODEL, d = i % DMODEL;
    double expo = (double)(2 * (d / 2)) / (double)DMODEL;
    double ang  = (double)s / pow(10000.0, expo);
    pe[i] = (float)((d & 1) ? cos(ang) : sin(ang));
}

// ---------------- cls rows: X[n][0][:] = cls + pe[0] ------------------------
__global__ void cls_kernel(const float* __restrict__ cls,
                           const float* __restrict__ pe,
                           float* __restrict__ X)
{
    int i = blockIdx.x * 256 + threadIdx.x;
    if (i >= BATCH * DMODEL) return;
    int d = i % DMODEL;
    int n = i / DMODEL;
    X[(size_t)n * SEQ * DMODEL + d] = cls[d] + pe[d];
}

// ---------------- bf16 MMA / ldmatrix helpers -------------------------------
__device__ __forceinline__ void mma_bf16(float* c, const uint32_t* a, const uint32_t* b)
{
    asm volatile(
        "mma.sync.aligned.m16n8k16.row.col.f32.bf16.bf16.f32 "
        "{%0,%1,%2,%3}, {%4,%5,%6,%7}, {%8,%9}, {%0,%1,%2,%3};"
        : "+f"(c[0]), "+f"(c[1]), "+f"(c[2]), "+f"(c[3])
        : "r"(a[0]), "r"(a[1]), "r"(a[2]), "r"(a[3]), "r"(b[0]), "r"(b[1]));
}

#define LDSM4(r0, r1, r2, r3, addr) \
    asm volatile("ldmatrix.sync.aligned.m8n8.x4.shared.b16 {%0,%1,%2,%3}, [%4];" \
                 : "=r"(r0), "=r"(r1), "=r"(r2), "=r"(r3) : "r"(addr))

#define CP16(dst, src) asm volatile("cp.async.cg.shared.global [%0], [%1], 16;\n" :: "r"(dst), "l"(src))
#define CP_COMMIT()    asm volatile("cp.async.commit_group;\n" ::)
#define CP_WAIT1()     asm volatile("cp.async.wait_group 1;\n" ::)
#define CP_WAIT0()     asm volatile("cp.async.wait_group 0;\n" ::)

// ---------------- bf16 tensor-core GEMM, 128x128 tile (frozen config) -------
#define STR 36                      // u32 stride per 64-bf16 row (pad 4) = 144B
#define ABUF (128 * STR)            // u32
#define GEMM_SMEM (4 * ABUF * 4)    // A0,A1,B0,B1 = 73728 B

template<int ACT, bool HASRES, bool OUTBF, bool ADDPE>
__global__ void __launch_bounds__(256) gemm_bf(const bf16* __restrict__ A,
                                               const bf16* __restrict__ W,
                                               const float* __restrict__ bias,
                                               const float* __restrict__ res,
                                               const float* __restrict__ pe,
                                               void* __restrict__ Cout,
                                               int M, int N, int K)
{
    extern __shared__ uint32_t sm_[];
    const uint32_t smem_byte = (uint32_t)__cvta_generic_to_shared(sm_);

    const int t    = threadIdx.x;
    const int warp = t >> 5, lane = t & 31;
    const int g    = lane >> 2, q4 = lane & 3;
    const int warp_m = (warp >> 1) * 32;
    const int warp_n = (warp & 1) * 64;
    const int row0 = blockIdx.y * 128, col0 = blockIdx.x * 128;

    float acc[2][8][4];
#pragma unroll
    for (int mi = 0; mi < 2; mi++)
#pragma unroll
        for (int ni = 0; ni < 8; ni++)
#pragma unroll
            for (int e = 0; e < 4; e++) acc[mi][ni][e] = 0.f;

    auto stage = [&](int k0, int buf) {
        uint32_t abase = smem_byte + buf * (ABUF * 4);
        uint32_t bbase = smem_byte + (2 + buf) * (ABUF * 4);
#pragma unroll
        for (int i = 0; i < 4; i++) {
            int c = t + i * 256;
            int r = c >> 3, co = c & 7;
            CP16(abase + (r * STR + co * 4) * 4, A + (size_t)(row0 + r) * K + k0 + co * 8);
            CP16(bbase + (r * STR + co * 4) * 4, W + (size_t)(col0 + r) * K + k0 + co * 8);
        }
        CP_COMMIT();
    };

    uint32_t a_addr[2][2], b_addr[2][4];
    {
        int ar = warp_m + (lane & 15);
        int ab = (lane >> 4) * 16;
        int br = warp_n + ((lane >> 4) & 1) * 8 + (lane & 7);
        int bb = ((lane >> 3) & 1) * 16;
#pragma unroll
        for (int buf = 0; buf < 2; buf++) {
            uint32_t abase = smem_byte + buf * (ABUF * 4);
            uint32_t bbase = smem_byte + (2 + buf) * (ABUF * 4);
#pragma unroll
            for (int mi = 0; mi < 2; mi++)
                a_addr[buf][mi] = abase + (ar + mi * 16) * (STR * 4) + ab;
#pragma unroll
            for (int nj = 0; nj < 4; nj++)
                b_addr[buf][nj] = bbase + (br + nj * 16) * (STR * 4) + bb;
        }
    }

    const int KT = K >> 6;
    stage(0, 0);

    for (int kt = 0; kt < KT; kt++) {
        const int cur = kt & 1;
        if (kt + 1 < KT) { stage((kt + 1) << 6, cur ^ 1); CP_WAIT1(); }
        else             { CP_WAIT0(); }
        __syncthreads();

#pragma unroll
        for (int ks = 0; ks < 4; ks++) {
            const uint32_t kb = ks * 32;
            uint32_t af[2][4];
            LDSM4(af[0][0], af[0][1], af[0][2], af[0][3], a_addr[cur][0] + kb);
            LDSM4(af[1][0], af[1][1], af[1][2], af[1][3], a_addr[cur][1] + kb);
            uint32_t bf_[8][2];
#pragma unroll
            for (int nj = 0; nj < 4; nj++)
                LDSM4(bf_[2 * nj][0], bf_[2 * nj][1], bf_[2 * nj + 1][0], bf_[2 * nj + 1][1],
                      b_addr[cur][nj] + kb);
#pragma unroll
            for (int mi = 0; mi < 2; mi++)
#pragma unroll
                for (int ni = 0; ni < 8; ni++)
                    mma_bf16(acc[mi][ni], af[mi], bf_[ni]);
        }
        __syncthreads();
    }

    // epilogue
#pragma unroll
    for (int mi = 0; mi < 2; mi++) {
        int ra = row0 + warp_m + mi * 16 + g;
        int rb = ra + 8;
        size_t orow_a, orow_b;
        if (ADDPE) {
            orow_a = (size_t)(ra / NP) * SEQ + (ra % NP) + 1;
            orow_b = (size_t)(rb / NP) * SEQ + (rb % NP) + 1;
        } else {
            orow_a = ra; orow_b = rb;
        }
        int pes_a = ADDPE ? ((ra % NP) + 1) : 0;
        int pes_b = ADDPE ? ((rb % NP) + 1) : 0;
#pragma unroll
        for (int ni = 0; ni < 8; ni++) {
            int col = col0 + warp_n + ni * 8 + q4 * 2;
            float b0 = bias[col], b1 = bias[col + 1];
            float v00 = acc[mi][ni][0] + b0, v01 = acc[mi][ni][1] + b1;
            float v10 = acc[mi][ni][2] + b0, v11 = acc[mi][ni][3] + b1;
            if (ACT == 1) {
                v00 = 0.5f * v00 * (1.0f + erff(v00 * 0.70710678118654752f));
                v01 = 0.5f * v01 * (1.0f + erff(v01 * 0.70710678118654752f));
                v10 = 0.5f * v10 * (1.0f + erff(v10 * 0.70710678118654752f));
                v11 = 0.5f * v11 * (1.0f + erff(v11 * 0.70710678118654752f));
            }
            if (HASRES) {
                float2 r0 = *(const float2*)(res + orow_a * N + col);
                float2 r1 = *(const float2*)(res + orow_b * N + col);
                v00 += r0.x; v01 += r0.y; v10 += r1.x; v11 += r1.y;
            }
            if (ADDPE) {
                float2 p0 = *(const float2*)(pe + (size_t)pes_a * DMODEL + col);
                float2 p1 = *(const float2*)(pe + (size_t)pes_b * DMODEL + col);
                v00 += p0.x; v01 += p0.y; v10 += p1.x; v11 += p1.y;
            }
            if (OUTBF) {
                bf16* C = (bf16*)Cout;
                __nv_bfloat162 p0 = __floats2bfloat162_rn(v00, v01);
                __nv_bfloat162 p1 = __floats2bfloat162_rn(v10, v11);
                *reinterpret_cast<uint32_t*>(C + orow_a * N + col) = *reinterpret_cast<uint32_t*>(&p0);
                *reinterpret_cast<uint32_t*>(C + orow_b * N + col) = *reinterpret_cast<uint32_t*>(&p1);
            } else {
                float* C = (float*)Cout;
                *(float2*)(C + orow_a * N + col) = make_float2(v00, v01);
                *(float2*)(C + orow_b * N + col) = make_float2(v10, v11);
            }
        }
    }
}

// ---------------- LayerNorm: warp per row, bf16 out -------------------------
__global__ void ln_kernel(const float* __restrict__ x,
                          const float* __restrict__ g,
                          const float* __restrict__ b,
                          bf16* __restrict__ y)
{
    const int row  = blockIdx.x * 8 + (threadIdx.x >> 5);
    const int lane = threadIdx.x & 31;
    const float4* xp = (const float4*)(x + (size_t)row * DMODEL);
    float4 u = xp[lane * 2], w = xp[lane * 2 + 1];

    float s = u.x + u.y + u.z + u.w + w.x + w.y + w.z + w.w;
#pragma unroll
    for (int off = 16; off; off >>= 1) s += __shfl_xor_sync(0xffffffffu, s, off);
    float mu = s * (1.f / DMODEL);

    float d0 = u.x - mu, d1 = u.y - mu, d2 = u.z - mu, d3 = u.w - mu;
    float d4 = w.x - mu, d5 = w.y - mu, d6 = w.z - mu, d7 = w.w - mu;
    float s2 = d0*d0 + d1*d1 + d2*d2 + d3*d3 + d4*d4 + d5*d5 + d6*d6 + d7*d7;
#pragma unroll
    for (int off = 16; off; off >>= 1) s2 += __shfl_xor_sync(0xffffffffu, s2, off);
    float inv = rsqrtf(s2 * (1.f / DMODEL) + LNEPS);

    const float4* gp = (const float4*)g;
    const float4* bp = (const float4*)b;
    float4 g0 = gp[lane * 2], g1 = gp[lane * 2 + 1];
    float4 b0 = bp[lane * 2], b1 = bp[lane * 2 + 1];

    __nv_bfloat162 p0 = __floats2bfloat162_rn(d0 * inv * g0.x + b0.x, d1 * inv * g0.y + b0.y);
    __nv_bfloat162 p1 = __floats2bfloat162_rn(d2 * inv * g0.z + b0.z, d3 * inv * g0.w + b0.w);
    __nv_bfloat162 p2 = __floats2bfloat162_rn(d4 * inv * g1.x + b1.x, d5 * inv * g1.y + b1.y);
    __nv_bfloat162 p3 = __floats2bfloat162_rn(d6 * inv * g1.z + b1.z, d7 * inv * g1.w + b1.w);
    uint4 o;
    o.x = *reinterpret_cast<uint32_t*>(&p0);
    o.y = *reinterpret_cast<uint32_t*>(&p1);
    o.z = *reinterpret_cast<uint32_t*>(&p2);
    o.w = *reinterpret_cast<uint32_t*>(&p3);
    *reinterpret_cast<uint4*>(y + (size_t)row * DMODEL + lane * 8) = o;
}

// ---------------- fused per-head QKV projection, 32 rows/block ---------------
// q output pre-scaled by 1/sqrt(DH).
__global__ void qkv_kernel(const bf16* __restrict__ x1,
                           const float* __restrict__ wq, const float* __restrict__ bq,
                           const float* __restrict__ wk, const float* __restrict__ bk,
                           const float* __restrict__ wv, const float* __restrict__ bv,
                           bf16* __restrict__ q, bf16* __restrict__ k, bf16* __restrict__ v)
{
    __shared__ float wqs[32 * 33], wks[32 * 33], wvs[32 * 33];
    __shared__ float bqs[32], bks[32], bvs[32];
    __shared__ float xr[32 * 33];
    const int nh = blockIdx.x;
    const int n = nh / NHEAD, h = nh % NHEAD;
    const int t = threadIdx.x;
    const float* wqg = wq + (size_t)h * DH * DH;
    const float* wkg = wk + (size_t)h * DH * DH;
    const float* wvg = wv + (size_t)h * DH * DH;

    for (int i = t; i < DH * DH; i += 256) {
        int e = i >> 5, d = i & 31;
        wqs[e * 33 + d] = wqg[i];
        wks[e * 33 + d] = wkg[i];
        wvs[e * 33 + d] = wvg[i];
    }
    if (t < 32) { bqs[t] = bq[h * DH + t]; bks[t] = bk[h * DH + t]; bvs[t] = bv[h * DH + t]; }

    const int s0 = blockIdx.y * 32;
    for (int i = t; i < 32 * 32; i += 256) {
        int r = i >> 5, d = i & 31;
        int s = s0 + r;
        xr[r * 33 + d] = (s < SEQ)
            ? __bfloat162float(x1[((size_t)n * SEQ + s) * DMODEL + h * DH + d])
            : 0.f;
    }
    __syncthreads();

    const float scale = 0.17677669529663689f;  // 1/sqrt(32)
    const int wr = (t >> 5) * 4, lane = t & 31;
    const float bqv = bqs[lane], bkv = bks[lane], bvv = bvs[lane];
#pragma unroll
    for (int r = 0; r < 4; r++) {
        int s = s0 + wr + r;
        if (s >= SEQ) break;
        const float* xp = xr + (wr + r) * 33;
        float aq = bqv, ak = bkv, av = bvv;
#pragma unroll
        for (int d = 0; d < 32; d++) {
            float xv = xp[d];
            aq += xv * wqs[lane * 33 + d];
            ak += xv * wks[lane * 33 + d];
            av += xv * wvs[lane * 33 + d];
        }
        size_t oidx = ((size_t)nh * SEQ + s) * DH + lane;
        q[oidx] = __float2bfloat16(aq * scale);
        k[oidx] = __float2bfloat16(ak);
        v[oidx] = __float2bfloat16(av);
    }
}

// ---------------- tensor-core flash attention per (n,h) ---------------------
// q is pre-scaled; kt=0..5 unmasked, kt=6 masked (peeled).
#define SPAD 224
#define NKT  7
#define KSTR 20
#define VSTR 116

__global__ void __launch_bounds__(224) attn_tc(const bf16* __restrict__ q,
                                               const bf16* __restrict__ k,
                                               const bf16* __restrict__ v,
                                               bf16* __restrict__ o)
{
    __shared__ uint32_t Ks[SPAD * KSTR];
    __shared__ uint32_t VT[32 * VSTR];

    const int nh = blockIdx.x;
    const int n = nh / NHEAD, h = nh % NHEAD;
    const int t = threadIdx.x, warp = t >> 5, lane = t & 31;
    const int g = lane >> 2, q4 = lane & 3;
    const size_t base = (size_t)nh * SEQ * DH;
    const uint32_t* q32 = (const uint32_t*)(q + base);
    const uint32_t* k32 = (const uint32_t*)(k + base);
    const uint32_t* v32 = (const uint32_t*)(v + base);

    for (int i = t; i < SPAD * 16; i += 224) {
        int r = i >> 4, c = i & 15;
        Ks[r * KSTR + c] = (r < SEQ) ? k32[r * 16 + c] : 0u;
    }
    bf16* VT16 = (bf16*)VT;
    for (int i = t; i < SPAD * 16; i += 224) {
        int tt = i >> 4, c = i & 15;
        uint32_t val = (tt < SEQ) ? v32[tt * 16 + c] : 0u;
        __nv_bfloat162 pr = *reinterpret_cast<__nv_bfloat162*>(&val);
        VT16[(2 * c)     * (VSTR * 2) + tt] = pr.x;
        VT16[(2 * c + 1) * (VSTR * 2) + tt] = pr.y;
    }
    __syncthreads();

    const int qbase = warp * 32;
    uint32_t qf[2][2][4];
#pragma unroll
    for (int mi = 0; mi < 2; mi++) {
        int r0 = qbase + mi * 16 + g, r1 = r0 + 8;
        bool v0 = r0 < SEQ, v1 = r1 < SEQ;
#pragma unroll
        for (int ks = 0; ks < 2; ks++) {
            qf[mi][ks][0] = v0 ? q32[r0 * 16 + ks * 8 + q4]     : 0u;
            qf[mi][ks][1] = v1 ? q32[r1 * 16 + ks * 8 + q4]     : 0u;
            qf[mi][ks][2] = v0 ? q32[r0 * 16 + ks * 8 + q4 + 4] : 0u;
            qf[mi][ks][3] = v1 ? q32[r1 * 16 + ks * 8 + q4 + 4] : 0u;
        }
    }

    float Oa[2][4][4];
#pragma unroll
    for (int mi = 0; mi < 2; mi++)
#pragma unroll
        for (int ne = 0; ne < 4; ne++)
#pragma unroll
            for (int e = 0; e < 4; e++) Oa[mi][ne][e] = 0.f;
    float m_[2][2] = {{-1e30f, -1e30f}, {-1e30f, -1e30f}};
    float l_[2][2] = {{0.f, 0.f}, {0.f, 0.f}};

    auto body = [&](int kt, bool last_mask) {
        float sc[2][4][4];
#pragma unroll
        for (int mi = 0; mi < 2; mi++)
#pragma unroll
            for (int ni = 0; ni < 4; ni++)
#pragma unroll
                for (int e = 0; e < 4; e++) sc[mi][ni][e] = 0.f;

        uint32_t kf[2][4][2];
#pragma unroll
        for (int ks = 0; ks < 2; ks++)
#pragma unroll
            for (int ni = 0; ni < 4; ni++) {
                int r = kt * 32 + ni * 8 + g;
                kf[ks][ni][0] = Ks[r * KSTR + ks * 8 + q4];
                kf[ks][ni][1] = Ks[r * KSTR + ks * 8 + q4 + 4];
            }
#pragma unroll
        for (int mi = 0; mi < 2; mi++)
#pragma unroll
            for (int ni = 0; ni < 4; ni++)
#pragma unroll
                for (int ks = 0; ks < 2; ks++)
                    mma_bf16(sc[mi][ni], qf[mi][ks], kf[ks][ni]);

        if (last_mask) {
#pragma unroll
            for (int mi = 0; mi < 2; mi++)
#pragma unroll
                for (int ni = 0; ni < 4; ni++) {
                    int col = kt * 32 + ni * 8 + q4 * 2;
#pragma unroll
                    for (int hf = 0; hf < 2; hf++) {
                        if (col     >= SEQ) sc[mi][ni][hf * 2]     = -1e30f;
                        if (col + 1 >= SEQ) sc[mi][ni][hf * 2 + 1] = -1e30f;
                    }
                }
        }

#pragma unroll
        for (int mi = 0; mi < 2; mi++) {
#pragma unroll
            for (int hf = 0; hf < 2; hf++) {
                float mx = fmaxf(fmaxf(sc[mi][0][hf * 2], sc[mi][0][hf * 2 + 1]),
                                 fmaxf(sc[mi][1][hf * 2], sc[mi][1][hf * 2 + 1]));
                mx = fmaxf(mx, fmaxf(fmaxf(sc[mi][2][hf * 2], sc[mi][2][hf * 2 + 1]),
                                     fmaxf(sc[mi][3][hf * 2], sc[mi][3][hf * 2 + 1])));
                mx = fmaxf(mx, __shfl_xor_sync(0xffffffffu, mx, 1));
                mx = fmaxf(mx, __shfl_xor_sync(0xffffffffu, mx, 2));
                float mnew = fmaxf(m_[mi][hf], mx);
                float f = __expf(m_[mi][hf] - mnew);
                m_[mi][hf] = mnew;
                float rs = 0.f;
#pragma unroll
                for (int ni = 0; ni < 4; ni++) {
                    float p0 = __expf(sc[mi][ni][hf * 2]     - mnew);
                    float p1 = __expf(sc[mi][ni][hf * 2 + 1] - mnew);
                    sc[mi][ni][hf * 2]     = p0;
                    sc[mi][ni][hf * 2 + 1] = p1;
                    rs += p0 + p1;
                }
                rs += __shfl_xor_sync(0xffffffffu, rs, 1);
                rs += __shfl_xor_sync(0xffffffffu, rs, 2);
                l_[mi][hf] = l_[mi][hf] * f + rs;
#pragma unroll
                for (int ne = 0; ne < 4; ne++) {
                    Oa[mi][ne][hf * 2]     *= f;
                    Oa[mi][ne][hf * 2 + 1] *= f;
                }
            }
        }

        uint32_t pa[2][2][4];
#pragma unroll
        for (int mi = 0; mi < 2; mi++)
#pragma unroll
            for (int ks = 0; ks < 2; ks++) {
                __nv_bfloat162 t0 = __floats2bfloat162_rn(sc[mi][2 * ks][0],     sc[mi][2 * ks][1]);
                __nv_bfloat162 t1 = __floats2bfloat162_rn(sc[mi][2 * ks][2],     sc[mi][2 * ks][3]);
                __nv_bfloat162 t2 = __floats2bfloat162_rn(sc[mi][2 * ks + 1][0], sc[mi][2 * ks + 1][1]);
                __nv_bfloat162 t3 = __floats2bfloat162_rn(sc[mi][2 * ks + 1][2], sc[mi][2 * ks + 1][3]);
                pa[mi][ks][0] = *reinterpret_cast<uint32_t*>(&t0);
                pa[mi][ks][1] = *reinterpret_cast<uint32_t*>(&t1);
                pa[mi][ks][2] = *reinterpret_cast<uint32_t*>(&t2);
                pa[mi][ks][3] = *reinterpret_cast<uint32_t*>(&t3);
            }

        uint32_t vf[2][4][2];
#pragma unroll
        for (int ks = 0; ks < 2; ks++)
#pragma unroll
            for (int ne = 0; ne < 4; ne++) {
                int r = ne * 8 + g;
                int cu = kt * 16 + ks * 8 + q4;
                vf[ks][ne][0] = VT[r * VSTR + cu];
                vf[ks][ne][1] = VT[r * VSTR + cu + 4];
            }
#pragma unroll
        for (int mi = 0; mi < 2; mi++)
#pragma unroll
            for (int ne = 0; ne < 4; ne++)
#pragma unroll
                for (int ks = 0; ks < 2; ks++)
                    mma_bf16(Oa[mi][ne], pa[mi][ks], vf[ks][ne]);
    };

    for (int kt = 0; kt < NKT - 1; kt++) body(kt, false);
    body(NKT - 1, true);

#pragma unroll
    for (int mi = 0; mi < 2; mi++) {
#pragma unroll
        for (int hf = 0; hf < 2; hf++) {
            int row = qbase + mi * 16 + hf * 8 + g;
            if (row >= SEQ) continue;
            float inv = 1.f / l_[mi][hf];
            bf16* op = o + ((size_t)n * SEQ + row) * DMODEL + h * DH;
#pragma unroll
            for (int ne = 0; ne < 4; ne++) {
                __nv_bfloat162 p = __floats2bfloat162_rn(Oa[mi][ne][hf * 2] * inv,
                                                         Oa[mi][ne][hf * 2 + 1] * inv);
                *reinterpret_cast<uint32_t*>(op + ne * 8 + q4 * 2) = *reinterpret_cast<uint32_t*>(&p);
            }
        }
    }
}

// ---------------- classification head ---------------------------------------
__global__ void head_kernel(const float* __restrict__ X, const float* __restrict__ w_out,
                            const float* __restrict__ b_out, float* __restrict__ out)
{
    __shared__ float cls_s[DMODEL];
    __shared__ float logits[OUTC];
    __shared__ float red[8];
    const int n = blockIdx.x;
    const int t = threadIdx.x, wid = t >> 5, lane = t & 31;

    cls_s[t] = X[(size_t)n * SEQ * DMODEL + t];
    __syncthreads();

    for (int j = wid; j < OUTC; j += 8) {
        float acc = 0.f;
#pragma unroll
        for (int k = lane; k < DMODEL; k += 32) acc += cls_s[k] * w_out[(size_t)j * DMODEL + k];
#pragma unroll
        for (int off = 16; off; off >>= 1) acc += __shfl_xor_sync(0xffffffffu, acc, off);
        if (lane == 0) logits[j] = acc + b_out[j];
    }
    __syncthreads();

    float mx = -1e30f;
    for (int j = t; j < OUTC; j += 256) mx = fmaxf(mx, logits[j]);
#pragma unroll
    for (int off = 16; off; off >>= 1) mx = fmaxf(mx, __shfl_xor_sync(0xffffffffu, mx, off));
    if (lane == 0) red[wid] = mx;
    __syncthreads();
    float bm = -1e30f;
#pragma unroll
    for (int i = 0; i < 8; i++) bm = fmaxf(bm, red[i]);
    __syncthreads();

    float sum = 0.f;
    for (int j = t; j < OUTC; j += 256) {
        float e = __expf(logits[j] - bm);
        logits[j] = e;
        sum += e;
    }
#pragma unroll
    for (int off = 16; off; off >>= 1) sum += __shfl_xor_sync(0xffffffffu, sum, off);
    if (lane == 0) red[wid] = sum;
    __syncthreads();
    float bs = 0.f;
#pragma unroll
    for (int i = 0; i < 8; i++) bs += red[i];
    float inv = 1.f / bs;
    __syncthreads();
    for (int j = t; j < OUTC; j += 256) out[(size_t)n * OUTC + j] = logits[j] * inv;
}

// ---------------- launcher ----------------
extern "C" void kernel_launch(void* const* d_in, const int* in_sizes, int n_in,
                              void* d_out, int out_size)
{
    const float* images  = (const float*)d_in[0];
    const float* w_map   = (const float*)d_in[1];
    const float* b_map   = (const float*)d_in[2];
    const float* cls_tok = (const float*)d_in[3];
    const float* norm1_g = (const float*)d_in[4];
    const float* norm1_b = (const float*)d_in[5];
    const float* wq      = (const float*)d_in[6];
    const float* bq      = (const float*)d_in[7];
    const float* wk      = (const float*)d_in[8];
    const float* bk      = (const float*)d_in[9];
    const float* wv      = (const float*)d_in[10];
    const float* bv      = (const float*)d_in[11];
    const float* w_last  = (const float*)d_in[12];
    const float* b_last  = (const float*)d_in[13];
    const float* norm2_g = (const float*)d_in[14];
    const float* norm2_b = (const float*)d_in[15];
    const float* w_mlp1  = (const float*)d_in[16];
    const float* b_mlp1  = (const float*)d_in[17];
    const float* w_mlp2  = (const float*)d_in[18];
    const float* b_mlp2  = (const float*)d_in[19];
    const float* w_out   = (const float*)d_in[20];
    const float* b_out   = (const float*)d_in[21];
    float* out = (float*)d_out;

    bf16 *patches, *x1b, *qb, *kb, *vb, *ob, *h1b;
    bf16 *wmapb, *wlastb, *wmlp1b, *wmlp2b;
    float *X, *pe;
    cudaGetSymbolAddress((void**)&patches, g_patches_b);
    cudaGetSymbolAddress((void**)&X,   g_X);
    cudaGetSymbolAddress((void**)&x1b, g_x1b);
    cudaGetSymbolAddress((void**)&qb,  g_qb);
    cudaGetSymbolAddress((void**)&kb,  g_kb);
    cudaGetSymbolAddress((void**)&vb,  g_vb);
    cudaGetSymbolAddress((void**)&ob,  g_ob);
    cudaGetSymbolAddress((void**)&h1b, g_h1b);
    cudaGetSymbolAddress((void**)&pe,  g_pe);
    cudaGetSymbolAddress((void**)&wmapb,  g_wmapb);
    cudaGetSymbolAddress((void**)&wlastb, g_wlastb);
    cudaGetSymbolAddress((void**)&wmlp1b, g_wmlp1b);
    cudaGetSymbolAddress((void**)&wmlp2b, g_wmlp2b);

    cudaFuncSetAttribute(gemm_bf<0, false, false, true >, cudaFuncAttributeMaxDynamicSharedMemorySize, GEMM_SMEM);
    cudaFuncSetAttribute(gemm_bf<0, true,  false, false>, cudaFuncAttributeMaxDynamicSharedMemorySize, GEMM_SMEM);
    cudaFuncSetAttribute(gemm_bf<1, false, true,  false>, cudaFuncAttributeMaxDynamicSharedMemorySize, GEMM_SMEM);

    // 0) weight conversion to bf16, single launch
    {
        int n0 = DMODEL * IN_D;
        int n1 = NLAYER * DMODEL * DMODEL;
        int n3 = NLAYER * 4 * DMODEL * DMODEL;
        int totf4 = (n0 + n1 + 2 * n3) / 4;
        cvt_all_kernel<<<(totf4 + 255) / 256, 256>>>(
            w_map, wmapb, n0, w_last, wlastb, n1,
            w_mlp1, wmlp1b, n3, w_mlp2, wmlp2b, n3);
    }

    // 1) patches + PE table
    {
        int tot = BATCH * NP * IN_D / 4;
        patch_kernel<<<(tot + 255) / 256, 256>>>(images, patches);
        int pt = SEQ * DMODEL;
        pe_kernel<<<(pt + 255) / 256, 256>>>(pe);
    }

    // 2) patch-embed GEMM fused with assemble: X[n][p+1][:] = patches@w_map^T + b + pe
    gemm_bf<0, false, false, true><<<dim3(DMODEL / 128, (BATCH * NP) / 128), 256, GEMM_SMEM>>>(
        patches, wmapb, b_map, nullptr, pe, X, BATCH * NP, DMODEL, IN_D);

    // 2b) cls rows
    cls_kernel<<<(BATCH * DMODEL + 255) / 256, 256>>>(cls_tok, pe, X);

    const int MROWS = BATCH * SEQ;   // 25216 = 128*197

    for (int l = 0; l < NLAYER; l++) {
        ln_kernel<<<MROWS / 8, 256>>>(X, norm1_g + l * DMODEL, norm1_b + l * DMODEL, x1b);

        qkv_kernel<<<dim3(BATCH * NHEAD, (SEQ + 31) / 32), 256>>>(
            x1b,
            wq + (size_t)l * NHEAD * DH * DH, bq + (size_t)l * NHEAD * DH,
            wk + (size_t)l * NHEAD * DH * DH, bk + (size_t)l * NHEAD * DH,
            wv + (size_t)l * NHEAD * DH * DH, bv + (size_t)l * NHEAD * DH,
            qb, kb, vb);

        attn_tc<<<BATCH * NHEAD, 224>>>(qb, kb, vb, ob);

        // o-proj + residual: X = X + o @ w_last^T + b_last (25216,256,256)
        gemm_bf<0, true, false, false><<<dim3(DMODEL / 128, MROWS / 128), 256, GEMM_SMEM>>>(
            ob, wlastb + (size_t)l * DMODEL * DMODEL, b_last + l * DMODEL, X, nullptr, X,
            MROWS, DMODEL, DMODEL);

        ln_kernel<<<MROWS / 8, 256>>>(X, norm2_g + l * DMODEL, norm2_b + l * DMODEL, x1b);

        // MLP1 + GELU -> bf16 h1 (25216,1024,256)
        gemm_bf<1, false, true, false><<<dim3((4 * DMODEL) / 128, MROWS / 128), 256, GEMM_SMEM>>>(
            x1b, wmlp1b + (size_t)l * 4 * DMODEL * DMODEL, b_mlp1 + l * 4 * DMODEL,
            nullptr, nullptr, h1b, MROWS, 4 * DMODEL, DMODEL);

        // MLP2 + residual: X = X + h1 @ w_mlp2^T + b2 (25216,256,1024)
        gemm_bf<0, true, false, false><<<dim3(DMODEL / 128, MROWS / 128), 256, GEMM_SMEM>>>(
            h1b, wmlp2b + (size_t)l * 4 * DMODEL * DMODEL, b_mlp2 + l * DMODEL, X, nullptr, X,
            MROWS, DMODEL, 4 * DMODEL);
    }

    head_kernel<<<BATCH, 256>>>(X, w_out, b_out, out);
}

// round 12
// speedup vs baseline: 1.4613x; 1.1346x over previous
#include <cuda_runtime.h>
#include <cuda_bf16.h>
#include <math.h>
#include <stdint.h>

// ---------------- problem constants ----------------
#define BATCH 128
#define CH    3
#define HIM   224
#define PGRID 14
#define NP    196
#define PATCH 16
#define IN_D  768
#define DMODEL 256
#define NHEAD 8
#define DH    32
#define NLAYER 4
#define SEQ   197
#define OUTC  1000
#define OUTP  1024          // padded head cols
#define LNEPS 1e-5f

typedef __nv_bfloat16 bf16;

// ---------------- scratch (device globals) ----------------
__device__ bf16  g_patches_b[BATCH * NP * IN_D];
__device__ float g_X [BATCH * SEQ * DMODEL];
__device__ bf16  g_x1b[BATCH * SEQ * DMODEL];
__device__ bf16  g_qb [BATCH * SEQ * DMODEL];             // [n,h,s,e] (pre-scaled)
__device__ bf16  g_kb [BATCH * SEQ * DMODEL];
__device__ bf16  g_vb [BATCH * SEQ * DMODEL];
__device__ bf16  g_ob [BATCH * SEQ * DMODEL];             // [n,s,d]
__device__ bf16  g_h1b[BATCH * SEQ * 4 * DMODEL];
__device__ float g_pe[SEQ * DMODEL];
__device__ bf16  g_wmapb [DMODEL * IN_D];
__device__ bf16  g_wlastb[NLAYER * DMODEL * DMODEL];
__device__ bf16  g_wmlp1b[NLAYER * 4 * DMODEL * DMODEL];
__device__ bf16  g_wmlp2b[NLAYER * 4 * DMODEL * DMODEL];
__device__ bf16  g_woutb[OUTP * DMODEL];                  // padded bf16 head weights
__device__ float g_bout_pad[OUTP];
__device__ bf16  g_clsb[BATCH * DMODEL];
__device__ float g_logits[BATCH * OUTP];

// ---------------- fp32 -> bf16 convert, all weights in one launch ----------
__device__ __forceinline__ void cvt4(const float* __restrict__ s, bf16* __restrict__ d, int i)
{
    float4 v = *(const float4*)(s + i);
    __nv_bfloat162 p0 = __floats2bfloat162_rn(v.x, v.y);
    __nv_bfloat162 p1 = __floats2bfloat162_rn(v.z, v.w);
    uint2 o;
    o.x = *reinterpret_cast<uint32_t*>(&p0);
    o.y = *reinterpret_cast<uint32_t*>(&p1);
    *reinterpret_cast<uint2*>(d + i) = o;
}

__global__ void cvt_all_kernel(const float* __restrict__ s0, bf16* __restrict__ d0, int n0,
                               const float* __restrict__ s1, bf16* __restrict__ d1, int n1,
                               const float* __restrict__ s2, bf16* __restrict__ d2, int n2,
                               const float* __restrict__ s3, bf16* __restrict__ d3, int n3)
{
    int i = (blockIdx.x * 256 + threadIdx.x) * 4;
    if (i < n0) { cvt4(s0, d0, i); return; }
    i -= n0;
    if (i < n1) { cvt4(s1, d1, i); return; }
    i -= n1;
    if (i < n2) { cvt4(s2, d2, i); return; }
    i -= n2;
    if (i < n3) { cvt4(s3, d3, i); return; }
}

// ---------------- head weight pad+convert (runs once) -----------------------
__global__ void cvt_head_kernel(const float* __restrict__ w_out, const float* __restrict__ b_out,
                                bf16* __restrict__ woutb, float* __restrict__ bpad)
{
    int tid = blockIdx.x * 256 + threadIdx.x;
    int i = tid * 4;
    if (i < OUTP * DMODEL) {
        int row = i / DMODEL;
        if (row < OUTC) {
            cvt4(w_out, woutb, i);
        } else {
            uint2 z = {0u, 0u};
            *reinterpret_cast<uint2*>(woutb + i) = z;
        }
    }
    if (tid < OUTP) bpad[tid] = (tid < OUTC) ? b_out[tid] : 0.f;
}

// ---------------- cls row extraction: X[n][0][:] -> bf16 --------------------
__global__ void cls_extract_kernel(const float* __restrict__ X, bf16* __restrict__ clsb)
{
    int i = (blockIdx.x * 256 + threadIdx.x) * 4;
    if (i >= BATCH * DMODEL) return;
    int n = i / DMODEL, d = i % DMODEL;
    float4 v = *(const float4*)(X + (size_t)n * SEQ * DMODEL + d);
    __nv_bfloat162 p0 = __floats2bfloat162_rn(v.x, v.y);
    __nv_bfloat162 p1 = __floats2bfloat162_rn(v.z, v.w);
    uint2 o;
    o.x = *reinterpret_cast<uint32_t*>(&p0);
    o.y = *reinterpret_cast<uint32_t*>(&p1);
    *reinterpret_cast<uint2*>(clsb + i) = o;
}

// ---------------- patch extraction (float4 gather, writes bf16) ------------
__global__ void patch_kernel(const float* __restrict__ img, bf16* __restrict__ out)
{
    int tid = blockIdx.x * 256 + threadIdx.x;
    int idx = tid * 4;
    if (idx >= BATCH * NP * IN_D) return;
    int i = idx % IN_D;
    int p = (idx / IN_D) % NP;
    int n = idx / (IN_D * NP);
    int c   = i >> 8;
    int r   = (i >> 4) & 15;
    int col = i & 15;
    int py = p / PGRID, px = p % PGRID;
    float4 v = *(const float4*)(img + (((size_t)n * CH + c) * HIM + py * PATCH + r) * HIM
                                    + px * PATCH + col);
    __nv_bfloat162 p0 = __floats2bfloat162_rn(v.x, v.y);
    __nv_bfloat162 p1 = __floats2bfloat162_rn(v.z, v.w);
    uint2 o;
    o.x = *reinterpret_cast<uint32_t*>(&p0);
    o.y = *reinterpret_cast<uint32_t*>(&p1);
    *reinterpret_cast<uint2*>(out + idx) = o;
}

// ---------------- positional encoding (fp64) ----------------
__global__ void pe_kernel(float* __restrict__ pe)
{
    int i = blockIdx.x * 256 + threadIdx.x;
    if (i >= SEQ * DMODEL) return;
    int s = i / DMODEL, d = i % DMODEL;
    double expo = (double)(2 * (d / 2)) / (double)DMODEL;
    double ang  = (double)s / pow(10000.0, expo);
    pe[i] = (float)((d & 1) ? cos(ang) : sin(ang));
}

// ---------------- cls rows: X[n][0][:] = cls + pe[0] ------------------------
__global__ void cls_kernel(const float* __restrict__ cls,
                           const float* __restrict__ pe,
                           float* __restrict__ X)
{
    int i = blockIdx.x * 256 + threadIdx.x;
    if (i >= BATCH * DMODEL) return;
    int d = i % DMODEL;
    int n = i / DMODEL;
    X[(size_t)n * SEQ * DMODEL + d] = cls[d] + pe[d];
}

// ---------------- bf16 MMA / ldmatrix helpers -------------------------------
__device__ __forceinline__ void mma_bf16(float* c, const uint32_t* a, const uint32_t* b)
{
    asm volatile(
        "mma.sync.aligned.m16n8k16.row.col.f32.bf16.bf16.f32 "
        "{%0,%1,%2,%3}, {%4,%5,%6,%7}, {%8,%9}, {%0,%1,%2,%3};"
        : "+f"(c[0]), "+f"(c[1]), "+f"(c[2]), "+f"(c[3])
        : "r"(a[0]), "r"(a[1]), "r"(a[2]), "r"(a[3]), "r"(b[0]), "r"(b[1]));
}

#define LDSM4(r0, r1, r2, r3, addr) \
    asm volatile("ldmatrix.sync.aligned.m8n8.x4.shared.b16 {%0,%1,%2,%3}, [%4];" \
                 : "=r"(r0), "=r"(r1), "=r"(r2), "=r"(r3) : "r"(addr))

#define CP16(dst, src) asm volatile("cp.async.cg.shared.global [%0], [%1], 16;\n" :: "r"(dst), "l"(src))
#define CP_COMMIT()    asm volatile("cp.async.commit_group;\n" ::)
#define CP_WAIT1()     asm volatile("cp.async.wait_group 1;\n" ::)
#define CP_WAIT0()     asm volatile("cp.async.wait_group 0;\n" ::)

// ---------------- bf16 tensor-core GEMM, 128x128 tile (frozen config) -------
#define STR 36                      // u32 stride per 64-bf16 row (pad 4) = 144B
#define ABUF (128 * STR)            // u32
#define GEMM_SMEM (4 * ABUF * 4)    // A0,A1,B0,B1 = 73728 B

template<int ACT, bool HASRES, bool OUTBF, bool ADDPE>
__global__ void __launch_bounds__(256) gemm_bf(const bf16* __restrict__ A,
                                               const bf16* __restrict__ W,
                                               const float* __restrict__ bias,
                                               const float* __restrict__ res,
                                               const float* __restrict__ pe,
                                               void* __restrict__ Cout,
                                               int M, int N, int K)
{
    extern __shared__ uint32_t sm_[];
    const uint32_t smem_byte = (uint32_t)__cvta_generic_to_shared(sm_);

    const int t    = threadIdx.x;
    const int warp = t >> 5, lane = t & 31;
    const int g    = lane >> 2, q4 = lane & 3;
    const int warp_m = (warp >> 1) * 32;
    const int warp_n = (warp & 1) * 64;
    const int row0 = blockIdx.y * 128, col0 = blockIdx.x * 128;

    float acc[2][8][4];
#pragma unroll
    for (int mi = 0; mi < 2; mi++)
#pragma unroll
        for (int ni = 0; ni < 8; ni++)
#pragma unroll
            for (int e = 0; e < 4; e++) acc[mi][ni][e] = 0.f;

    auto stage = [&](int k0, int buf) {
        uint32_t abase = smem_byte + buf * (ABUF * 4);
        uint32_t bbase = smem_byte + (2 + buf) * (ABUF * 4);
#pragma unroll
        for (int i = 0; i < 4; i++) {
            int c = t + i * 256;
            int r = c >> 3, co = c & 7;
            CP16(abase + (r * STR + co * 4) * 4, A + (size_t)(row0 + r) * K + k0 + co * 8);
            CP16(bbase + (r * STR + co * 4) * 4, W + (size_t)(col0 + r) * K + k0 + co * 8);
        }
        CP_COMMIT();
    };

    uint32_t a_addr[2][2], b_addr[2][4];
    {
        int ar = warp_m + (lane & 15);
        int ab = (lane >> 4) * 16;
        int br = warp_n + ((lane >> 4) & 1) * 8 + (lane & 7);
        int bb = ((lane >> 3) & 1) * 16;
#pragma unroll
        for (int buf = 0; buf < 2; buf++) {
            uint32_t abase = smem_byte + buf * (ABUF * 4);
            uint32_t bbase = smem_byte + (2 + buf) * (ABUF * 4);
#pragma unroll
            for (int mi = 0; mi < 2; mi++)
                a_addr[buf][mi] = abase + (ar + mi * 16) * (STR * 4) + ab;
#pragma unroll
            for (int nj = 0; nj < 4; nj++)
                b_addr[buf][nj] = bbase + (br + nj * 16) * (STR * 4) + bb;
        }
    }

    const int KT = K >> 6;
    stage(0, 0);

    for (int kt = 0; kt < KT; kt++) {
        const int cur = kt & 1;
        if (kt + 1 < KT) { stage((kt + 1) << 6, cur ^ 1); CP_WAIT1(); }
        else             { CP_WAIT0(); }
        __syncthreads();

#pragma unroll
        for (int ks = 0; ks < 4; ks++) {
            const uint32_t kb = ks * 32;
            uint32_t af[2][4];
            LDSM4(af[0][0], af[0][1], af[0][2], af[0][3], a_addr[cur][0] + kb);
            LDSM4(af[1][0], af[1][1], af[1][2], af[1][3], a_addr[cur][1] + kb);
            uint32_t bf_[8][2];
#pragma unroll
            for (int nj = 0; nj < 4; nj++)
                LDSM4(bf_[2 * nj][0], bf_[2 * nj][1], bf_[2 * nj + 1][0], bf_[2 * nj + 1][1],
                      b_addr[cur][nj] + kb);
#pragma unroll
            for (int mi = 0; mi < 2; mi++)
#pragma unroll
                for (int ni = 0; ni < 8; ni++)
                    mma_bf16(acc[mi][ni], af[mi], bf_[ni]);
        }
        __syncthreads();
    }

    // epilogue
#pragma unroll
    for (int mi = 0; mi < 2; mi++) {
        int ra = row0 + warp_m + mi * 16 + g;
        int rb = ra + 8;
        size_t orow_a, orow_b;
        if (ADDPE) {
            orow_a = (size_t)(ra / NP) * SEQ + (ra % NP) + 1;
            orow_b = (size_t)(rb / NP) * SEQ + (rb % NP) + 1;
        } else {
            orow_a = ra; orow_b = rb;
        }
        int pes_a = ADDPE ? ((ra % NP) + 1) : 0;
        int pes_b = ADDPE ? ((rb % NP) + 1) : 0;
#pragma unroll
        for (int ni = 0; ni < 8; ni++) {
            int col = col0 + warp_n + ni * 8 + q4 * 2;
            float b0 = bias[col], b1 = bias[col + 1];
            float v00 = acc[mi][ni][0] + b0, v01 = acc[mi][ni][1] + b1;
            float v10 = acc[mi][ni][2] + b0, v11 = acc[mi][ni][3] + b1;
            if (ACT == 1) {
                v00 = 0.5f * v00 * (1.0f + erff(v00 * 0.70710678118654752f));
                v01 = 0.5f * v01 * (1.0f + erff(v01 * 0.70710678118654752f));
                v10 = 0.5f * v10 * (1.0f + erff(v10 * 0.70710678118654752f));
                v11 = 0.5f * v11 * (1.0f + erff(v11 * 0.70710678118654752f));
            }
            if (HASRES) {
                float2 r0 = *(const float2*)(res + orow_a * N + col);
                float2 r1 = *(const float2*)(res + orow_b * N + col);
                v00 += r0.x; v01 += r0.y; v10 += r1.x; v11 += r1.y;
            }
            if (ADDPE) {
                float2 p0 = *(const float2*)(pe + (size_t)pes_a * DMODEL + col);
                float2 p1 = *(const float2*)(pe + (size_t)pes_b * DMODEL + col);
                v00 += p0.x; v01 += p0.y; v10 += p1.x; v11 += p1.y;
            }
            if (OUTBF) {
                bf16* C = (bf16*)Cout;
                __nv_bfloat162 p0 = __floats2bfloat162_rn(v00, v01);
                __nv_bfloat162 p1 = __floats2bfloat162_rn(v10, v11);
                *reinterpret_cast<uint32_t*>(C + orow_a * N + col) = *reinterpret_cast<uint32_t*>(&p0);
                *reinterpret_cast<uint32_t*>(C + orow_b * N + col) = *reinterpret_cast<uint32_t*>(&p1);
            } else {
                float* C = (float*)Cout;
                *(float2*)(C + orow_a * N + col) = make_float2(v00, v01);
                *(float2*)(C + orow_b * N + col) = make_float2(v10, v11);
            }
        }
    }
}

// ---------------- LayerNorm: warp per row, bf16 out -------------------------
__global__ void ln_kernel(const float* __restrict__ x,
                          const float* __restrict__ g,
                          const float* __restrict__ b,
                          bf16* __restrict__ y)
{
    const int row  = blockIdx.x * 8 + (threadIdx.x >> 5);
    const int lane = threadIdx.x & 31;
    const float4* xp = (const float4*)(x + (size_t)row * DMODEL);
    float4 u = xp[lane * 2], w = xp[lane * 2 + 1];

    float s = u.x + u.y + u.z + u.w + w.x + w.y + w.z + w.w;
#pragma unroll
    for (int off = 16; off; off >>= 1) s += __shfl_xor_sync(0xffffffffu, s, off);
    float mu = s * (1.f / DMODEL);

    float d0 = u.x - mu, d1 = u.y - mu, d2 = u.z - mu, d3 = u.w - mu;
    float d4 = w.x - mu, d5 = w.y - mu, d6 = w.z - mu, d7 = w.w - mu;
    float s2 = d0*d0 + d1*d1 + d2*d2 + d3*d3 + d4*d4 + d5*d5 + d6*d6 + d7*d7;
#pragma unroll
    for (int off = 16; off; off >>= 1) s2 += __shfl_xor_sync(0xffffffffu, s2, off);
    float inv = rsqrtf(s2 * (1.f / DMODEL) + LNEPS);

    const float4* gp = (const float4*)g;
    const float4* bp = (const float4*)b;
    float4 g0 = gp[lane * 2], g1 = gp[lane * 2 + 1];
    float4 b0 = bp[lane * 2], b1 = bp[lane * 2 + 1];

    __nv_bfloat162 p0 = __floats2bfloat162_rn(d0 * inv * g0.x + b0.x, d1 * inv * g0.y + b0.y);
    __nv_bfloat162 p1 = __floats2bfloat162_rn(d2 * inv * g0.z + b0.z, d3 * inv * g0.w + b0.w);
    __nv_bfloat162 p2 = __floats2bfloat162_rn(d4 * inv * g1.x + b1.x, d5 * inv * g1.y + b1.y);
    __nv_bfloat162 p3 = __floats2bfloat162_rn(d6 * inv * g1.z + b1.z, d7 * inv * g1.w + b1.w);
    uint4 o;
    o.x = *reinterpret_cast<uint32_t*>(&p0);
    o.y = *reinterpret_cast<uint32_t*>(&p1);
    o.z = *reinterpret_cast<uint32_t*>(&p2);
    o.w = *reinterpret_cast<uint32_t*>(&p3);
    *reinterpret_cast<uint4*>(y + (size_t)row * DMODEL + lane * 8) = o;
}

// ---------------- fused per-head QKV projection, 128 rows/block --------------
// q output pre-scaled by 1/sqrt(DH). grid (B*H, 2).
__global__ void qkv_kernel(const bf16* __restrict__ x1,
                           const float* __restrict__ wq, const float* __restrict__ bq,
                           const float* __restrict__ wk, const float* __restrict__ bk,
                           const float* __restrict__ wv, const float* __restrict__ bv,
                           bf16* __restrict__ q, bf16* __restrict__ k, bf16* __restrict__ v)
{
    __shared__ float wqs[32 * 33], wks[32 * 33], wvs[32 * 33];
    __shared__ float bqs[32], bks[32], bvs[32];
    __shared__ float xr[128 * 33];
    const int nh = blockIdx.x;
    const int n = nh / NHEAD, h = nh % NHEAD;
    const int t = threadIdx.x;
    const float* wqg = wq + (size_t)h * DH * DH;
    const float* wkg = wk + (size_t)h * DH * DH;
    const float* wvg = wv + (size_t)h * DH * DH;

    for (int i = t; i < DH * DH; i += 256) {
        int e = i >> 5, d = i & 31;
        wqs[e * 33 + d] = wqg[i];
        wks[e * 33 + d] = wkg[i];
        wvs[e * 33 + d] = wvg[i];
    }
    if (t < 32) { bqs[t] = bq[h * DH + t]; bks[t] = bk[h * DH + t]; bvs[t] = bv[h * DH + t]; }

    const int s0 = blockIdx.y * 128;
    for (int i = t; i < 128 * 32; i += 256) {
        int r = i >> 5, d = i & 31;
        int s = s0 + r;
        xr[r * 33 + d] = (s < SEQ)
            ? __bfloat162float(x1[((size_t)n * SEQ + s) * DMODEL + h * DH + d])
            : 0.f;
    }
    __syncthreads();

    const float scale = 0.17677669529663689f;  // 1/sqrt(32)
    const int wr = (t >> 5) * 16, lane = t & 31;
    const float bqv = bqs[lane], bkv = bks[lane], bvv = bvs[lane];
#pragma unroll 4
    for (int r = 0; r < 16; r++) {
        int s = s0 + wr + r;
        if (s >= SEQ) break;
        const float* xp = xr + (wr + r) * 33;
        float aq = bqv, ak = bkv, av = bvv;
#pragma unroll
        for (int d = 0; d < 32; d++) {
            float xv = xp[d];
            aq += xv * wqs[lane * 33 + d];
            ak += xv * wks[lane * 33 + d];
            av += xv * wvs[lane * 33 + d];
        }
        size_t oidx = ((size_t)nh * SEQ + s) * DH + lane;
        q[oidx] = __float2bfloat16(aq * scale);
        k[oidx] = __float2bfloat16(ak);
        v[oidx] = __float2bfloat16(av);
    }
}

// ---------------- tensor-core flash attention per (n,h) ---------------------
#define SPAD 224
#define NKT  7
#define KSTR 20
#define VSTR 116

__global__ void __launch_bounds__(224) attn_tc(const bf16* __restrict__ q,
                                               const bf16* __restrict__ k,
                                               const bf16* __restrict__ v,
                                               bf16* __restrict__ o)
{
    __shared__ uint32_t Ks[SPAD * KSTR];
    __shared__ uint32_t VT[32 * VSTR];

    const int nh = blockIdx.x;
    const int n = nh / NHEAD, h = nh % NHEAD;
    const int t = threadIdx.x, warp = t >> 5, lane = t & 31;
    const int g = lane >> 2, q4 = lane & 3;
    const size_t base = (size_t)nh * SEQ * DH;
    const uint32_t* q32 = (const uint32_t*)(q + base);
    const uint32_t* k32 = (const uint32_t*)(k + base);
    const uint32_t* v32 = (const uint32_t*)(v + base);

    for (int i = t; i < SPAD * 16; i += 224) {
        int r = i >> 4, c = i & 15;
        Ks[r * KSTR + c] = (r < SEQ) ? k32[r * 16 + c] : 0u;
    }
    bf16* VT16 = (bf16*)VT;
    for (int i = t; i < SPAD * 16; i += 224) {
        int tt = i >> 4, c = i & 15;
        uint32_t val = (tt < SEQ) ? v32[tt * 16 + c] : 0u;
        __nv_bfloat162 pr = *reinterpret_cast<__nv_bfloat162*>(&val);
        VT16[(2 * c)     * (VSTR * 2) + tt] = pr.x;
        VT16[(2 * c + 1) * (VSTR * 2) + tt] = pr.y;
    }
    __syncthreads();

    const int qbase = warp * 32;
    uint32_t qf[2][2][4];
#pragma unroll
    for (int mi = 0; mi < 2; mi++) {
        int r0 = qbase + mi * 16 + g, r1 = r0 + 8;
        bool v0 = r0 < SEQ, v1 = r1 < SEQ;
#pragma unroll
        for (int ks = 0; ks < 2; ks++) {
            qf[mi][ks][0] = v0 ? q32[r0 * 16 + ks * 8 + q4]     : 0u;
            qf[mi][ks][1] = v1 ? q32[r1 * 16 + ks * 8 + q4]     : 0u;
            qf[mi][ks][2] = v0 ? q32[r0 * 16 + ks * 8 + q4 + 4] : 0u;
            qf[mi][ks][3] = v1 ? q32[r1 * 16 + ks * 8 + q4 + 4] : 0u;
        }
    }

    float Oa[2][4][4];
#pragma unroll
    for (int mi = 0; mi < 2; mi++)
#pragma unroll
        for (int ne = 0; ne < 4; ne++)
#pragma unroll
            for (int e = 0; e < 4; e++) Oa[mi][ne][e] = 0.f;
    float m_[2][2] = {{-1e30f, -1e30f}, {-1e30f, -1e30f}};
    float l_[2][2] = {{0.f, 0.f}, {0.f, 0.f}};

    auto body = [&](int kt, bool last_mask) {
        float sc[2][4][4];
#pragma unroll
        for (int mi = 0; mi < 2; mi++)
#pragma unroll
            for (int ni = 0; ni < 4; ni++)
#pragma unroll
                for (int e = 0; e < 4; e++) sc[mi][ni][e] = 0.f;

        uint32_t kf[2][4][2];
#pragma unroll
        for (int ks = 0; ks < 2; ks++)
#pragma unroll
            for (int ni = 0; ni < 4; ni++) {
                int r = kt * 32 + ni * 8 + g;
                kf[ks][ni][0] = Ks[r * KSTR + ks * 8 + q4];
                kf[ks][ni][1] = Ks[r * KSTR + ks * 8 + q4 + 4];
            }
#pragma unroll
        for (int mi = 0; mi < 2; mi++)
#pragma unroll
            for (int ni = 0; ni < 4; ni++)
#pragma unroll
                for (int ks = 0; ks < 2; ks++)
                    mma_bf16(sc[mi][ni], qf[mi][ks], kf[ks][ni]);

        if (last_mask) {
#pragma unroll
            for (int mi = 0; mi < 2; mi++)
#pragma unroll
                for (int ni = 0; ni < 4; ni++) {
                    int col = kt * 32 + ni * 8 + q4 * 2;
#pragma unroll
                    for (int hf = 0; hf < 2; hf++) {
                        if (col     >= SEQ) sc[mi][ni][hf * 2]     = -1e30f;
                        if (col + 1 >= SEQ) sc[mi][ni][hf * 2 + 1] = -1e30f;
                    }
                }
        }

#pragma unroll
        for (int mi = 0; mi < 2; mi++) {
#pragma unroll
            for (int hf = 0; hf < 2; hf++) {
                float mx = fmaxf(fmaxf(sc[mi][0][hf * 2], sc[mi][0][hf * 2 + 1]),
                                 fmaxf(sc[mi][1][hf * 2], sc[mi][1][hf * 2 + 1]));
                mx = fmaxf(mx, fmaxf(fmaxf(sc[mi][2][hf * 2], sc[mi][2][hf * 2 + 1]),
                                     fmaxf(sc[mi][3][hf * 2], sc[mi][3][hf * 2 + 1])));
                mx = fmaxf(mx, __shfl_xor_sync(0xffffffffu, mx, 1));
                mx = fmaxf(mx, __shfl_xor_sync(0xffffffffu, mx, 2));
                float mnew = fmaxf(m_[mi][hf], mx);
                float f = __expf(m_[mi][hf] - mnew);
                m_[mi][hf] = mnew;
                float rs = 0.f;
#pragma unroll
                for (int ni = 0; ni < 4; ni++) {
                    float p0 = __expf(sc[mi][ni][hf * 2]     - mnew);
                    float p1 = __expf(sc[mi][ni][hf * 2 + 1] - mnew);
                    sc[mi][ni][hf * 2]     = p0;
                    sc[mi][ni][hf * 2 + 1] = p1;
                    rs += p0 + p1;
                }
                rs += __shfl_xor_sync(0xffffffffu, rs, 1);
                rs += __shfl_xor_sync(0xffffffffu, rs, 2);
                l_[mi][hf] = l_[mi][hf] * f + rs;
#pragma unroll
                for (int ne = 0; ne < 4; ne++) {
                    Oa[mi][ne][hf * 2]     *= f;
                    Oa[mi][ne][hf * 2 + 1] *= f;
                }
            }
        }

        uint32_t pa[2][2][4];
#pragma unroll
        for (int mi = 0; mi < 2; mi++)
#pragma unroll
            for (int ks = 0; ks < 2; ks++) {
                __nv_bfloat162 t0 = __floats2bfloat162_rn(sc[mi][2 * ks][0],     sc[mi][2 * ks][1]);
                __nv_bfloat162 t1 = __floats2bfloat162_rn(sc[mi][2 * ks][2],     sc[mi][2 * ks][3]);
                __nv_bfloat162 t2 = __floats2bfloat162_rn(sc[mi][2 * ks + 1][0], sc[mi][2 * ks + 1][1]);
                __nv_bfloat162 t3 = __floats2bfloat162_rn(sc[mi][2 * ks + 1][2], sc[mi][2 * ks + 1][3]);
                pa[mi][ks][0] = *reinterpret_cast<uint32_t*>(&t0);
                pa[mi][ks][1] = *reinterpret_cast<uint32_t*>(&t1);
                pa[mi][ks][2] = *reinterpret_cast<uint32_t*>(&t2);
                pa[mi][ks][3] = *reinterpret_cast<uint32_t*>(&t3);
            }

        uint32_t vf[2][4][2];
#pragma unroll
        for (int ks = 0; ks < 2; ks++)
#pragma unroll
            for (int ne = 0; ne < 4; ne++) {
                int r = ne * 8 + g;
                int cu = kt * 16 + ks * 8 + q4;
                vf[ks][ne][0] = VT[r * VSTR + cu];
                vf[ks][ne][1] = VT[r * VSTR + cu + 4];
            }
#pragma unroll
        for (int mi = 0; mi < 2; mi++)
#pragma unroll
            for (int ne = 0; ne < 4; ne++)
#pragma unroll
                for (int ks = 0; ks < 2; ks++)
                    mma_bf16(Oa[mi][ne], pa[mi][ks], vf[ks][ne]);
    };

    for (int kt = 0; kt < NKT - 1; kt++) body(kt, false);
    body(NKT - 1, true);

#pragma unroll
    for (int mi = 0; mi < 2; mi++) {
#pragma unroll
        for (int hf = 0; hf < 2; hf++) {
            int row = qbase + mi * 16 + hf * 8 + g;
            if (row >= SEQ) continue;
            float inv = 1.f / l_[mi][hf];
            bf16* op = o + ((size_t)n * SEQ + row) * DMODEL + h * DH;
#pragma unroll
            for (int ne = 0; ne < 4; ne++) {
                __nv_bfloat162 p = __floats2bfloat162_rn(Oa[mi][ne][hf * 2] * inv,
                                                         Oa[mi][ne][hf * 2 + 1] * inv);
                *reinterpret_cast<uint32_t*>(op + ne * 8 + q4 * 2) = *reinterpret_cast<uint32_t*>(&p);
            }
        }
    }
}

// ---------------- softmax over precomputed logits ---------------------------
__global__ void softmax_head_kernel(const float* __restrict__ logits_in,
                                    float* __restrict__ out)
{
    __shared__ float logits[OUTC];
    __shared__ float red[8];
    const int n = blockIdx.x;
    const int t = threadIdx.x, wid = t >> 5, lane = t & 31;

    for (int j = t; j < OUTC; j += 256) logits[j] = logits_in[(size_t)n * OUTP + j];
    __syncthreads();

    float mx = -1e30f;
    for (int j = t; j < OUTC; j += 256) mx = fmaxf(mx, logits[j]);
#pragma unroll
    for (int off = 16; off; off >>= 1) mx = fmaxf(mx, __shfl_xor_sync(0xffffffffu, mx, off));
    if (lane == 0) red[wid] = mx;
    __syncthreads();
    float bm = -1e30f;
#pragma unroll
    for (int i = 0; i < 8; i++) bm = fmaxf(bm, red[i]);
    __syncthreads();

    float sum = 0.f;
    for (int j = t; j < OUTC; j += 256) {
        float e = __expf(logits[j] - bm);
        logits[j] = e;
        sum += e;
    }
#pragma unroll
    for (int off = 16; off; off >>= 1) sum += __shfl_xor_sync(0xffffffffu, sum, off);
    if (lane == 0) red[wid] = sum;
    __syncthreads();
    float bs = 0.f;
#pragma unroll
    for (int i = 0; i < 8; i++) bs += red[i];
    float inv = 1.f / bs;
    __syncthreads();
    for (int j = t; j < OUTC; j += 256) out[(size_t)n * OUTC + j] = logits[j] * inv;
}

// ---------------- launcher ----------------
extern "C" void kernel_launch(void* const* d_in, const int* in_sizes, int n_in,
                              void* d_out, int out_size)
{
    const float* images  = (const float*)d_in[0];
    const float* w_map   = (const float*)d_in[1];
    const float* b_map   = (const float*)d_in[2];
    const float* cls_tok = (const float*)d_in[3];
    const float* norm1_g = (const float*)d_in[4];
    const float* norm1_b = (const float*)d_in[5];
    const float* wq      = (const float*)d_in[6];
    const float* bq      = (const float*)d_in[7];
    const float* wk      = (const float*)d_in[8];
    const float* bk      = (const float*)d_in[9];
    const float* wv      = (const float*)d_in[10];
    const float* bv      = (const float*)d_in[11];
    const float* w_last  = (const float*)d_in[12];
    const float* b_last  = (const float*)d_in[13];
    const float* norm2_g = (const float*)d_in[14];
    const float* norm2_b = (const float*)d_in[15];
    const float* w_mlp1  = (const float*)d_in[16];
    const float* b_mlp1  = (const float*)d_in[17];
    const float* w_mlp2  = (const float*)d_in[18];
    const float* b_mlp2  = (const float*)d_in[19];
    const float* w_out   = (const float*)d_in[20];
    const float* b_out   = (const float*)d_in[21];
    float* out = (float*)d_out;

    bf16 *patches, *x1b, *qb, *kb, *vb, *ob, *h1b;
    bf16 *wmapb, *wlastb, *wmlp1b, *wmlp2b, *woutb, *clsb;
    float *X, *pe, *bout_pad, *logits;
    cudaGetSymbolAddress((void**)&patches, g_patches_b);
    cudaGetSymbolAddress((void**)&X,   g_X);
    cudaGetSymbolAddress((void**)&x1b, g_x1b);
    cudaGetSymbolAddress((void**)&qb,  g_qb);
    cudaGetSymbolAddress((void**)&kb,  g_kb);
    cudaGetSymbolAddress((void**)&vb,  g_vb);
    cudaGetSymbolAddress((void**)&ob,  g_ob);
    cudaGetSymbolAddress((void**)&h1b, g_h1b);
    cudaGetSymbolAddress((void**)&pe,  g_pe);
    cudaGetSymbolAddress((void**)&wmapb,  g_wmapb);
    cudaGetSymbolAddress((void**)&wlastb, g_wlastb);
    cudaGetSymbolAddress((void**)&wmlp1b, g_wmlp1b);
    cudaGetSymbolAddress((void**)&wmlp2b, g_wmlp2b);
    cudaGetSymbolAddress((void**)&woutb,  g_woutb);
    cudaGetSymbolAddress((void**)&clsb,   g_clsb);
    cudaGetSymbolAddress((void**)&bout_pad, g_bout_pad);
    cudaGetSymbolAddress((void**)&logits,  g_logits);

    cudaFuncSetAttribute(gemm_bf<0, false, false, true >, cudaFuncAttributeMaxDynamicSharedMemorySize, GEMM_SMEM);
    cudaFuncSetAttribute(gemm_bf<0, true,  false, false>, cudaFuncAttributeMaxDynamicSharedMemorySize, GEMM_SMEM);
    cudaFuncSetAttribute(gemm_bf<1, false, true,  false>, cudaFuncAttributeMaxDynamicSharedMemorySize, GEMM_SMEM);
    cudaFuncSetAttribute(gemm_bf<0, false, false, false>, cudaFuncAttributeMaxDynamicSharedMemorySize, GEMM_SMEM);

    // 0) weight conversion to bf16 (+ padded head weights)
    {
        int n0 = DMODEL * IN_D;
        int n1 = NLAYER * DMODEL * DMODEL;
        int n3 = NLAYER * 4 * DMODEL * DMODEL;
        int totf4 = (n0 + n1 + 2 * n3) / 4;
        cvt_all_kernel<<<(totf4 + 255) / 256, 256>>>(
            w_map, wmapb, n0, w_last, wlastb, n1,
            w_mlp1, wmlp1b, n3, w_mlp2, wmlp2b, n3);
        int hw = OUTP * DMODEL / 4;
        cvt_head_kernel<<<(hw + 255) / 256, 256>>>(w_out, b_out, woutb, bout_pad);
    }

    // 1) patches + PE table
    {
        int tot = BATCH * NP * IN_D / 4;
        patch_kernel<<<(tot + 255) / 256, 256>>>(images, patches);
        int pt = SEQ * DMODEL;
        pe_kernel<<<(pt + 255) / 256, 256>>>(pe);
    }

    // 2) patch-embed GEMM fused with assemble
    gemm_bf<0, false, false, true><<<dim3(DMODEL / 128, (BATCH * NP) / 128), 256, GEMM_SMEM>>>(
        patches, wmapb, b_map, nullptr, pe, X, BATCH * NP, DMODEL, IN_D);

    // 2b) cls rows
    cls_kernel<<<(BATCH * DMODEL + 255) / 256, 256>>>(cls_tok, pe, X);

    const int MROWS = BATCH * SEQ;   // 25216 = 128*197

    for (int l = 0; l < NLAYER; l++) {
        ln_kernel<<<MROWS / 8, 256>>>(X, norm1_g + l * DMODEL, norm1_b + l * DMODEL, x1b);

        qkv_kernel<<<dim3(BATCH * NHEAD, 2), 256>>>(
            x1b,
            wq + (size_t)l * NHEAD * DH * DH, bq + (size_t)l * NHEAD * DH,
            wk + (size_t)l * NHEAD * DH * DH, bk + (size_t)l * NHEAD * DH,
            wv + (size_t)l * NHEAD * DH * DH, bv + (size_t)l * NHEAD * DH,
            qb, kb, vb);

        attn_tc<<<BATCH * NHEAD, 224>>>(qb, kb, vb, ob);

        // o-proj + residual: X = X + o @ w_last^T + b_last (25216,256,256)
        gemm_bf<0, true, false, false><<<dim3(DMODEL / 128, MROWS / 128), 256, GEMM_SMEM>>>(
            ob, wlastb + (size_t)l * DMODEL * DMODEL, b_last + l * DMODEL, X, nullptr, X,
            MROWS, DMODEL, DMODEL);

        ln_kernel<<<MROWS / 8, 256>>>(X, norm2_g + l * DMODEL, norm2_b + l * DMODEL, x1b);

        // MLP1 + GELU -> bf16 h1 (25216,1024,256)
        gemm_bf<1, false, true, false><<<dim3((4 * DMODEL) / 128, MROWS / 128), 256, GEMM_SMEM>>>(
            x1b, wmlp1b + (size_t)l * 4 * DMODEL * DMODEL, b_mlp1 + l * 4 * DMODEL,
            nullptr, nullptr, h1b, MROWS, 4 * DMODEL, DMODEL);

        // MLP2 + residual: X = X + h1 @ w_mlp2^T + b2 (25216,256,1024)
        gemm_bf<0, true, false, false><<<dim3(DMODEL / 128, MROWS / 128), 256, GEMM_SMEM>>>(
            h1b, wmlp2b + (size_t)l * 4 * DMODEL * DMODEL, b_mlp2 + l * DMODEL, X, nullptr, X,
            MROWS, DMODEL, 4 * DMODEL);
    }

    // head: cls extraction -> tensor-core logits GEMM -> softmax
    cls_extract_kernel<<<(BATCH * DMODEL / 4 + 255) / 256, 256>>>(X, clsb);
    gemm_bf<0, false, false, false><<<dim3(OUTP / 128, BATCH / 128), 256, GEMM_SMEM>>>(
        clsb, woutb, bout_pad, nullptr, nullptr, logits, BATCH, OUTP, DMODEL);
    softmax_head_kernel<<<BATCH, 256>>>(logits, out);
}

// round 13
// speedup vs baseline: 1.4631x; 1.0012x over previous
#include <cuda_runtime.h>
#include <cuda_bf16.h>
#include <math.h>
#include <stdint.h>

// ---------------- problem constants ----------------
#define BATCH 128
#define CH    3
#define HIM   224
#define PGRID 14
#define NP    196
#define PATCH 16
#define IN_D  768
#define DMODEL 256
#define NHEAD 8
#define DH    32
#define NLAYER 4
#define SEQ   197
#define OUTC  1000
#define OUTP  1024          // padded head cols
#define LNEPS 1e-5f

typedef __nv_bfloat16 bf16;

// ---------------- scratch (device globals) ----------------
__device__ bf16  g_patches_b[BATCH * NP * IN_D];
__device__ float g_X [BATCH * SEQ * DMODEL];
__device__ bf16  g_x1b[BATCH * SEQ * DMODEL];
__device__ bf16  g_qb [BATCH * SEQ * DMODEL];             // [n,h,s,e] (pre-scaled)
__device__ bf16  g_kb [BATCH * SEQ * DMODEL];
__device__ bf16  g_vb [BATCH * SEQ * DMODEL];
__device__ bf16  g_ob [BATCH * SEQ * DMODEL];             // [n,s,d]
__device__ bf16  g_h1b[BATCH * SEQ * 4 * DMODEL];
__device__ float g_pe[SEQ * DMODEL];
__device__ bf16  g_wmapb [DMODEL * IN_D];
__device__ bf16  g_wlastb[NLAYER * DMODEL * DMODEL];
__device__ bf16  g_wmlp1b[NLAYER * 4 * DMODEL * DMODEL];
__device__ bf16  g_wmlp2b[NLAYER * 4 * DMODEL * DMODEL];
__device__ bf16  g_wout_hi[OUTP * DMODEL];
__device__ bf16  g_wout_lo[OUTP * DMODEL];
__device__ float g_bout_pad[OUTP];
__device__ float g_bzero[OUTP];
__device__ bf16  g_cls_hi[BATCH * DMODEL];
__device__ bf16  g_cls_lo[BATCH * DMODEL];
__device__ float g_logits[BATCH * OUTP];

// ---------------- fp32 -> bf16 convert, all weights in one launch ----------
__device__ __forceinline__ void cvt4(const float* __restrict__ s, bf16* __restrict__ d, int i)
{
    float4 v = *(const float4*)(s + i);
    __nv_bfloat162 p0 = __floats2bfloat162_rn(v.x, v.y);
    __nv_bfloat162 p1 = __floats2bfloat162_rn(v.z, v.w);
    uint2 o;
    o.x = *reinterpret_cast<uint32_t*>(&p0);
    o.y = *reinterpret_cast<uint32_t*>(&p1);
    *reinterpret_cast<uint2*>(d + i) = o;
}

__global__ void cvt_all_kernel(const float* __restrict__ s0, bf16* __restrict__ d0, int n0,
                               const float* __restrict__ s1, bf16* __restrict__ d1, int n1,
                               const float* __restrict__ s2, bf16* __restrict__ d2, int n2,
                               const float* __restrict__ s3, bf16* __restrict__ d3, int n3)
{
    int i = (blockIdx.x * 256 + threadIdx.x) * 4;
    if (i < n0) { cvt4(s0, d0, i); return; }
    i -= n0;
    if (i < n1) { cvt4(s1, d1, i); return; }
    i -= n1;
    if (i < n2) { cvt4(s2, d2, i); return; }
    i -= n2;
    if (i < n3) { cvt4(s3, d3, i); return; }
}

// ---------------- head weight pad + hi/lo split (runs per launch) ----------
__global__ void cvt_head_kernel(const float* __restrict__ w_out, const float* __restrict__ b_out,
                                bf16* __restrict__ whi, bf16* __restrict__ wlo,
                                float* __restrict__ bpad, float* __restrict__ bzero)
{
    int tid = blockIdx.x * 256 + threadIdx.x;
    int i = tid * 4;
    if (i < OUTP * DMODEL) {
        int row = i / DMODEL;
        if (row < OUTC) {
            float4 v = *(const float4*)(w_out + i);
            bf16 h0 = __float2bfloat16(v.x), h1 = __float2bfloat16(v.y);
            bf16 h2 = __float2bfloat16(v.z), h3 = __float2bfloat16(v.w);
            whi[i]     = h0; whi[i + 1] = h1; whi[i + 2] = h2; whi[i + 3] = h3;
            wlo[i]     = __float2bfloat16(v.x - __bfloat162float(h0));
            wlo[i + 1] = __float2bfloat16(v.y - __bfloat162float(h1));
            wlo[i + 2] = __float2bfloat16(v.z - __bfloat162float(h2));
            wlo[i + 3] = __float2bfloat16(v.w - __bfloat162float(h3));
        } else {
            uint2 z = {0u, 0u};
            *reinterpret_cast<uint2*>(whi + i) = z;
            *reinterpret_cast<uint2*>(wlo + i) = z;
        }
    }
    if (tid < OUTP) {
        bpad[tid]  = (tid < OUTC) ? b_out[tid] : 0.f;
        bzero[tid] = 0.f;
    }
}

// ---------------- cls row extraction: X[n][0][:] -> bf16 hi/lo --------------
__global__ void cls_extract_kernel(const float* __restrict__ X,
                                   bf16* __restrict__ chi, bf16* __restrict__ clo)
{
    int i = (blockIdx.x * 256 + threadIdx.x) * 4;
    if (i >= BATCH * DMODEL) return;
    int n = i / DMODEL, d = i % DMODEL;
    float4 v = *(const float4*)(X + (size_t)n * SEQ * DMODEL + d);
    bf16 h0 = __float2bfloat16(v.x), h1 = __float2bfloat16(v.y);
    bf16 h2 = __float2bfloat16(v.z), h3 = __float2bfloat16(v.w);
    chi[i]     = h0; chi[i + 1] = h1; chi[i + 2] = h2; chi[i + 3] = h3;
    clo[i]     = __float2bfloat16(v.x - __bfloat162float(h0));
    clo[i + 1] = __float2bfloat16(v.y - __bfloat162float(h1));
    clo[i + 2] = __float2bfloat16(v.z - __bfloat162float(h2));
    clo[i + 3] = __float2bfloat16(v.w - __bfloat162float(h3));
}

// ---------------- patch extraction (float4 gather, writes bf16) ------------
__global__ void patch_kernel(const float* __restrict__ img, bf16* __restrict__ out)
{
    int tid = blockIdx.x * 256 + threadIdx.x;
    int idx = tid * 4;
    if (idx >= BATCH * NP * IN_D) return;
    int i = idx % IN_D;
    int p = (idx / IN_D) % NP;
    int n = idx / (IN_D * NP);
    int c   = i >> 8;
    int r   = (i >> 4) & 15;
    int col = i & 15;
    int py = p / PGRID, px = p % PGRID;
    float4 v = *(const float4*)(img + (((size_t)n * CH + c) * HIM + py * PATCH + r) * HIM
                                    + px * PATCH + col);
    __nv_bfloat162 p0 = __floats2bfloat162_rn(v.x, v.y);
    __nv_bfloat162 p1 = __floats2bfloat162_rn(v.z, v.w);
    uint2 o;
    o.x = *reinterpret_cast<uint32_t*>(&p0);
    o.y = *reinterpret_cast<uint32_t*>(&p1);
    *reinterpret_cast<uint2*>(out + idx) = o;
}

// ---------------- positional encoding (fp32; sinf/cosf are range-reduced) ---
__global__ void pe_kernel(float* __restrict__ pe)
{
    int i = blockIdx.x * 256 + threadIdx.x;
    if (i >= SEQ * DMODEL) return;
    int s = i / DMODEL, d = i % DMODEL;
    float expo = (float)(2 * (d / 2)) * (1.0f / DMODEL);
    float ang  = (float)s * powf(10000.0f, -expo);
    pe[i] = (d & 1) ? cosf(ang) : sinf(ang);
}

// ---------------- cls rows: X[n][0][:] = cls + pe[0] ------------------------
__global__ void cls_kernel(const float* __restrict__ cls,
                           const float* __restrict__ pe,
                           float* __restrict__ X)
{
    int i = blockIdx.x * 256 + threadIdx.x;
    if (i >= BATCH * DMODEL) return;
    int d = i % DMODEL;
    int n = i / DMODEL;
    X[(size_t)n * SEQ * DMODEL + d] = cls[d] + pe[d];
}

// ---------------- bf16 MMA / ldmatrix helpers -------------------------------
__device__ __forceinline__ void mma_bf16(float* c, const uint32_t* a, const uint32_t* b)
{
    asm volatile(
        "mma.sync.aligned.m16n8k16.row.col.f32.bf16.bf16.f32 "
        "{%0,%1,%2,%3}, {%4,%5,%6,%7}, {%8,%9}, {%0,%1,%2,%3};"
        : "+f"(c[0]), "+f"(c[1]), "+f"(c[2]), "+f"(c[3])
        : "r"(a[0]), "r"(a[1]), "r"(a[2]), "r"(a[3]), "r"(b[0]), "r"(b[1]));
}

#define LDSM4(r0, r1, r2, r3, addr) \
    asm volatile("ldmatrix.sync.aligned.m8n8.x4.shared.b16 {%0,%1,%2,%3}, [%4];" \
                 : "=r"(r0), "=r"(r1), "=r"(r2), "=r"(r3) : "r"(addr))

#define CP16(dst, src) asm volatile("cp.async.cg.shared.global [%0], [%1], 16;\n" :: "r"(dst), "l"(src))
#define CP_COMMIT()    asm volatile("cp.async.commit_group;\n" ::)
#define CP_WAIT1()     asm volatile("cp.async.wait_group 1;\n" ::)
#define CP_WAIT0()     asm volatile("cp.async.wait_group 0;\n" ::)

// ---------------- bf16 tensor-core GEMM, 128x128 tile (frozen config) -------
#define STR 36                      // u32 stride per 64-bf16 row (pad 4) = 144B
#define ABUF (128 * STR)            // u32
#define GEMM_SMEM (4 * ABUF * 4)    // A0,A1,B0,B1 = 73728 B

template<int ACT, bool HASRES, bool OUTBF, bool ADDPE>
__global__ void __launch_bounds__(256) gemm_bf(const bf16* __restrict__ A,
                                               const bf16* __restrict__ W,
                                               const float* __restrict__ bias,
                                               const float* __restrict__ res,
                                               const float* __restrict__ pe,
                                               void* __restrict__ Cout,
                                               int M, int N, int K)
{
    extern __shared__ uint32_t sm_[];
    const uint32_t smem_byte = (uint32_t)__cvta_generic_to_shared(sm_);

    const int t    = threadIdx.x;
    const int warp = t >> 5, lane = t & 31;
    const int g    = lane >> 2, q4 = lane & 3;
    const int warp_m = (warp >> 1) * 32;
    const int warp_n = (warp & 1) * 64;
    const int row0 = blockIdx.y * 128, col0 = blockIdx.x * 128;

    float acc[2][8][4];
#pragma unroll
    for (int mi = 0; mi < 2; mi++)
#pragma unroll
        for (int ni = 0; ni < 8; ni++)
#pragma unroll
            for (int e = 0; e < 4; e++) acc[mi][ni][e] = 0.f;

    auto stage = [&](int k0, int buf) {
        uint32_t abase = smem_byte + buf * (ABUF * 4);
        uint32_t bbase = smem_byte + (2 + buf) * (ABUF * 4);
#pragma unroll
        for (int i = 0; i < 4; i++) {
            int c = t + i * 256;
            int r = c >> 3, co = c & 7;
            CP16(abase + (r * STR + co * 4) * 4, A + (size_t)(row0 + r) * K + k0 + co * 8);
            CP16(bbase + (r * STR + co * 4) * 4, W + (size_t)(col0 + r) * K + k0 + co * 8);
        }
        CP_COMMIT();
    };

    uint32_t a_addr[2][2], b_addr[2][4];
    {
        int ar = warp_m + (lane & 15);
        int ab = (lane >> 4) * 16;
        int br = warp_n + ((lane >> 4) & 1) * 8 + (lane & 7);
        int bb = ((lane >> 3) & 1) * 16;
#pragma unroll
        for (int buf = 0; buf < 2; buf++) {
            uint32_t abase = smem_byte + buf * (ABUF * 4);
            uint32_t bbase = smem_byte + (2 + buf) * (ABUF * 4);
#pragma unroll
            for (int mi = 0; mi < 2; mi++)
                a_addr[buf][mi] = abase + (ar + mi * 16) * (STR * 4) + ab;
#pragma unroll
            for (int nj = 0; nj < 4; nj++)
                b_addr[buf][nj] = bbase + (br + nj * 16) * (STR * 4) + bb;
        }
    }

    const int KT = K >> 6;
    stage(0, 0);

    for (int kt = 0; kt < KT; kt++) {
        const int cur = kt & 1;
        if (kt + 1 < KT) { stage((kt + 1) << 6, cur ^ 1); CP_WAIT1(); }
        else             { CP_WAIT0(); }
        __syncthreads();

#pragma unroll
        for (int ks = 0; ks < 4; ks++) {
            const uint32_t kb = ks * 32;
            uint32_t af[2][4];
            LDSM4(af[0][0], af[0][1], af[0][2], af[0][3], a_addr[cur][0] + kb);
            LDSM4(af[1][0], af[1][1], af[1][2], af[1][3], a_addr[cur][1] + kb);
            uint32_t bf_[8][2];
#pragma unroll
            for (int nj = 0; nj < 4; nj++)
                LDSM4(bf_[2 * nj][0], bf_[2 * nj][1], bf_[2 * nj + 1][0], bf_[2 * nj + 1][1],
                      b_addr[cur][nj] + kb);
#pragma unroll
            for (int mi = 0; mi < 2; mi++)
#pragma unroll
                for (int ni = 0; ni < 8; ni++)
                    mma_bf16(acc[mi][ni], af[mi], bf_[ni]);
        }
        __syncthreads();
    }

    // epilogue
#pragma unroll
    for (int mi = 0; mi < 2; mi++) {
        int ra = row0 + warp_m + mi * 16 + g;
        int rb = ra + 8;
        size_t orow_a, orow_b;
        if (ADDPE) {
            orow_a = (size_t)(ra / NP) * SEQ + (ra % NP) + 1;
            orow_b = (size_t)(rb / NP) * SEQ + (rb % NP) + 1;
        } else {
            orow_a = ra; orow_b = rb;
        }
        int pes_a = ADDPE ? ((ra % NP) + 1) : 0;
        int pes_b = ADDPE ? ((rb % NP) + 1) : 0;
#pragma unroll
        for (int ni = 0; ni < 8; ni++) {
            int col = col0 + warp_n + ni * 8 + q4 * 2;
            float b0 = bias[col], b1 = bias[col + 1];
            float v00 = acc[mi][ni][0] + b0, v01 = acc[mi][ni][1] + b1;
            float v10 = acc[mi][ni][2] + b0, v11 = acc[mi][ni][3] + b1;
            if (ACT == 1) {
                v00 = 0.5f * v00 * (1.0f + erff(v00 * 0.70710678118654752f));
                v01 = 0.5f * v01 * (1.0f + erff(v01 * 0.70710678118654752f));
                v10 = 0.5f * v10 * (1.0f + erff(v10 * 0.70710678118654752f));
                v11 = 0.5f * v11 * (1.0f + erff(v11 * 0.70710678118654752f));
            }
            if (HASRES) {
                float2 r0 = *(const float2*)(res + orow_a * N + col);
                float2 r1 = *(const float2*)(res + orow_b * N + col);
                v00 += r0.x; v01 += r0.y; v10 += r1.x; v11 += r1.y;
            }
            if (ADDPE) {
                float2 p0 = *(const float2*)(pe + (size_t)pes_a * DMODEL + col);
                float2 p1 = *(const float2*)(pe + (size_t)pes_b * DMODEL + col);
                v00 += p0.x; v01 += p0.y; v10 += p1.x; v11 += p1.y;
            }
            if (OUTBF) {
                bf16* C = (bf16*)Cout;
                __nv_bfloat162 p0 = __floats2bfloat162_rn(v00, v01);
                __nv_bfloat162 p1 = __floats2bfloat162_rn(v10, v11);
                *reinterpret_cast<uint32_t*>(C + orow_a * N + col) = *reinterpret_cast<uint32_t*>(&p0);
                *reinterpret_cast<uint32_t*>(C + orow_b * N + col) = *reinterpret_cast<uint32_t*>(&p1);
            } else {
                float* C = (float*)Cout;
                *(float2*)(C + orow_a * N + col) = make_float2(v00, v01);
                *(float2*)(C + orow_b * N + col) = make_float2(v10, v11);
            }
        }
    }
}

// ---------------- LayerNorm: warp per row, bf16 out -------------------------
__global__ void ln_kernel(const float* __restrict__ x,
                          const float* __restrict__ g,
                          const float* __restrict__ b,
                          bf16* __restrict__ y)
{
    const int row  = blockIdx.x * 8 + (threadIdx.x >> 5);
    const int lane = threadIdx.x & 31;
    const float4* xp = (const float4*)(x + (size_t)row * DMODEL);
    float4 u = xp[lane * 2], w = xp[lane * 2 + 1];

    float s = u.x + u.y + u.z + u.w + w.x + w.y + w.z + w.w;
#pragma unroll
    for (int off = 16; off; off >>= 1) s += __shfl_xor_sync(0xffffffffu, s, off);
    float mu = s * (1.f / DMODEL);

    float d0 = u.x - mu, d1 = u.y - mu, d2 = u.z - mu, d3 = u.w - mu;
    float d4 = w.x - mu, d5 = w.y - mu, d6 = w.z - mu, d7 = w.w - mu;
    float s2 = d0*d0 + d1*d1 + d2*d2 + d3*d3 + d4*d4 + d5*d5 + d6*d6 + d7*d7;
#pragma unroll
    for (int off = 16; off; off >>= 1) s2 += __shfl_xor_sync(0xffffffffu, s2, off);
    float inv = rsqrtf(s2 * (1.f / DMODEL) + LNEPS);

    const float4* gp = (const float4*)g;
    const float4* bp = (const float4*)b;
    float4 g0 = gp[lane * 2], g1 = gp[lane * 2 + 1];
    float4 b0 = bp[lane * 2], b1 = bp[lane * 2 + 1];

    __nv_bfloat162 p0 = __floats2bfloat162_rn(d0 * inv * g0.x + b0.x, d1 * inv * g0.y + b0.y);
    __nv_bfloat162 p1 = __floats2bfloat162_rn(d2 * inv * g0.z + b0.z, d3 * inv * g0.w + b0.w);
    __nv_bfloat162 p2 = __floats2bfloat162_rn(d4 * inv * g1.x + b1.x, d5 * inv * g1.y + b1.y);
    __nv_bfloat162 p3 = __floats2bfloat162_rn(d6 * inv * g1.z + b1.z, d7 * inv * g1.w + b1.w);
    uint4 o;
    o.x = *reinterpret_cast<uint32_t*>(&p0);
    o.y = *reinterpret_cast<uint32_t*>(&p1);
    o.z = *reinterpret_cast<uint32_t*>(&p2);
    o.w = *reinterpret_cast<uint32_t*>(&p3);
    *reinterpret_cast<uint4*>(y + (size_t)row * DMODEL + lane * 8) = o;
}

// ---------------- fused per-head QKV projection, 128 rows/block --------------
__global__ void qkv_kernel(const bf16* __restrict__ x1,
                           const float* __restrict__ wq, const float* __restrict__ bq,
                           const float* __restrict__ wk, const float* __restrict__ bk,
                           const float* __restrict__ wv, const float* __restrict__ bv,
                           bf16* __restrict__ q, bf16* __restrict__ k, bf16* __restrict__ v)
{
    __shared__ float wqs[32 * 33], wks[32 * 33], wvs[32 * 33];
    __shared__ float bqs[32], bks[32], bvs[32];
    __shared__ float xr[128 * 33];
    const int nh = blockIdx.x;
    const int n = nh / NHEAD, h = nh % NHEAD;
    const int t = threadIdx.x;
    const float* wqg = wq + (size_t)h * DH * DH;
    const float* wkg = wk + (size_t)h * DH * DH;
    const float* wvg = wv + (size_t)h * DH * DH;

    for (int i = t; i < DH * DH; i += 256) {
        int e = i >> 5, d = i & 31;
        wqs[e * 33 + d] = wqg[i];
        wks[e * 33 + d] = wkg[i];
        wvs[e * 33 + d] = wvg[i];
    }
    if (t < 32) { bqs[t] = bq[h * DH + t]; bks[t] = bk[h * DH + t]; bvs[t] = bv[h * DH + t]; }

    const int s0 = blockIdx.y * 128;
    for (int i = t; i < 128 * 32; i += 256) {
        int r = i >> 5, d = i & 31;
        int s = s0 + r;
        xr[r * 33 + d] = (s < SEQ)
            ? __bfloat162float(x1[((size_t)n * SEQ + s) * DMODEL + h * DH + d])
            : 0.f;
    }
    __syncthreads();

    const float scale = 0.17677669529663689f;  // 1/sqrt(32)
    const int wr = (t >> 5) * 16, lane = t & 31;
    const float bqv = bqs[lane], bkv = bks[lane], bvv = bvs[lane];
#pragma unroll 4
    for (int r = 0; r < 16; r++) {
        int s = s0 + wr + r;
        if (s >= SEQ) break;
        const float* xp = xr + (wr + r) * 33;
        float aq = bqv, ak = bkv, av = bvv;
#pragma unroll
        for (int d = 0; d < 32; d++) {
            float xv = xp[d];
            aq += xv * wqs[lane * 33 + d];
            ak += xv * wks[lane * 33 + d];
            av += xv * wvs[lane * 33 + d];
        }
        size_t oidx = ((size_t)nh * SEQ + s) * DH + lane;
        q[oidx] = __float2bfloat16(aq * scale);
        k[oidx] = __float2bfloat16(ak);
        v[oidx] = __float2bfloat16(av);
    }
}

// ---------------- tensor-core flash attention per (n,h) ---------------------
#define SPAD 224
#define NKT  7
#define KSTR 20
#define VSTR 116

__global__ void __launch_bounds__(224) attn_tc(const bf16* __restrict__ q,
                                               const bf16* __restrict__ k,
                                               const bf16* __restrict__ v,
                                               bf16* __restrict__ o)
{
    __shared__ uint32_t Ks[SPAD * KSTR];
    __shared__ uint32_t VT[32 * VSTR];

    const int nh = blockIdx.x;
    const int n = nh / NHEAD, h = nh % NHEAD;
    const int t = threadIdx.x, warp = t >> 5, lane = t & 31;
    const int g = lane >> 2, q4 = lane & 3;
    const size_t base = (size_t)nh * SEQ * DH;
    const uint32_t* q32 = (const uint32_t*)(q + base);
    const uint32_t* k32 = (const uint32_t*)(k + base);
    const uint32_t* v32 = (const uint32_t*)(v + base);

    for (int i = t; i < SPAD * 16; i += 224) {
        int r = i >> 4, c = i & 15;
        Ks[r * KSTR + c] = (r < SEQ) ? k32[r * 16 + c] : 0u;
    }
    bf16* VT16 = (bf16*)VT;
    for (int i = t; i < SPAD * 16; i += 224) {
        int tt = i >> 4, c = i & 15;
        uint32_t val = (tt < SEQ) ? v32[tt * 16 + c] : 0u;
        __nv_bfloat162 pr = *reinterpret_cast<__nv_bfloat162*>(&val);
        VT16[(2 * c)     * (VSTR * 2) + tt] = pr.x;
        VT16[(2 * c + 1) * (VSTR * 2) + tt] = pr.y;
    }
    __syncthreads();

    const int qbase = warp * 32;
    uint32_t qf[2][2][4];
#pragma unroll
    for (int mi = 0; mi < 2; mi++) {
        int r0 = qbase + mi * 16 + g, r1 = r0 + 8;
        bool v0 = r0 < SEQ, v1 = r1 < SEQ;
#pragma unroll
        for (int ks = 0; ks < 2; ks++) {
            qf[mi][ks][0] = v0 ? q32[r0 * 16 + ks * 8 + q4]     : 0u;
            qf[mi][ks][1] = v1 ? q32[r1 * 16 + ks * 8 + q4]     : 0u;
            qf[mi][ks][2] = v0 ? q32[r0 * 16 + ks * 8 + q4 + 4] : 0u;
            qf[mi][ks][3] = v1 ? q32[r1 * 16 + ks * 8 + q4 + 4] : 0u;
        }
    }

    float Oa[2][4][4];
#pragma unroll
    for (int mi = 0; mi < 2; mi++)
#pragma unroll
        for (int ne = 0; ne < 4; ne++)
#pragma unroll
            for (int e = 0; e < 4; e++) Oa[mi][ne][e] = 0.f;
    float m_[2][2] = {{-1e30f, -1e30f}, {-1e30f, -1e30f}};
    float l_[2][2] = {{0.f, 0.f}, {0.f, 0.f}};

    auto body = [&](int kt, bool last_mask) {
        float sc[2][4][4];
#pragma unroll
        for (int mi = 0; mi < 2; mi++)
#pragma unroll
            for (int ni = 0; ni < 4; ni++)
#pragma unroll
                for (int e = 0; e < 4; e++) sc[mi][ni][e] = 0.f;

        uint32_t kf[2][4][2];
#pragma unroll
        for (int ks = 0; ks < 2; ks++)
#pragma unroll
            for (int ni = 0; ni < 4; ni++) {
                int r = kt * 32 + ni * 8 + g;
                kf[ks][ni][0] = Ks[r * KSTR + ks * 8 + q4];
                kf[ks][ni][1] = Ks[r * KSTR + ks * 8 + q4 + 4];
            }
#pragma unroll
        for (int mi = 0; mi < 2; mi++)
#pragma unroll
            for (int ni = 0; ni < 4; ni++)
#pragma unroll
                for (int ks = 0; ks < 2; ks++)
                    mma_bf16(sc[mi][ni], qf[mi][ks], kf[ks][ni]);

        if (last_mask) {
#pragma unroll
            for (int mi = 0; mi < 2; mi++)
#pragma unroll
                for (int ni = 0; ni < 4; ni++) {
                    int col = kt * 32 + ni * 8 + q4 * 2;
#pragma unroll
                    for (int hf = 0; hf < 2; hf++) {
                        if (col     >= SEQ) sc[mi][ni][hf * 2]     = -1e30f;
                        if (col + 1 >= SEQ) sc[mi][ni][hf * 2 + 1] = -1e30f;
                    }
                }
        }

#pragma unroll
        for (int mi = 0; mi < 2; mi++) {
#pragma unroll
            for (int hf = 0; hf < 2; hf++) {
                float mx = fmaxf(fmaxf(sc[mi][0][hf * 2], sc[mi][0][hf * 2 + 1]),
                                 fmaxf(sc[mi][1][hf * 2], sc[mi][1][hf * 2 + 1]));
                mx = fmaxf(mx, fmaxf(fmaxf(sc[mi][2][hf * 2], sc[mi][2][hf * 2 + 1]),
                                     fmaxf(sc[mi][3][hf * 2], sc[mi][3][hf * 2 + 1])));
                mx = fmaxf(mx, __shfl_xor_sync(0xffffffffu, mx, 1));
                mx = fmaxf(mx, __shfl_xor_sync(0xffffffffu, mx, 2));
                float mnew = fmaxf(m_[mi][hf], mx);
                float f = __expf(m_[mi][hf] - mnew);
                m_[mi][hf] = mnew;
                float rs = 0.f;
#pragma unroll
                for (int ni = 0; ni < 4; ni++) {
                    float p0 = __expf(sc[mi][ni][hf * 2]     - mnew);
                    float p1 = __expf(sc[mi][ni][hf * 2 + 1] - mnew);
                    sc[mi][ni][hf * 2]     = p0;
                    sc[mi][ni][hf * 2 + 1] = p1;
                    rs += p0 + p1;
                }
                rs += __shfl_xor_sync(0xffffffffu, rs, 1);
                rs += __shfl_xor_sync(0xffffffffu, rs, 2);
                l_[mi][hf] = l_[mi][hf] * f + rs;
#pragma unroll
                for (int ne = 0; ne < 4; ne++) {
                    Oa[mi][ne][hf * 2]     *= f;
                    Oa[mi][ne][hf * 2 + 1] *= f;
                }
            }
        }

        uint32_t pa[2][2][4];
#pragma unroll
        for (int mi = 0; mi < 2; mi++)
#pragma unroll
            for (int ks = 0; ks < 2; ks++) {
                __nv_bfloat162 t0 = __floats2bfloat162_rn(sc[mi][2 * ks][0],     sc[mi][2 * ks][1]);
                __nv_bfloat162 t1 = __floats2bfloat162_rn(sc[mi][2 * ks][2],     sc[mi][2 * ks][3]);
                __nv_bfloat162 t2 = __floats2bfloat162_rn(sc[mi][2 * ks + 1][0], sc[mi][2 * ks + 1][1]);
                __nv_bfloat162 t3 = __floats2bfloat162_rn(sc[mi][2 * ks + 1][2], sc[mi][2 * ks + 1][3]);
                pa[mi][ks][0] = *reinterpret_cast<uint32_t*>(&t0);
                pa[mi][ks][1] = *reinterpret_cast<uint32_t*>(&t1);
                pa[mi][ks][2] = *reinterpret_cast<uint32_t*>(&t2);
                pa[mi][ks][3] = *reinterpret_cast<uint32_t*>(&t3);
            }

        uint32_t vf[2][4][2];
#pragma unroll
        for (int ks = 0; ks < 2; ks++)
#pragma unroll
            for (int ne = 0; ne < 4; ne++) {
                int r = ne * 8 + g;
                int cu = kt * 16 + ks * 8 + q4;
                vf[ks][ne][0] = VT[r * VSTR + cu];
                vf[ks][ne][1] = VT[r * VSTR + cu + 4];
            }
#pragma unroll
        for (int mi = 0; mi < 2; mi++)
#pragma unroll
            for (int ne = 0; ne < 4; ne++)
#pragma unroll
                for (int ks = 0; ks < 2; ks++)
                    mma_bf16(Oa[mi][ne], pa[mi][ks], vf[ks][ne]);
    };

    for (int kt = 0; kt < NKT - 1; kt++) body(kt, false);
    body(NKT - 1, true);

#pragma unroll
    for (int mi = 0; mi < 2; mi++) {
#pragma unroll
        for (int hf = 0; hf < 2; hf++) {
            int row = qbase + mi * 16 + hf * 8 + g;
            if (row >= SEQ) continue;
            float inv = 1.f / l_[mi][hf];
            bf16* op = o + ((size_t)n * SEQ + row) * DMODEL + h * DH;
#pragma unroll
            for (int ne = 0; ne < 4; ne++) {
                __nv_bfloat162 p = __floats2bfloat162_rn(Oa[mi][ne][hf * 2] * inv,
                                                         Oa[mi][ne][hf * 2 + 1] * inv);
                *reinterpret_cast<uint32_t*>(op + ne * 8 + q4 * 2) = *reinterpret_cast<uint32_t*>(&p);
            }
        }
    }
}

// ---------------- softmax over precomputed logits ---------------------------
__global__ void softmax_head_kernel(const float* __restrict__ logits_in,
                                    float* __restrict__ out)
{
    __shared__ float logits[OUTC];
    __shared__ float red[8];
    const int n = blockIdx.x;
    const int t = threadIdx.x, wid = t >> 5, lane = t & 31;

    for (int j = t; j < OUTC; j += 256) logits[j] = logits_in[(size_t)n * OUTP + j];
    __syncthreads();

    float mx = -1e30f;
    for (int j = t; j < OUTC; j += 256) mx = fmaxf(mx, logits[j]);
#pragma unroll
    for (int off = 16; off; off >>= 1) mx = fmaxf(mx, __shfl_xor_sync(0xffffffffu, mx, off));
    if (lane == 0) red[wid] = mx;
    __syncthreads();
    float bm = -1e30f;
#pragma unroll
    for (int i = 0; i < 8; i++) bm = fmaxf(bm, red[i]);
    __syncthreads();

    float sum = 0.f;
    for (int j = t; j < OUTC; j += 256) {
        float e = __expf(logits[j] - bm);
        logits[j] = e;
        sum += e;
    }
#pragma unroll
    for (int off = 16; off; off >>= 1) sum += __shfl_xor_sync(0xffffffffu, sum, off);
    if (lane == 0) red[wid] = sum;
    __syncthreads();
    float bs = 0.f;
#pragma unroll
    for (int i = 0; i < 8; i++) bs += red[i];
    float inv = 1.f / bs;
    __syncthreads();
    for (int j = t; j < OUTC; j += 256) out[(size_t)n * OUTC + j] = logits[j] * inv;
}

// ---------------- launcher ----------------
extern "C" void kernel_launch(void* const* d_in, const int* in_sizes, int n_in,
                              void* d_out, int out_size)
{
    const float* images  = (const float*)d_in[0];
    const float* w_map   = (const float*)d_in[1];
    const float* b_map   = (const float*)d_in[2];
    const float* cls_tok = (const float*)d_in[3];
    const float* norm1_g = (const float*)d_in[4];
    const float* norm1_b = (const float*)d_in[5];
    const float* wq      = (const float*)d_in[6];
    const float* bq      = (const float*)d_in[7];
    const float* wk      = (const float*)d_in[8];
    const float* bk      = (const float*)d_in[9];
    const float* wv      = (const float*)d_in[10];
    const float* bv      = (const float*)d_in[11];
    const float* w_last  = (const float*)d_in[12];
    const float* b_last  = (const float*)d_in[13];
    const float* norm2_g = (const float*)d_in[14];
    const float* norm2_b = (const float*)d_in[15];
    const float* w_mlp1  = (const float*)d_in[16];
    const float* b_mlp1  = (const float*)d_in[17];
    const float* w_mlp2  = (const float*)d_in[18];
    const float* b_mlp2  = (const float*)d_in[19];
    const float* w_out   = (const float*)d_in[20];
    const float* b_out   = (const float*)d_in[21];
    float* out = (float*)d_out;

    bf16 *patches, *x1b, *qb, *kb, *vb, *ob, *h1b;
    bf16 *wmapb, *wlastb, *wmlp1b, *wmlp2b, *whi, *wlo, *chi, *clo;
    float *X, *pe, *bout_pad, *bzero, *logits;
    cudaGetSymbolAddress((void**)&patches, g_patches_b);
    cudaGetSymbolAddress((void**)&X,   g_X);
    cudaGetSymbolAddress((void**)&x1b, g_x1b);
    cudaGetSymbolAddress((void**)&qb,  g_qb);
    cudaGetSymbolAddress((void**)&kb,  g_kb);
    cudaGetSymbolAddress((void**)&vb,  g_vb);
    cudaGetSymbolAddress((void**)&ob,  g_ob);
    cudaGetSymbolAddress((void**)&h1b, g_h1b);
    cudaGetSymbolAddress((void**)&pe,  g_pe);
    cudaGetSymbolAddress((void**)&wmapb,  g_wmapb);
    cudaGetSymbolAddress((void**)&wlastb, g_wlastb);
    cudaGetSymbolAddress((void**)&wmlp1b, g_wmlp1b);
    cudaGetSymbolAddress((void**)&wmlp2b, g_wmlp2b);
    cudaGetSymbolAddress((void**)&whi, g_wout_hi);
    cudaGetSymbolAddress((void**)&wlo, g_wout_lo);
    cudaGetSymbolAddress((void**)&chi, g_cls_hi);
    cudaGetSymbolAddress((void**)&clo, g_cls_lo);
    cudaGetSymbolAddress((void**)&bout_pad, g_bout_pad);
    cudaGetSymbolAddress((void**)&bzero,    g_bzero);
    cudaGetSymbolAddress((void**)&logits,   g_logits);

    cudaFuncSetAttribute(gemm_bf<0, false, false, true >, cudaFuncAttributeMaxDynamicSharedMemorySize, GEMM_SMEM);
    cudaFuncSetAttribute(gemm_bf<0, true,  false, false>, cudaFuncAttributeMaxDynamicSharedMemorySize, GEMM_SMEM);
    cudaFuncSetAttribute(gemm_bf<1, false, true,  false>, cudaFuncAttributeMaxDynamicSharedMemorySize, GEMM_SMEM);
    cudaFuncSetAttribute(gemm_bf<0, false, false, false>, cudaFuncAttributeMaxDynamicSharedMemorySize, GEMM_SMEM);

    // 0) weight conversion to bf16 (+ padded hi/lo head weights)
    {
        int n0 = DMODEL * IN_D;
        int n1 = NLAYER * DMODEL * DMODEL;
        int n3 = NLAYER * 4 * DMODEL * DMODEL;
        int totf4 = (n0 + n1 + 2 * n3) / 4;
        cvt_all_kernel<<<(totf4 + 255) / 256, 256>>>(
            w_map, wmapb, n0, w_last, wlastb, n1,
            w_mlp1, wmlp1b, n3, w_mlp2, wmlp2b, n3);
        int hw = OUTP * DMODEL / 4;
        cvt_head_kernel<<<(hw + 255) / 256, 256>>>(w_out, b_out, whi, wlo, bout_pad, bzero);
    }

    // 1) patches + PE table
    {
        int tot = BATCH * NP * IN_D / 4;
        patch_kernel<<<(tot + 255) / 256, 256>>>(images, patches);
        int pt = SEQ * DMODEL;
        pe_kernel<<<(pt + 255) / 256, 256>>>(pe);
    }

    // 2) patch-embed GEMM fused with assemble
    gemm_bf<0, false, false, true><<<dim3(DMODEL / 128, (BATCH * NP) / 128), 256, GEMM_SMEM>>>(
        patches, wmapb, b_map, nullptr, pe, X, BATCH * NP, DMODEL, IN_D);

    // 2b) cls rows
    cls_kernel<<<(BATCH * DMODEL + 255) / 256, 256>>>(cls_tok, pe, X);

    const int MROWS = BATCH * SEQ;   // 25216 = 128*197

    for (int l = 0; l < NLAYER; l++) {
        ln_kernel<<<MROWS / 8, 256>>>(X, norm1_g + l * DMODEL, norm1_b + l * DMODEL, x1b);

        qkv_kernel<<<dim3(BATCH * NHEAD, 2), 256>>>(
            x1b,
            wq + (size_t)l * NHEAD * DH * DH, bq + (size_t)l * NHEAD * DH,
            wk + (size_t)l * NHEAD * DH * DH, bk + (size_t)l * NHEAD * DH,
            wv + (size_t)l * NHEAD * DH * DH, bv + (size_t)l * NHEAD * DH,
            qb, kb, vb);

        attn_tc<<<BATCH * NHEAD, 224>>>(qb, kb, vb, ob);

        // o-proj + residual: X = X + o @ w_last^T + b_last (25216,256,256)
        gemm_bf<0, true, false, false><<<dim3(DMODEL / 128, MROWS / 128), 256, GEMM_SMEM>>>(
            ob, wlastb + (size_t)l * DMODEL * DMODEL, b_last + l * DMODEL, X, nullptr, X,
            MROWS, DMODEL, DMODEL);

        ln_kernel<<<MROWS / 8, 256>>>(X, norm2_g + l * DMODEL, norm2_b + l * DMODEL, x1b);

        // MLP1 + GELU -> bf16 h1 (25216,1024,256)
        gemm_bf<1, false, true, false><<<dim3((4 * DMODEL) / 128, MROWS / 128), 256, GEMM_SMEM>>>(
            x1b, wmlp1b + (size_t)l * 4 * DMODEL * DMODEL, b_mlp1 + l * 4 * DMODEL,
            nullptr, nullptr, h1b, MROWS, 4 * DMODEL, DMODEL);

        // MLP2 + residual: X = X + h1 @ w_mlp2^T + b2 (25216,256,1024)
        gemm_bf<0, true, false, false><<<dim3(DMODEL / 128, MROWS / 128), 256, GEMM_SMEM>>>(
            h1b, wmlp2b + (size_t)l * 4 * DMODEL * DMODEL, b_mlp2 + l * DMODEL, X, nullptr, X,
            MROWS, DMODEL, 4 * DMODEL);
    }

    // head: cls hi/lo extraction -> 3-term compensated bf16 GEMM -> softmax
    cls_extract_kernel<<<(BATCH * DMODEL / 4 + 255) / 256, 256>>>(X, chi, clo);
    gemm_bf<0, false, false, false><<<dim3(OUTP / 128, BATCH / 128), 256, GEMM_SMEM>>>(
        chi, whi, bout_pad, nullptr, nullptr, logits, BATCH, OUTP, DMODEL);
    gemm_bf<0, true, false, false><<<dim3(OUTP / 128, BATCH / 128), 256, GEMM_SMEM>>>(
        chi, wlo, bzero, logits, nullptr, logits, BATCH, OUTP, DMODEL);
    gemm_bf<0, true, false, false><<<dim3(OUTP / 128, BATCH / 128), 256, GEMM_SMEM>>>(
        clo, whi, bzero, logits, nullptr, logits, BATCH, OUTP, DMODEL);
    softmax_head_kernel<<<BATCH, 256>>>(logits, out);
}

// round 14
// speedup vs baseline: 1.4822x; 1.0131x over previous
#include <cuda_runtime.h>
#include <cuda_bf16.h>
#include <math.h>
#include <stdint.h>

// ---------------- problem constants ----------------
#define BATCH 128
#define CH    3
#define HIM   224
#define PGRID 14
#define NP    196
#define PATCH 16
#define IN_D  768
#define DMODEL 256
#define NHEAD 8
#define DH    32
#define NLAYER 4
#define SEQ   197
#define OUTC  1000
#define OUTP  1024
#define LNEPS 1e-5f

typedef __nv_bfloat16 bf16;

// ---------------- scratch (device globals) ----------------
__device__ bf16  g_patches_b[BATCH * NP * IN_D];
__device__ float g_X [BATCH * SEQ * DMODEL];
__device__ bf16  g_x1b[BATCH * SEQ * DMODEL];
__device__ bf16  g_qb [BATCH * SEQ * DMODEL];             // [n,h,s,e] (pre-scaled by scale*log2e)
__device__ bf16  g_kb [BATCH * SEQ * DMODEL];
__device__ bf16  g_vb [BATCH * SEQ * DMODEL];
__device__ bf16  g_ob [BATCH * SEQ * DMODEL];             // [n,s,d]
__device__ bf16  g_h1b[BATCH * SEQ * 4 * DMODEL];
__device__ float g_pe[SEQ * DMODEL];
__device__ bf16  g_wmapb [DMODEL * IN_D];
__device__ bf16  g_wlastb[NLAYER * DMODEL * DMODEL];
__device__ bf16  g_wmlp1b[NLAYER * 4 * DMODEL * DMODEL];
__device__ bf16  g_wmlp2b[NLAYER * 4 * DMODEL * DMODEL];
__device__ bf16  g_wout_hi[OUTP * DMODEL];
__device__ bf16  g_wout_lo[OUTP * DMODEL];
__device__ float g_bout_pad[OUTP];
__device__ float g_bzero[OUTP];
__device__ bf16  g_cls_hi[BATCH * DMODEL];
__device__ bf16  g_cls_lo[BATCH * DMODEL];
__device__ float g_logits[BATCH * OUTP];

__device__ __forceinline__ float ex2f(float x)
{
    float r;
    asm("ex2.approx.f32 %0, %1;" : "=f"(r) : "f"(x));
    return r;
}

// ---------------- fp32 -> bf16 convert, all weights in one launch ----------
__device__ __forceinline__ void cvt4(const float* __restrict__ s, bf16* __restrict__ d, int i)
{
    float4 v = *(const float4*)(s + i);
    __nv_bfloat162 p0 = __floats2bfloat162_rn(v.x, v.y);
    __nv_bfloat162 p1 = __floats2bfloat162_rn(v.z, v.w);
    uint2 o;
    o.x = *reinterpret_cast<uint32_t*>(&p0);
    o.y = *reinterpret_cast<uint32_t*>(&p1);
    *reinterpret_cast<uint2*>(d + i) = o;
}

__global__ void cvt_all_kernel(const float* __restrict__ s0, bf16* __restrict__ d0, int n0,
                               const float* __restrict__ s1, bf16* __restrict__ d1, int n1,
                               const float* __restrict__ s2, bf16* __restrict__ d2, int n2,
                               const float* __restrict__ s3, bf16* __restrict__ d3, int n3)
{
    int i = (blockIdx.x * 256 + threadIdx.x) * 4;
    if (i < n0) { cvt4(s0, d0, i); return; }
    i -= n0;
    if (i < n1) { cvt4(s1, d1, i); return; }
    i -= n1;
    if (i < n2) { cvt4(s2, d2, i); return; }
    i -= n2;
    if (i < n3) { cvt4(s3, d3, i); return; }
}

// ---------------- head weight pad + hi/lo split ------------------------------
__global__ void cvt_head_kernel(const float* __restrict__ w_out, const float* __restrict__ b_out,
                                bf16* __restrict__ whi, bf16* __restrict__ wlo,
                                float* __restrict__ bpad, float* __restrict__ bzero)
{
    int tid = blockIdx.x * 256 + threadIdx.x;
    int i = tid * 4;
    if (i < OUTP * DMODEL) {
        int row = i / DMODEL;
        if (row < OUTC) {
            float4 v = *(const float4*)(w_out + i);
            bf16 h0 = __float2bfloat16(v.x), h1 = __float2bfloat16(v.y);
            bf16 h2 = __float2bfloat16(v.z), h3 = __float2bfloat16(v.w);
            whi[i]     = h0; whi[i + 1] = h1; whi[i + 2] = h2; whi[i + 3] = h3;
            wlo[i]     = __float2bfloat16(v.x - __bfloat162float(h0));
            wlo[i + 1] = __float2bfloat16(v.y - __bfloat162float(h1));
            wlo[i + 2] = __float2bfloat16(v.z - __bfloat162float(h2));
            wlo[i + 3] = __float2bfloat16(v.w - __bfloat162float(h3));
        } else {
            uint2 z = {0u, 0u};
            *reinterpret_cast<uint2*>(whi + i) = z;
            *reinterpret_cast<uint2*>(wlo + i) = z;
        }
    }
    if (tid < OUTP) {
        bpad[tid]  = (tid < OUTC) ? b_out[tid] : 0.f;
        bzero[tid] = 0.f;
    }
}

// ---------------- cls row extraction: X[n][0][:] -> bf16 hi/lo --------------
__global__ void cls_extract_kernel(const float* __restrict__ X,
                                   bf16* __restrict__ chi, bf16* __restrict__ clo)
{
    int i = (blockIdx.x * 256 + threadIdx.x) * 4;
    if (i >= BATCH * DMODEL) return;
    int n = i / DMODEL, d = i % DMODEL;
    float4 v = *(const float4*)(X + (size_t)n * SEQ * DMODEL + d);
    bf16 h0 = __float2bfloat16(v.x), h1 = __float2bfloat16(v.y);
    bf16 h2 = __float2bfloat16(v.z), h3 = __float2bfloat16(v.w);
    chi[i]     = h0; chi[i + 1] = h1; chi[i + 2] = h2; chi[i + 3] = h3;
    clo[i]     = __float2bfloat16(v.x - __bfloat162float(h0));
    clo[i + 1] = __float2bfloat16(v.y - __bfloat162float(h1));
    clo[i + 2] = __float2bfloat16(v.z - __bfloat162float(h2));
    clo[i + 3] = __float2bfloat16(v.w - __bfloat162float(h3));
}

// ---------------- patch extraction (float4 gather, writes bf16) ------------
__global__ void patch_kernel(const float* __restrict__ img, bf16* __restrict__ out)
{
    int tid = blockIdx.x * 256 + threadIdx.x;
    int idx = tid * 4;
    if (idx >= BATCH * NP * IN_D) return;
    int i = idx % IN_D;
    int p = (idx / IN_D) % NP;
    int n = idx / (IN_D * NP);
    int c   = i >> 8;
    int r   = (i >> 4) & 15;
    int col = i & 15;
    int py = p / PGRID, px = p % PGRID;
    float4 v = *(const float4*)(img + (((size_t)n * CH + c) * HIM + py * PATCH + r) * HIM
                                    + px * PATCH + col);
    __nv_bfloat162 p0 = __floats2bfloat162_rn(v.x, v.y);
    __nv_bfloat162 p1 = __floats2bfloat162_rn(v.z, v.w);
    uint2 o;
    o.x = *reinterpret_cast<uint32_t*>(&p0);
    o.y = *reinterpret_cast<uint32_t*>(&p1);
    *reinterpret_cast<uint2*>(out + idx) = o;
}

// ---------------- positional encoding (fp32) ----------------
__global__ void pe_kernel(float* __restrict__ pe)
{
    int i = blockIdx.x * 256 + threadIdx.x;
    if (i >= SEQ * DMODEL) return;
    int s = i / DMODEL, d = i % DMODEL;
    float expo = (float)(2 * (d / 2)) * (1.0f / DMODEL);
    float ang  = (float)s * powf(10000.0f, -expo);
    pe[i] = (d & 1) ? cosf(ang) : sinf(ang);
}

// ---------------- cls rows: X[n][0][:] = cls + pe[0] ------------------------
__global__ void cls_kernel(const float* __restrict__ cls,
                           const float* __restrict__ pe,
                           float* __restrict__ X)
{
    int i = blockIdx.x * 256 + threadIdx.x;
    if (i >= BATCH * DMODEL) return;
    int d = i % DMODEL;
    int n = i / DMODEL;
    X[(size_t)n * SEQ * DMODEL + d] = cls[d] + pe[d];
}

// ---------------- bf16 MMA / ldmatrix helpers -------------------------------
__device__ __forceinline__ void mma_bf16(float* c, const uint32_t* a, const uint32_t* b)
{
    asm volatile(
        "mma.sync.aligned.m16n8k16.row.col.f32.bf16.bf16.f32 "
        "{%0,%1,%2,%3}, {%4,%5,%6,%7}, {%8,%9}, {%0,%1,%2,%3};"
        : "+f"(c[0]), "+f"(c[1]), "+f"(c[2]), "+f"(c[3])
        : "r"(a[0]), "r"(a[1]), "r"(a[2]), "r"(a[3]), "r"(b[0]), "r"(b[1]));
}

#define LDSM4(r0, r1, r2, r3, addr) \
    asm volatile("ldmatrix.sync.aligned.m8n8.x4.shared.b16 {%0,%1,%2,%3}, [%4];" \
                 : "=r"(r0), "=r"(r1), "=r"(r2), "=r"(r3) : "r"(addr))

#define CP16(dst, src) asm volatile("cp.async.cg.shared.global [%0], [%1], 16;\n" :: "r"(dst), "l"(src))
#define CP_COMMIT()    asm volatile("cp.async.commit_group;\n" ::)
#define CP_WAIT1()     asm volatile("cp.async.wait_group 1;\n" ::)
#define CP_WAIT0()     asm volatile("cp.async.wait_group 0;\n" ::)

// ---------------- bf16 tensor-core GEMM, 128x128 tile (frozen config) -------
#define STR 36
#define ABUF (128 * STR)
#define GEMM_SMEM (4 * ABUF * 4)

template<int ACT, bool HASRES, bool OUTBF, bool ADDPE>
__global__ void __launch_bounds__(256) gemm_bf(const bf16* __restrict__ A,
                                               const bf16* __restrict__ W,
                                               const float* __restrict__ bias,
                                               const float* __restrict__ res,
                                               const float* __restrict__ pe,
                                               void* __restrict__ Cout,
                                               int M, int N, int K)
{
    extern __shared__ uint32_t sm_[];
    const uint32_t smem_byte = (uint32_t)__cvta_generic_to_shared(sm_);

    const int t    = threadIdx.x;
    const int warp = t >> 5, lane = t & 31;
    const int g    = lane >> 2, q4 = lane & 3;
    const int warp_m = (warp >> 1) * 32;
    const int warp_n = (warp & 1) * 64;
    const int row0 = blockIdx.y * 128, col0 = blockIdx.x * 128;

    float acc[2][8][4];
#pragma unroll
    for (int mi = 0; mi < 2; mi++)
#pragma unroll
        for (int ni = 0; ni < 8; ni++)
#pragma unroll
            for (int e = 0; e < 4; e++) acc[mi][ni][e] = 0.f;

    auto stage = [&](int k0, int buf) {
        uint32_t abase = smem_byte + buf * (ABUF * 4);
        uint32_t bbase = smem_byte + (2 + buf) * (ABUF * 4);
#pragma unroll
        for (int i = 0; i < 4; i++) {
            int c = t + i * 256;
            int r = c >> 3, co = c & 7;
            CP16(abase + (r * STR + co * 4) * 4, A + (size_t)(row0 + r) * K + k0 + co * 8);
            CP16(bbase + (r * STR + co * 4) * 4, W + (size_t)(col0 + r) * K + k0 + co * 8);
        }
        CP_COMMIT();
    };

    uint32_t a_addr[2][2], b_addr[2][4];
    {
        int ar = warp_m + (lane & 15);
        int ab = (lane >> 4) * 16;
        int br = warp_n + ((lane >> 4) & 1) * 8 + (lane & 7);
        int bb = ((lane >> 3) & 1) * 16;
#pragma unroll
        for (int buf = 0; buf < 2; buf++) {
            uint32_t abase = smem_byte + buf * (ABUF * 4);
            uint32_t bbase = smem_byte + (2 + buf) * (ABUF * 4);
#pragma unroll
            for (int mi = 0; mi < 2; mi++)
                a_addr[buf][mi] = abase + (ar + mi * 16) * (STR * 4) + ab;
#pragma unroll
            for (int nj = 0; nj < 4; nj++)
                b_addr[buf][nj] = bbase + (br + nj * 16) * (STR * 4) + bb;
        }
    }

    const int KT = K >> 6;
    stage(0, 0);

    for (int kt = 0; kt < KT; kt++) {
        const int cur = kt & 1;
        if (kt + 1 < KT) { stage((kt + 1) << 6, cur ^ 1); CP_WAIT1(); }
        else             { CP_WAIT0(); }
        __syncthreads();

#pragma unroll
        for (int ks = 0; ks < 4; ks++) {
            const uint32_t kb = ks * 32;
            uint32_t af[2][4];
            LDSM4(af[0][0], af[0][1], af[0][2], af[0][3], a_addr[cur][0] + kb);
            LDSM4(af[1][0], af[1][1], af[1][2], af[1][3], a_addr[cur][1] + kb);
            uint32_t bf_[8][2];
#pragma unroll
            for (int nj = 0; nj < 4; nj++)
                LDSM4(bf_[2 * nj][0], bf_[2 * nj][1], bf_[2 * nj + 1][0], bf_[2 * nj + 1][1],
                      b_addr[cur][nj] + kb);
#pragma unroll
            for (int mi = 0; mi < 2; mi++)
#pragma unroll
                for (int ni = 0; ni < 8; ni++)
                    mma_bf16(acc[mi][ni], af[mi], bf_[ni]);
        }
        __syncthreads();
    }

#pragma unroll
    for (int mi = 0; mi < 2; mi++) {
        int ra = row0 + warp_m + mi * 16 + g;
        int rb = ra + 8;
        size_t orow_a, orow_b;
        if (ADDPE) {
            orow_a = (size_t)(ra / NP) * SEQ + (ra % NP) + 1;
            orow_b = (size_t)(rb / NP) * SEQ + (rb % NP) + 1;
        } else {
            orow_a = ra; orow_b = rb;
        }
        int pes_a = ADDPE ? ((ra % NP) + 1) : 0;
        int pes_b = ADDPE ? ((rb % NP) + 1) : 0;
#pragma unroll
        for (int ni = 0; ni < 8; ni++) {
            int col = col0 + warp_n + ni * 8 + q4 * 2;
            float b0 = bias[col], b1 = bias[col + 1];
            float v00 = acc[mi][ni][0] + b0, v01 = acc[mi][ni][1] + b1;
            float v10 = acc[mi][ni][2] + b0, v11 = acc[mi][ni][3] + b1;
            if (ACT == 1) {
                v00 = 0.5f * v00 * (1.0f + erff(v00 * 0.70710678118654752f));
                v01 = 0.5f * v01 * (1.0f + erff(v01 * 0.70710678118654752f));
                v10 = 0.5f * v10 * (1.0f + erff(v10 * 0.70710678118654752f));
                v11 = 0.5f * v11 * (1.0f + erff(v11 * 0.70710678118654752f));
            }
            if (HASRES) {
                float2 r0 = *(const float2*)(res + orow_a * N + col);
                float2 r1 = *(const float2*)(res + orow_b * N + col);
                v00 += r0.x; v01 += r0.y; v10 += r1.x; v11 += r1.y;
            }
            if (ADDPE) {
                float2 p0 = *(const float2*)(pe + (size_t)pes_a * DMODEL + col);
                float2 p1 = *(const float2*)(pe + (size_t)pes_b * DMODEL + col);
                v00 += p0.x; v01 += p0.y; v10 += p1.x; v11 += p1.y;
            }
            if (OUTBF) {
                bf16* C = (bf16*)Cout;
                __nv_bfloat162 p0 = __floats2bfloat162_rn(v00, v01);
                __nv_bfloat162 p1 = __floats2bfloat162_rn(v10, v11);
                *reinterpret_cast<uint32_t*>(C + orow_a * N + col) = *reinterpret_cast<uint32_t*>(&p0);
                *reinterpret_cast<uint32_t*>(C + orow_b * N + col) = *reinterpret_cast<uint32_t*>(&p1);
            } else {
                float* C = (float*)Cout;
                *(float2*)(C + orow_a * N + col) = make_float2(v00, v01);
                *(float2*)(C + orow_b * N + col) = make_float2(v10, v11);
            }
        }
    }
}

// ---------------- LayerNorm: 2 rows per warp, bf16 out ----------------------
__global__ void ln_kernel(const float* __restrict__ x,
                          const float* __restrict__ g,
                          const float* __restrict__ b,
                          bf16* __restrict__ y)
{
    const int warp = threadIdx.x >> 5, lane = threadIdx.x & 31;
    const int row0 = blockIdx.x * 16 + warp * 2;   // this warp: rows row0, row0+1

    const float4* xpA = (const float4*)(x + (size_t)row0 * DMODEL);
    const float4* xpB = (const float4*)(x + (size_t)(row0 + 1) * DMODEL);
    float4 uA = xpA[lane * 2], wA = xpA[lane * 2 + 1];
    float4 uB = xpB[lane * 2], wB = xpB[lane * 2 + 1];

    float sA = uA.x + uA.y + uA.z + uA.w + wA.x + wA.y + wA.z + wA.w;
    float sB = uB.x + uB.y + uB.z + uB.w + wB.x + wB.y + wB.z + wB.w;
#pragma unroll
    for (int off = 16; off; off >>= 1) {
        sA += __shfl_xor_sync(0xffffffffu, sA, off);
        sB += __shfl_xor_sync(0xffffffffu, sB, off);
    }
    float muA = sA * (1.f / DMODEL), muB = sB * (1.f / DMODEL);

    float a0 = uA.x - muA, a1 = uA.y - muA, a2 = uA.z - muA, a3 = uA.w - muA;
    float a4 = wA.x - muA, a5 = wA.y - muA, a6 = wA.z - muA, a7 = wA.w - muA;
    float c0 = uB.x - muB, c1 = uB.y - muB, c2 = uB.z - muB, c3 = uB.w - muB;
    float c4 = wB.x - muB, c5 = wB.y - muB, c6 = wB.z - muB, c7 = wB.w - muB;
    float s2A = a0*a0 + a1*a1 + a2*a2 + a3*a3 + a4*a4 + a5*a5 + a6*a6 + a7*a7;
    float s2B = c0*c0 + c1*c1 + c2*c2 + c3*c3 + c4*c4 + c5*c5 + c6*c6 + c7*c7;
#pragma unroll
    for (int off = 16; off; off >>= 1) {
        s2A += __shfl_xor_sync(0xffffffffu, s2A, off);
        s2B += __shfl_xor_sync(0xffffffffu, s2B, off);
    }
    float invA = rsqrtf(s2A * (1.f / DMODEL) + LNEPS);
    float invB = rsqrtf(s2B * (1.f / DMODEL) + LNEPS);

    const float4* gp = (const float4*)g;
    const float4* bp = (const float4*)b;
    float4 g0 = gp[lane * 2], g1 = gp[lane * 2 + 1];
    float4 b0 = bp[lane * 2], b1 = bp[lane * 2 + 1];

    {
        __nv_bfloat162 p0 = __floats2bfloat162_rn(a0 * invA * g0.x + b0.x, a1 * invA * g0.y + b0.y);
        __nv_bfloat162 p1 = __floats2bfloat162_rn(a2 * invA * g0.z + b0.z, a3 * invA * g0.w + b0.w);
        __nv_bfloat162 p2 = __floats2bfloat162_rn(a4 * invA * g1.x + b1.x, a5 * invA * g1.y + b1.y);
        __nv_bfloat162 p3 = __floats2bfloat162_rn(a6 * invA * g1.z + b1.z, a7 * invA * g1.w + b1.w);
        uint4 o;
        o.x = *reinterpret_cast<uint32_t*>(&p0);
        o.y = *reinterpret_cast<uint32_t*>(&p1);
        o.z = *reinterpret_cast<uint32_t*>(&p2);
        o.w = *reinterpret_cast<uint32_t*>(&p3);
        *reinterpret_cast<uint4*>(y + (size_t)row0 * DMODEL + lane * 8) = o;
    }
    {
        __nv_bfloat162 p0 = __floats2bfloat162_rn(c0 * invB * g0.x + b0.x, c1 * invB * g0.y + b0.y);
        __nv_bfloat162 p1 = __floats2bfloat162_rn(c2 * invB * g0.z + b0.z, c3 * invB * g0.w + b0.w);
        __nv_bfloat162 p2 = __floats2bfloat162_rn(c4 * invB * g1.x + b1.x, c5 * invB * g1.y + b1.y);
        __nv_bfloat162 p3 = __floats2bfloat162_rn(c6 * invB * g1.z + b1.z, c7 * invB * g1.w + b1.w);
        uint4 o;
        o.x = *reinterpret_cast<uint32_t*>(&p0);
        o.y = *reinterpret_cast<uint32_t*>(&p1);
        o.z = *reinterpret_cast<uint32_t*>(&p2);
        o.w = *reinterpret_cast<uint32_t*>(&p3);
        *reinterpret_cast<uint4*>(y + (size_t)(row0 + 1) * DMODEL + lane * 8) = o;
    }
}

// ---------------- fused per-head QKV projection, 128 rows/block --------------
// q output pre-scaled by log2(e)/sqrt(DH) for base-2 softmax.
__global__ void qkv_kernel(const bf16* __restrict__ x1,
                           const float* __restrict__ wq, const float* __restrict__ bq,
                           const float* __restrict__ wk, const float* __restrict__ bk,
                           const float* __restrict__ wv, const float* __restrict__ bv,
                           bf16* __restrict__ q, bf16* __restrict__ k, bf16* __restrict__ v)
{
    __shared__ float wqs[32 * 33], wks[32 * 33], wvs[32 * 33];
    __shared__ float bqs[32], bks[32], bvs[32];
    __shared__ float xr[128 * 33];
    const int nh = blockIdx.x;
    const int n = nh / NHEAD, h = nh % NHEAD;
    const int t = threadIdx.x;
    const float* wqg = wq + (size_t)h * DH * DH;
    const float* wkg = wk + (size_t)h * DH * DH;
    const float* wvg = wv + (size_t)h * DH * DH;

    for (int i = t; i < DH * DH; i += 256) {
        int e = i >> 5, d = i & 31;
        wqs[e * 33 + d] = wqg[i];
        wks[e * 33 + d] = wkg[i];
        wvs[e * 33 + d] = wvg[i];
    }
    if (t < 32) { bqs[t] = bq[h * DH + t]; bks[t] = bk[h * DH + t]; bvs[t] = bv[h * DH + t]; }

    const int s0 = blockIdx.y * 128;
    for (int i = t; i < 128 * 32; i += 256) {
        int r = i >> 5, d = i & 31;
        int s = s0 + r;
        xr[r * 33 + d] = (s < SEQ)
            ? __bfloat162float(x1[((size_t)n * SEQ + s) * DMODEL + h * DH + d])
            : 0.f;
    }
    __syncthreads();

    const float scale = 0.17677669529663689f * 1.4426950408889634f;  // log2e/sqrt(32)
    const int wr = (t >> 5) * 16, lane = t & 31;
    const float bqv = bqs[lane], bkv = bks[lane], bvv = bvs[lane];
#pragma unroll 4
    for (int r = 0; r < 16; r++) {
        int s = s0 + wr + r;
        if (s >= SEQ) break;
        const float* xp = xr + (wr + r) * 33;
        float aq = bqv, ak = bkv, av = bvv;
#pragma unroll
        for (int d = 0; d < 32; d++) {
            float xv = xp[d];
            aq += xv * wqs[lane * 33 + d];
            ak += xv * wks[lane * 33 + d];
            av += xv * wvs[lane * 33 + d];
        }
        size_t oidx = ((size_t)nh * SEQ + s) * DH + lane;
        q[oidx] = __float2bfloat16(aq * scale);
        k[oidx] = __float2bfloat16(ak);
        v[oidx] = __float2bfloat16(av);
    }
}

// ---------------- tensor-core flash attention per (n,h), base-2 softmax -----
#define SPAD 224
#define NKT  7
#define KSTR 20
#define VSTR 116

__global__ void __launch_bounds__(224) attn_tc(const bf16* __restrict__ q,
                                               const bf16* __restrict__ k,
                                               const bf16* __restrict__ v,
                                               bf16* __restrict__ o)
{
    __shared__ uint32_t Ks[SPAD * KSTR];
    __shared__ uint32_t VT[32 * VSTR];

    const int nh = blockIdx.x;
    const int n = nh / NHEAD, h = nh % NHEAD;
    const int t = threadIdx.x, warp = t >> 5, lane = t & 31;
    const int g = lane >> 2, q4 = lane & 3;
    const size_t base = (size_t)nh * SEQ * DH;
    const uint32_t* q32 = (const uint32_t*)(q + base);
    const uint32_t* k32 = (const uint32_t*)(k + base);
    const uint32_t* v32 = (const uint32_t*)(v + base);

    for (int i = t; i < SPAD * 16; i += 224) {
        int r = i >> 4, c = i & 15;
        Ks[r * KSTR + c] = (r < SEQ) ? k32[r * 16 + c] : 0u;
    }
    bf16* VT16 = (bf16*)VT;
    for (int i = t; i < SPAD * 16; i += 224) {
        int tt = i >> 4, c = i & 15;
        uint32_t val = (tt < SEQ) ? v32[tt * 16 + c] : 0u;
        __nv_bfloat162 pr = *reinterpret_cast<__nv_bfloat162*>(&val);
        VT16[(2 * c)     * (VSTR * 2) + tt] = pr.x;
        VT16[(2 * c + 1) * (VSTR * 2) + tt] = pr.y;
    }
    __syncthreads();

    const int qbase = warp * 32;
    uint32_t qf[2][2][4];
#pragma unroll
    for (int mi = 0; mi < 2; mi++) {
        int r0 = qbase + mi * 16 + g, r1 = r0 + 8;
        bool v0 = r0 < SEQ, v1 = r1 < SEQ;
#pragma unroll
        for (int ks = 0; ks < 2; ks++) {
            qf[mi][ks][0] = v0 ? q32[r0 * 16 + ks * 8 + q4]     : 0u;
            qf[mi][ks][1] = v1 ? q32[r1 * 16 + ks * 8 + q4]     : 0u;
            qf[mi][ks][2] = v0 ? q32[r0 * 16 + ks * 8 + q4 + 4] : 0u;
            qf[mi][ks][3] = v1 ? q32[r1 * 16 + ks * 8 + q4 + 4] : 0u;
        }
    }

    float Oa[2][4][4];
#pragma unroll
    for (int mi = 0; mi < 2; mi++)
#pragma unroll
        for (int ne = 0; ne < 4; ne++)
#pragma unroll
            for (int e = 0; e < 4; e++) Oa[mi][ne][e] = 0.f;
    float m_[2][2] = {{-1e30f, -1e30f}, {-1e30f, -1e30f}};
    float l_[2][2] = {{0.f, 0.f}, {0.f, 0.f}};

    auto body = [&](int kt, bool last_mask) {
        float sc[2][4][4];
#pragma unroll
        for (int mi = 0; mi < 2; mi++)
#pragma unroll
            for (int ni = 0; ni < 4; ni++)
#pragma unroll
                for (int e = 0; e < 4; e++) sc[mi][ni][e] = 0.f;

        uint32_t kf[2][4][2];
#pragma unroll
        for (int ks = 0; ks < 2; ks++)
#pragma unroll
            for (int ni = 0; ni < 4; ni++) {
                int r = kt * 32 + ni * 8 + g;
                kf[ks][ni][0] = Ks[r * KSTR + ks * 8 + q4];
                kf[ks][ni][1] = Ks[r * KSTR + ks * 8 + q4 + 4];
            }
#pragma unroll
        for (int mi = 0; mi < 2; mi++)
#pragma unroll
            for (int ni = 0; ni < 4; ni++)
#pragma unroll
                for (int ks = 0; ks < 2; ks++)
                    mma_bf16(sc[mi][ni], qf[mi][ks], kf[ks][ni]);

        if (last_mask) {
#pragma unroll
            for (int mi = 0; mi < 2; mi++)
#pragma unroll
                for (int ni = 0; ni < 4; ni++) {
                    int col = kt * 32 + ni * 8 + q4 * 2;
#pragma unroll
                    for (int hf = 0; hf < 2; hf++) {
                        if (col     >= SEQ) sc[mi][ni][hf * 2]     = -1e30f;
                        if (col + 1 >= SEQ) sc[mi][ni][hf * 2 + 1] = -1e30f;
                    }
                }
        }

#pragma unroll
        for (int mi = 0; mi < 2; mi++) {
#pragma unroll
            for (int hf = 0; hf < 2; hf++) {
                float mx = fmaxf(fmaxf(sc[mi][0][hf * 2], sc[mi][0][hf * 2 + 1]),
                                 fmaxf(sc[mi][1][hf * 2], sc[mi][1][hf * 2 + 1]));
                mx = fmaxf(mx, fmaxf(fmaxf(sc[mi][2][hf * 2], sc[mi][2][hf * 2 + 1]),
                                     fmaxf(sc[mi][3][hf * 2], sc[mi][3][hf * 2 + 1])));
                mx = fmaxf(mx, __shfl_xor_sync(0xffffffffu, mx, 1));
                mx = fmaxf(mx, __shfl_xor_sync(0xffffffffu, mx, 2));
                float mnew = fmaxf(m_[mi][hf], mx);
                float f = ex2f(m_[mi][hf] - mnew);   // base-2 domain
                m_[mi][hf] = mnew;
                float rs = 0.f;
#pragma unroll
                for (int ni = 0; ni < 4; ni++) {
                    float p0 = ex2f(sc[mi][ni][hf * 2]     - mnew);
                    float p1 = ex2f(sc[mi][ni][hf * 2 + 1] - mnew);
                    sc[mi][ni][hf * 2]     = p0;
                    sc[mi][ni][hf * 2 + 1] = p1;
                    rs += p0 + p1;
                }
                rs += __shfl_xor_sync(0xffffffffu, rs, 1);
                rs += __shfl_xor_sync(0xffffffffu, rs, 2);
                l_[mi][hf] = l_[mi][hf] * f + rs;
#pragma unroll
                for (int ne = 0; ne < 4; ne++) {
                    Oa[mi][ne][hf * 2]     *= f;
                    Oa[mi][ne][hf * 2 + 1] *= f;
                }
            }
        }

        uint32_t pa[2][2][4];
#pragma unroll
        for (int mi = 0; mi < 2; mi++)
#pragma unroll
            for (int ks = 0; ks < 2; ks++) {
                __nv_bfloat162 t0 = __floats2bfloat162_rn(sc[mi][2 * ks][0],     sc[mi][2 * ks][1]);
                __nv_bfloat162 t1 = __floats2bfloat162_rn(sc[mi][2 * ks][2],     sc[mi][2 * ks][3]);
                __nv_bfloat162 t2 = __floats2bfloat162_rn(sc[mi][2 * ks + 1][0], sc[mi][2 * ks + 1][1]);
                __nv_bfloat162 t3 = __floats2bfloat162_rn(sc[mi][2 * ks + 1][2], sc[mi][2 * ks + 1][3]);
                pa[mi][ks][0] = *reinterpret_cast<uint32_t*>(&t0);
                pa[mi][ks][1] = *reinterpret_cast<uint32_t*>(&t1);
                pa[mi][ks][2] = *reinterpret_cast<uint32_t*>(&t2);
                pa[mi][ks][3] = *reinterpret_cast<uint32_t*>(&t3);
            }

        uint32_t vf[2][4][2];
#pragma unroll
        for (int ks = 0; ks < 2; ks++)
#pragma unroll
            for (int ne = 0; ne < 4; ne++) {
                int r = ne * 8 + g;
                int cu = kt * 16 + ks * 8 + q4;
                vf[ks][ne][0] = VT[r * VSTR + cu];
                vf[ks][ne][1] = VT[r * VSTR + cu + 4];
            }
#pragma unroll
        for (int mi = 0; mi < 2; mi++)
#pragma unroll
            for (int ne = 0; ne < 4; ne++)
#pragma unroll
                for (int ks = 0; ks < 2; ks++)
                    mma_bf16(Oa[mi][ne], pa[mi][ks], vf[ks][ne]);
    };

    for (int kt = 0; kt < NKT - 1; kt++) body(kt, false);
    body(NKT - 1, true);

#pragma unroll
    for (int mi = 0; mi < 2; mi++) {
#pragma unroll
        for (int hf = 0; hf < 2; hf++) {
            int row = qbase + mi * 16 + hf * 8 + g;
            if (row >= SEQ) continue;
            float inv = 1.f / l_[mi][hf];
            bf16* op = o + ((size_t)n * SEQ + row) * DMODEL + h * DH;
#pragma unroll
            for (int ne = 0; ne < 4; ne++) {
                __nv_bfloat162 p = __floats2bfloat162_rn(Oa[mi][ne][hf * 2] * inv,
                                                         Oa[mi][ne][hf * 2 + 1] * inv);
                *reinterpret_cast<uint32_t*>(op + ne * 8 + q4 * 2) = *reinterpret_cast<uint32_t*>(&p);
            }
        }
    }
}

// ---------------- softmax over precomputed logits ---------------------------
__global__ void softmax_head_kernel(const float* __restrict__ logits_in,
                                    float* __restrict__ out)
{
    __shared__ float logits[OUTC];
    __shared__ float red[8];
    const int n = blockIdx.x;
    const int t = threadIdx.x, wid = t >> 5, lane = t & 31;

    for (int j = t; j < OUTC; j += 256) logits[j] = logits_in[(size_t)n * OUTP + j];
    __syncthreads();

    float mx = -1e30f;
    for (int j = t; j < OUTC; j += 256) mx = fmaxf(mx, logits[j]);
#pragma unroll
    for (int off = 16; off; off >>= 1) mx = fmaxf(mx, __shfl_xor_sync(0xffffffffu, mx, off));
    if (lane == 0) red[wid] = mx;
    __syncthreads();
    float bm = -1e30f;
#pragma unroll
    for (int i = 0; i < 8; i++) bm = fmaxf(bm, red[i]);
    __syncthreads();

    float sum = 0.f;
    for (int j = t; j < OUTC; j += 256) {
        float e = __expf(logits[j] - bm);
        logits[j] = e;
        sum += e;
    }
#pragma unroll
    for (int off = 16; off; off >>= 1) sum += __shfl_xor_sync(0xffffffffu, sum, off);
    if (lane == 0) red[wid] = sum;
    __syncthreads();
    float bs = 0.f;
#pragma unroll
    for (int i = 0; i < 8; i++) bs += red[i];
    float inv = 1.f / bs;
    __syncthreads();
    for (int j = t; j < OUTC; j += 256) out[(size_t)n * OUTC + j] = logits[j] * inv;
}

// ---------------- launcher ----------------
extern "C" void kernel_launch(void* const* d_in, const int* in_sizes, int n_in,
                              void* d_out, int out_size)
{
    const float* images  = (const float*)d_in[0];
    const float* w_map   = (const float*)d_in[1];
    const float* b_map   = (const float*)d_in[2];
    const float* cls_tok = (const float*)d_in[3];
    const float* norm1_g = (const float*)d_in[4];
    const float* norm1_b = (const float*)d_in[5];
    const float* wq      = (const float*)d_in[6];
    const float* bq      = (const float*)d_in[7];
    const float* wk      = (const float*)d_in[8];
    const float* bk      = (const float*)d_in[9];
    const float* wv      = (const float*)d_in[10];
    const float* bv      = (const float*)d_in[11];
    const float* w_last  = (const float*)d_in[12];
    const float* b_last  = (const float*)d_in[13];
    const float* norm2_g = (const float*)d_in[14];
    const float* norm2_b = (const float*)d_in[15];
    const float* w_mlp1  = (const float*)d_in[16];
    const float* b_mlp1  = (const float*)d_in[17];
    const float* w_mlp2  = (const float*)d_in[18];
    const float* b_mlp2  = (const float*)d_in[19];
    const float* w_out   = (const float*)d_in[20];
    const float* b_out   = (const float*)d_in[21];
    float* out = (float*)d_out;

    bf16 *patches, *x1b, *qb, *kb, *vb, *ob, *h1b;
    bf16 *wmapb, *wlastb, *wmlp1b, *wmlp2b, *whi, *wlo, *chi, *clo;
    float *X, *pe, *bout_pad, *bzero, *logits;
    cudaGetSymbolAddress((void**)&patches, g_patches_b);
    cudaGetSymbolAddress((void**)&X,   g_X);
    cudaGetSymbolAddress((void**)&x1b, g_x1b);
    cudaGetSymbolAddress((void**)&qb,  g_qb);
    cudaGetSymbolAddress((void**)&kb,  g_kb);
    cudaGetSymbolAddress((void**)&vb,  g_vb);
    cudaGetSymbolAddress((void**)&ob,  g_ob);
    cudaGetSymbolAddress((void**)&h1b, g_h1b);
    cudaGetSymbolAddress((void**)&pe,  g_pe);
    cudaGetSymbolAddress((void**)&wmapb,  g_wmapb);
    cudaGetSymbolAddress((void**)&wlastb, g_wlastb);
    cudaGetSymbolAddress((void**)&wmlp1b, g_wmlp1b);
    cudaGetSymbolAddress((void**)&wmlp2b, g_wmlp2b);
    cudaGetSymbolAddress((void**)&whi, g_wout_hi);
    cudaGetSymbolAddress((void**)&wlo, g_wout_lo);
    cudaGetSymbolAddress((void**)&chi, g_cls_hi);
    cudaGetSymbolAddress((void**)&clo, g_cls_lo);
    cudaGetSymbolAddress((void**)&bout_pad, g_bout_pad);
    cudaGetSymbolAddress((void**)&bzero,    g_bzero);
    cudaGetSymbolAddress((void**)&logits,   g_logits);

    cudaFuncSetAttribute(gemm_bf<0, false, false, true >, cudaFuncAttributeMaxDynamicSharedMemorySize, GEMM_SMEM);
    cudaFuncSetAttribute(gemm_bf<0, true,  false, false>, cudaFuncAttributeMaxDynamicSharedMemorySize, GEMM_SMEM);
    cudaFuncSetAttribute(gemm_bf<1, false, true,  false>, cudaFuncAttributeMaxDynamicSharedMemorySize, GEMM_SMEM);
    cudaFuncSetAttribute(gemm_bf<0, false, false, false>, cudaFuncAttributeMaxDynamicSharedMemorySize, GEMM_SMEM);

    // 0) weight conversion to bf16 (+ padded hi/lo head weights)
    {
        int n0 = DMODEL * IN_D;
        int n1 = NLAYER * DMODEL * DMODEL;
        int n3 = NLAYER * 4 * DMODEL * DMODEL;
        int totf4 = (n0 + n1 + 2 * n3) / 4;
        cvt_all_kernel<<<(totf4 + 255) / 256, 256>>>(
            w_map, wmapb, n0, w_last, wlastb, n1,
            w_mlp1, wmlp1b, n3, w_mlp2, wmlp2b, n3);
        int hw = OUTP * DMODEL / 4;
        cvt_head_kernel<<<(hw + 255) / 256, 256>>>(w_out, b_out, whi, wlo, bout_pad, bzero);
    }

    // 1) patches + PE table
    {
        int tot = BATCH * NP * IN_D / 4;
        patch_kernel<<<(tot + 255) / 256, 256>>>(images, patches);
        int pt = SEQ * DMODEL;
        pe_kernel<<<(pt + 255) / 256, 256>>>(pe);
    }

    // 2) patch-embed GEMM fused with assemble
    gemm_bf<0, false, false, true><<<dim3(DMODEL / 128, (BATCH * NP) / 128), 256, GEMM_SMEM>>>(
        patches, wmapb, b_map, nullptr, pe, X, BATCH * NP, DMODEL, IN_D);

    // 2b) cls rows
    cls_kernel<<<(BATCH * DMODEL + 255) / 256, 256>>>(cls_tok, pe, X);

    const int MROWS = BATCH * SEQ;   // 25216 = 16*1576

    for (int l = 0; l < NLAYER; l++) {
        ln_kernel<<<MROWS / 16, 256>>>(X, norm1_g + l * DMODEL, norm1_b + l * DMODEL, x1b);

        qkv_kernel<<<dim3(BATCH * NHEAD, 2), 256>>>(
            x1b,
            wq + (size_t)l * NHEAD * DH * DH, bq + (size_t)l * NHEAD * DH,
            wk + (size_t)l * NHEAD * DH * DH, bk + (size_t)l * NHEAD * DH,
            wv + (size_t)l * NHEAD * DH * DH, bv + (size_t)l * NHEAD * DH,
            qb, kb, vb);

        attn_tc<<<BATCH * NHEAD, 224>>>(qb, kb, vb, ob);

        gemm_bf<0, true, false, false><<<dim3(DMODEL / 128, MROWS / 128), 256, GEMM_SMEM>>>(
            ob, wlastb + (size_t)l * DMODEL * DMODEL, b_last + l * DMODEL, X, nullptr, X,
            MROWS, DMODEL, DMODEL);

        ln_kernel<<<MROWS / 16, 256>>>(X, norm2_g + l * DMODEL, norm2_b + l * DMODEL, x1b);

        gemm_bf<1, false, true, false><<<dim3((4 * DMODEL) / 128, MROWS / 128), 256, GEMM_SMEM>>>(
            x1b, wmlp1b + (size_t)l * 4 * DMODEL * DMODEL, b_mlp1 + l * 4 * DMODEL,
            nullptr, nullptr, h1b, MROWS, 4 * DMODEL, DMODEL);

        gemm_bf<0, true, false, false><<<dim3(DMODEL / 128, MROWS / 128), 256, GEMM_SMEM>>>(
            h1b, wmlp2b + (size_t)l * 4 * DMODEL * DMODEL, b_mlp2 + l * DMODEL, X, nullptr, X,
            MROWS, DMODEL, 4 * DMODEL);
    }

    // head: cls hi/lo extraction -> 3-term compensated bf16 GEMM -> softmax
    cls_extract_kernel<<<(BATCH * DMODEL / 4 + 255) / 256, 256>>>(X, chi, clo);
    gemm_bf<0, false, false, false><<<dim3(OUTP / 128, BATCH / 128), 256, GEMM_SMEM>>>(
        chi, whi, bout_pad, nullptr, nullptr, logits, BATCH, OUTP, DMODEL);
    gemm_bf<0, true, false, false><<<dim3(OUTP / 128, BATCH / 128), 256, GEMM_SMEM>>>(
        chi, wlo, bzero, logits, nullptr, logits, BATCH, OUTP, DMODEL);
    gemm_bf<0, true, false, false><<<dim3(OUTP / 128, BATCH / 128), 256, GEMM_SMEM>>>(
        clo, whi, bzero, logits, nullptr, logits, BATCH, OUTP, DMODEL);
    softmax_head_kernel<<<BATCH, 256>>>(logits, out);
}

// round 15
// speedup vs baseline: 1.5638x; 1.0550x over previous
#include <cuda_runtime.h>
#include <cuda_bf16.h>
#include <math.h>
#include <stdint.h>

// ---------------- problem constants ----------------
#define BATCH 128
#define CH    3
#define HIM   224
#define PGRID 14
#define NP    196
#define PATCH 16
#define IN_D  768
#define DMODEL 256
#define NHEAD 8
#define DH    32
#define NLAYER 4
#define SEQ   197
#define OUTC  1000
#define OUTP  1024
#define HKDIM 768            // head GEMM K = 3*DMODEL
#define LNEPS 1e-5f

typedef __nv_bfloat16 bf16;

// ---------------- scratch (device globals) ----------------
__device__ bf16  g_patches_b[BATCH * NP * IN_D];
__device__ float g_X [BATCH * SEQ * DMODEL];
__device__ bf16  g_x1b[BATCH * SEQ * DMODEL];
__device__ bf16  g_qb [BATCH * SEQ * DMODEL];             // [n,h,s,e] (pre-scaled by scale*log2e)
__device__ bf16  g_kb [BATCH * SEQ * DMODEL];
__device__ bf16  g_vb [BATCH * SEQ * DMODEL];
__device__ bf16  g_ob [BATCH * SEQ * DMODEL];             // [n,s,d]
__device__ bf16  g_h1b[BATCH * SEQ * 4 * DMODEL];
__device__ float g_pe[SEQ * DMODEL];
__device__ bf16  g_wmapb [DMODEL * IN_D];
__device__ bf16  g_wlastb[NLAYER * DMODEL * DMODEL];
__device__ bf16  g_wmlp1b[NLAYER * 4 * DMODEL * DMODEL];
__device__ bf16  g_wmlp2b[NLAYER * 4 * DMODEL * DMODEL];
__device__ bf16  g_wout_cat[OUTP * HKDIM];                // [whi | wlo | whi]
__device__ float g_bout_pad[OUTP];
__device__ bf16  g_cls_cat[BATCH * HKDIM];                // [chi | chi | clo]
__device__ float g_logits[BATCH * OUTP];

__device__ __forceinline__ float ex2f(float x)
{
    float r;
    asm("ex2.approx.f32 %0, %1;" : "=f"(r) : "f"(x));
    return r;
}

// ---------------- fp32 -> bf16 convert, all weights in one launch ----------
__device__ __forceinline__ void cvt4(const float* __restrict__ s, bf16* __restrict__ d, int i)
{
    float4 v = *(const float4*)(s + i);
    __nv_bfloat162 p0 = __floats2bfloat162_rn(v.x, v.y);
    __nv_bfloat162 p1 = __floats2bfloat162_rn(v.z, v.w);
    uint2 o;
    o.x = *reinterpret_cast<uint32_t*>(&p0);
    o.y = *reinterpret_cast<uint32_t*>(&p1);
    *reinterpret_cast<uint2*>(d + i) = o;
}

__global__ void cvt_all_kernel(const float* __restrict__ s0, bf16* __restrict__ d0, int n0,
                               const float* __restrict__ s1, bf16* __restrict__ d1, int n1,
                               const float* __restrict__ s2, bf16* __restrict__ d2, int n2,
                               const float* __restrict__ s3, bf16* __restrict__ d3, int n3)
{
    int i = (blockIdx.x * 256 + threadIdx.x) * 4;
    if (i < n0) { cvt4(s0, d0, i); return; }
    i -= n0;
    if (i < n1) { cvt4(s1, d1, i); return; }
    i -= n1;
    if (i < n2) { cvt4(s2, d2, i); return; }
    i -= n2;
    if (i < n3) { cvt4(s3, d3, i); return; }
}

// ---------------- head weight: pad + hi/lo split -> concat [whi|wlo|whi] ----
__global__ void cvt_head_kernel(const float* __restrict__ w_out, const float* __restrict__ b_out,
                                bf16* __restrict__ wcat, float* __restrict__ bpad)
{
    int tid = blockIdx.x * 256 + threadIdx.x;
    int i = tid * 4;                         // index into [OUTP x DMODEL]
    if (i < OUTP * DMODEL) {
        int row = i / DMODEL, col = i % DMODEL;
        bf16* wr = wcat + (size_t)row * HKDIM;
        if (row < OUTC) {
            float4 v = *(const float4*)(w_out + i);
            bf16 h0 = __float2bfloat16(v.x), h1 = __float2bfloat16(v.y);
            bf16 h2 = __float2bfloat16(v.z), h3 = __float2bfloat16(v.w);
            bf16 l0 = __float2bfloat16(v.x - __bfloat162float(h0));
            bf16 l1 = __float2bfloat16(v.y - __bfloat162float(h1));
            bf16 l2 = __float2bfloat16(v.z - __bfloat162float(h2));
            bf16 l3 = __float2bfloat16(v.w - __bfloat162float(h3));
            wr[col]     = h0; wr[col + 1] = h1; wr[col + 2] = h2; wr[col + 3] = h3;
            wr[DMODEL + col]     = l0; wr[DMODEL + col + 1] = l1;
            wr[DMODEL + col + 2] = l2; wr[DMODEL + col + 3] = l3;
            wr[2 * DMODEL + col]     = h0; wr[2 * DMODEL + col + 1] = h1;
            wr[2 * DMODEL + col + 2] = h2; wr[2 * DMODEL + col + 3] = h3;
        } else {
            uint2 z = {0u, 0u};
            *reinterpret_cast<uint2*>(wr + col) = z;
            *reinterpret_cast<uint2*>(wr + DMODEL + col) = z;
            *reinterpret_cast<uint2*>(wr + 2 * DMODEL + col) = z;
        }
    }
    if (tid < OUTP) bpad[tid] = (tid < OUTC) ? b_out[tid] : 0.f;
}

// ---------------- cls row extraction -> concat [chi|chi|clo] ----------------
__global__ void cls_extract_kernel(const float* __restrict__ X, bf16* __restrict__ ccat)
{
    int i = (blockIdx.x * 256 + threadIdx.x) * 4;
    if (i >= BATCH * DMODEL) return;
    int n = i / DMODEL, d = i % DMODEL;
    float4 v = *(const float4*)(X + (size_t)n * SEQ * DMODEL + d);
    bf16 h0 = __float2bfloat16(v.x), h1 = __float2bfloat16(v.y);
    bf16 h2 = __float2bfloat16(v.z), h3 = __float2bfloat16(v.w);
    bf16 l0 = __float2bfloat16(v.x - __bfloat162float(h0));
    bf16 l1 = __float2bfloat16(v.y - __bfloat162float(h1));
    bf16 l2 = __float2bfloat16(v.z - __bfloat162float(h2));
    bf16 l3 = __float2bfloat16(v.w - __bfloat162float(h3));
    bf16* cr = ccat + (size_t)n * HKDIM;
    cr[d]     = h0; cr[d + 1] = h1; cr[d + 2] = h2; cr[d + 3] = h3;
    cr[DMODEL + d]     = h0; cr[DMODEL + d + 1] = h1;
    cr[DMODEL + d + 2] = h2; cr[DMODEL + d + 3] = h3;
    cr[2 * DMODEL + d]     = l0; cr[2 * DMODEL + d + 1] = l1;
    cr[2 * DMODEL + d + 2] = l2; cr[2 * DMODEL + d + 3] = l3;
}

// ---------------- patch extraction (float4 gather, writes bf16) ------------
__global__ void patch_kernel(const float* __restrict__ img, bf16* __restrict__ out)
{
    int tid = blockIdx.x * 256 + threadIdx.x;
    int idx = tid * 4;
    if (idx >= BATCH * NP * IN_D) return;
    int i = idx % IN_D;
    int p = (idx / IN_D) % NP;
    int n = idx / (IN_D * NP);
    int c   = i >> 8;
    int r   = (i >> 4) & 15;
    int col = i & 15;
    int py = p / PGRID, px = p % PGRID;
    float4 v = *(const float4*)(img + (((size_t)n * CH + c) * HIM + py * PATCH + r) * HIM
                                    + px * PATCH + col);
    __nv_bfloat162 p0 = __floats2bfloat162_rn(v.x, v.y);
    __nv_bfloat162 p1 = __floats2bfloat162_rn(v.z, v.w);
    uint2 o;
    o.x = *reinterpret_cast<uint32_t*>(&p0);
    o.y = *reinterpret_cast<uint32_t*>(&p1);
    *reinterpret_cast<uint2*>(out + idx) = o;
}

// ---------------- positional encoding (fp32) ----------------
__global__ void pe_kernel(float* __restrict__ pe)
{
    int i = blockIdx.x * 256 + threadIdx.x;
    if (i >= SEQ * DMODEL) return;
    int s = i / DMODEL, d = i % DMODEL;
    float expo = (float)(2 * (d / 2)) * (1.0f / DMODEL);
    float ang  = (float)s * powf(10000.0f, -expo);
    pe[i] = (d & 1) ? cosf(ang) : sinf(ang);
}

// ---------------- cls rows: X[n][0][:] = cls + pe[0] ------------------------
__global__ void cls_kernel(const float* __restrict__ cls,
                           const float* __restrict__ pe,
                           float* __restrict__ X)
{
    int i = blockIdx.x * 256 + threadIdx.x;
    if (i >= BATCH * DMODEL) return;
    int d = i % DMODEL;
    int n = i / DMODEL;
    X[(size_t)n * SEQ * DMODEL + d] = cls[d] + pe[d];
}

// ---------------- bf16 MMA / ldmatrix helpers -------------------------------
__device__ __forceinline__ void mma_bf16(float* c, const uint32_t* a, const uint32_t* b)
{
    asm volatile(
        "mma.sync.aligned.m16n8k16.row.col.f32.bf16.bf16.f32 "
        "{%0,%1,%2,%3}, {%4,%5,%6,%7}, {%8,%9}, {%0,%1,%2,%3};"
        : "+f"(c[0]), "+f"(c[1]), "+f"(c[2]), "+f"(c[3])
        : "r"(a[0]), "r"(a[1]), "r"(a[2]), "r"(a[3]), "r"(b[0]), "r"(b[1]));
}

#define LDSM4(r0, r1, r2, r3, addr) \
    asm volatile("ldmatrix.sync.aligned.m8n8.x4.shared.b16 {%0,%1,%2,%3}, [%4];" \
                 : "=r"(r0), "=r"(r1), "=r"(r2), "=r"(r3) : "r"(addr))

#define CP16(dst, src) asm volatile("cp.async.cg.shared.global [%0], [%1], 16;\n" :: "r"(dst), "l"(src))
#define CP_COMMIT()    asm volatile("cp.async.commit_group;\n" ::)
#define CP_WAIT1()     asm volatile("cp.async.wait_group 1;\n" ::)
#define CP_WAIT0()     asm volatile("cp.async.wait_group 0;\n" ::)

// ---------------- bf16 tensor-core GEMM, 128x128 tile (frozen config) -------
#define STR 36
#define ABUF (128 * STR)
#define GEMM_SMEM (4 * ABUF * 4)

template<int ACT, bool HASRES, bool OUTBF, bool ADDPE>
__global__ void __launch_bounds__(256) gemm_bf(const bf16* __restrict__ A,
                                               const bf16* __restrict__ W,
                                               const float* __restrict__ bias,
                                               const float* __restrict__ res,
                                               const float* __restrict__ pe,
                                               void* __restrict__ Cout,
                                               int M, int N, int K)
{
    extern __shared__ uint32_t sm_[];
    const uint32_t smem_byte = (uint32_t)__cvta_generic_to_shared(sm_);

    const int t    = threadIdx.x;
    const int warp = t >> 5, lane = t & 31;
    const int g    = lane >> 2, q4 = lane & 3;
    const int warp_m = (warp >> 1) * 32;
    const int warp_n = (warp & 1) * 64;
    const int row0 = blockIdx.y * 128, col0 = blockIdx.x * 128;

    float acc[2][8][4];
#pragma unroll
    for (int mi = 0; mi < 2; mi++)
#pragma unroll
        for (int ni = 0; ni < 8; ni++)
#pragma unroll
            for (int e = 0; e < 4; e++) acc[mi][ni][e] = 0.f;

    auto stage = [&](int k0, int buf) {
        uint32_t abase = smem_byte + buf * (ABUF * 4);
        uint32_t bbase = smem_byte + (2 + buf) * (ABUF * 4);
#pragma unroll
        for (int i = 0; i < 4; i++) {
            int c = t + i * 256;
            int r = c >> 3, co = c & 7;
            CP16(abase + (r * STR + co * 4) * 4, A + (size_t)(row0 + r) * K + k0 + co * 8);
            CP16(bbase + (r * STR + co * 4) * 4, W + (size_t)(col0 + r) * K + k0 + co * 8);
        }
        CP_COMMIT();
    };

    uint32_t a_addr[2][2], b_addr[2][4];
    {
        int ar = warp_m + (lane & 15);
        int ab = (lane >> 4) * 16;
        int br = warp_n + ((lane >> 4) & 1) * 8 + (lane & 7);
        int bb = ((lane >> 3) & 1) * 16;
#pragma unroll
        for (int buf = 0; buf < 2; buf++) {
            uint32_t abase = smem_byte + buf * (ABUF * 4);
            uint32_t bbase = smem_byte + (2 + buf) * (ABUF * 4);
#pragma unroll
            for (int mi = 0; mi < 2; mi++)
                a_addr[buf][mi] = abase + (ar + mi * 16) * (STR * 4) + ab;
#pragma unroll
            for (int nj = 0; nj < 4; nj++)
                b_addr[buf][nj] = bbase + (br + nj * 16) * (STR * 4) + bb;
        }
    }

    const int KT = K >> 6;
    stage(0, 0);

    for (int kt = 0; kt < KT; kt++) {
        const int cur = kt & 1;
        if (kt + 1 < KT) { stage((kt + 1) << 6, cur ^ 1); CP_WAIT1(); }
        else             { CP_WAIT0(); }
        __syncthreads();

#pragma unroll
        for (int ks = 0; ks < 4; ks++) {
            const uint32_t kb = ks * 32;
            uint32_t af[2][4];
            LDSM4(af[0][0], af[0][1], af[0][2], af[0][3], a_addr[cur][0] + kb);
            LDSM4(af[1][0], af[1][1], af[1][2], af[1][3], a_addr[cur][1] + kb);
            uint32_t bf_[8][2];
#pragma unroll
            for (int nj = 0; nj < 4; nj++)
                LDSM4(bf_[2 * nj][0], bf_[2 * nj][1], bf_[2 * nj + 1][0], bf_[2 * nj + 1][1],
                      b_addr[cur][nj] + kb);
#pragma unroll
            for (int mi = 0; mi < 2; mi++)
#pragma unroll
                for (int ni = 0; ni < 8; ni++)
                    mma_bf16(acc[mi][ni], af[mi], bf_[ni]);
        }
        __syncthreads();
    }

#pragma unroll
    for (int mi = 0; mi < 2; mi++) {
        int ra = row0 + warp_m + mi * 16 + g;
        int rb = ra + 8;
        size_t orow_a, orow_b;
        if (ADDPE) {
            orow_a = (size_t)(ra / NP) * SEQ + (ra % NP) + 1;
            orow_b = (size_t)(rb / NP) * SEQ + (rb % NP) + 1;
        } else {
            orow_a = ra; orow_b = rb;
        }
        int pes_a = ADDPE ? ((ra % NP) + 1) : 0;
        int pes_b = ADDPE ? ((rb % NP) + 1) : 0;
#pragma unroll
        for (int ni = 0; ni < 8; ni++) {
            int col = col0 + warp_n + ni * 8 + q4 * 2;
            float b0 = bias[col], b1 = bias[col + 1];
            float v00 = acc[mi][ni][0] + b0, v01 = acc[mi][ni][1] + b1;
            float v10 = acc[mi][ni][2] + b0, v11 = acc[mi][ni][3] + b1;
            if (ACT == 1) {
                v00 = 0.5f * v00 * (1.0f + erff(v00 * 0.70710678118654752f));
                v01 = 0.5f * v01 * (1.0f + erff(v01 * 0.70710678118654752f));
                v10 = 0.5f * v10 * (1.0f + erff(v10 * 0.70710678118654752f));
                v11 = 0.5f * v11 * (1.0f + erff(v11 * 0.70710678118654752f));
            }
            if (HASRES) {
                float2 r0 = *(const float2*)(res + orow_a * N + col);
                float2 r1 = *(const float2*)(res + orow_b * N + col);
                v00 += r0.x; v01 += r0.y; v10 += r1.x; v11 += r1.y;
            }
            if (ADDPE) {
                float2 p0 = *(const float2*)(pe + (size_t)pes_a * DMODEL + col);
                float2 p1 = *(const float2*)(pe + (size_t)pes_b * DMODEL + col);
                v00 += p0.x; v01 += p0.y; v10 += p1.x; v11 += p1.y;
            }
            if (OUTBF) {
                bf16* C = (bf16*)Cout;
                __nv_bfloat162 p0 = __floats2bfloat162_rn(v00, v01);
                __nv_bfloat162 p1 = __floats2bfloat162_rn(v10, v11);
                *reinterpret_cast<uint32_t*>(C + orow_a * N + col) = *reinterpret_cast<uint32_t*>(&p0);
                *reinterpret_cast<uint32_t*>(C + orow_b * N + col) = *reinterpret_cast<uint32_t*>(&p1);
            } else {
                float* C = (float*)Cout;
                *(float2*)(C + orow_a * N + col) = make_float2(v00, v01);
                *(float2*)(C + orow_b * N + col) = make_float2(v10, v11);
            }
        }
    }
}

// ---------------- LayerNorm: 2 rows per warp, bf16 out ----------------------
__global__ void ln_kernel(const float* __restrict__ x,
                          const float* __restrict__ g,
                          const float* __restrict__ b,
                          bf16* __restrict__ y)
{
    const int warp = threadIdx.x >> 5, lane = threadIdx.x & 31;
    const int row0 = blockIdx.x * 16 + warp * 2;

    const float4* xpA = (const float4*)(x + (size_t)row0 * DMODEL);
    const float4* xpB = (const float4*)(x + (size_t)(row0 + 1) * DMODEL);
    float4 uA = xpA[lane * 2], wA = xpA[lane * 2 + 1];
    float4 uB = xpB[lane * 2], wB = xpB[lane * 2 + 1];

    float sA = uA.x + uA.y + uA.z + uA.w + wA.x + wA.y + wA.z + wA.w;
    float sB = uB.x + uB.y + uB.z + uB.w + wB.x + wB.y + wB.z + wB.w;
#pragma unroll
    for (int off = 16; off; off >>= 1) {
        sA += __shfl_xor_sync(0xffffffffu, sA, off);
        sB += __shfl_xor_sync(0xffffffffu, sB, off);
    }
    float muA = sA * (1.f / DMODEL), muB = sB * (1.f / DMODEL);

    float a0 = uA.x - muA, a1 = uA.y - muA, a2 = uA.z - muA, a3 = uA.w - muA;
    float a4 = wA.x - muA, a5 = wA.y - muA, a6 = wA.z - muA, a7 = wA.w - muA;
    float c0 = uB.x - muB, c1 = uB.y - muB, c2 = uB.z - muB, c3 = uB.w - muB;
    float c4 = wB.x - muB, c5 = wB.y - muB, c6 = wB.z - muB, c7 = wB.w - muB;
    float s2A = a0*a0 + a1*a1 + a2*a2 + a3*a3 + a4*a4 + a5*a5 + a6*a6 + a7*a7;
    float s2B = c0*c0 + c1*c1 + c2*c2 + c3*c3 + c4*c4 + c5*c5 + c6*c6 + c7*c7;
#pragma unroll
    for (int off = 16; off; off >>= 1) {
        s2A += __shfl_xor_sync(0xffffffffu, s2A, off);
        s2B += __shfl_xor_sync(0xffffffffu, s2B, off);
    }
    float invA = rsqrtf(s2A * (1.f / DMODEL) + LNEPS);
    float invB = rsqrtf(s2B * (1.f / DMODEL) + LNEPS);

    const float4* gp = (const float4*)g;
    const float4* bp = (const float4*)b;
    float4 g0 = gp[lane * 2], g1 = gp[lane * 2 + 1];
    float4 b0 = bp[lane * 2], b1 = bp[lane * 2 + 1];

    {
        __nv_bfloat162 p0 = __floats2bfloat162_rn(a0 * invA * g0.x + b0.x, a1 * invA * g0.y + b0.y);
        __nv_bfloat162 p1 = __floats2bfloat162_rn(a2 * invA * g0.z + b0.z, a3 * invA * g0.w + b0.w);
        __nv_bfloat162 p2 = __floats2bfloat162_rn(a4 * invA * g1.x + b1.x, a5 * invA * g1.y + b1.y);
        __nv_bfloat162 p3 = __floats2bfloat162_rn(a6 * invA * g1.z + b1.z, a7 * invA * g1.w + b1.w);
        uint4 o;
        o.x = *reinterpret_cast<uint32_t*>(&p0);
        o.y = *reinterpret_cast<uint32_t*>(&p1);
        o.z = *reinterpret_cast<uint32_t*>(&p2);
        o.w = *reinterpret_cast<uint32_t*>(&p3);
        *reinterpret_cast<uint4*>(y + (size_t)row0 * DMODEL + lane * 8) = o;
    }
    {
        __nv_bfloat162 p0 = __floats2bfloat162_rn(c0 * invB * g0.x + b0.x, c1 * invB * g0.y + b0.y);
        __nv_bfloat162 p1 = __floats2bfloat162_rn(c2 * invB * g0.z + b0.z, c3 * invB * g0.w + b0.w);
        __nv_bfloat162 p2 = __floats2bfloat162_rn(c4 * invB * g1.x + b1.x, c5 * invB * g1.y + b1.y);
        __nv_bfloat162 p3 = __floats2bfloat162_rn(c6 * invB * g1.z + b1.z, c7 * invB * g1.w + b1.w);
        uint4 o;
        o.x = *reinterpret_cast<uint32_t*>(&p0);
        o.y = *reinterpret_cast<uint32_t*>(&p1);
        o.z = *reinterpret_cast<uint32_t*>(&p2);
        o.w = *reinterpret_cast<uint32_t*>(&p3);
        *reinterpret_cast<uint4*>(y + (size_t)(row0 + 1) * DMODEL + lane * 8) = o;
    }
}

// ---------------- fused per-head QKV projection, full SEQ per block ----------
// grid (B*H), 256 threads = 8 warps x 25 rows. q pre-scaled by log2e/sqrt(DH).
__global__ void qkv_kernel(const bf16* __restrict__ x1,
                           const float* __restrict__ wq, const float* __restrict__ bq,
                           const float* __restrict__ wk, const float* __restrict__ bk,
                           const float* __restrict__ wv, const float* __restrict__ bv,
                           bf16* __restrict__ q, bf16* __restrict__ k, bf16* __restrict__ v)
{
    __shared__ float wqs[32 * 33], wks[32 * 33], wvs[32 * 33];
    __shared__ float bqs[32], bks[32], bvs[32];
    __shared__ float xr[200 * 33];
    const int nh = blockIdx.x;
    const int n = nh / NHEAD, h = nh % NHEAD;
    const int t = threadIdx.x;
    const float* wqg = wq + (size_t)h * DH * DH;
    const float* wkg = wk + (size_t)h * DH * DH;
    const float* wvg = wv + (size_t)h * DH * DH;

    for (int i = t; i < DH * DH; i += 256) {
        int e = i >> 5, d = i & 31;
        wqs[e * 33 + d] = wqg[i];
        wks[e * 33 + d] = wkg[i];
        wvs[e * 33 + d] = wvg[i];
    }
    if (t < 32) { bqs[t] = bq[h * DH + t]; bks[t] = bk[h * DH + t]; bvs[t] = bv[h * DH + t]; }

    for (int i = t; i < SEQ * 32; i += 256) {
        int r = i >> 5, d = i & 31;
        xr[r * 33 + d] = __bfloat162float(x1[((size_t)n * SEQ + r) * DMODEL + h * DH + d]);
    }
    __syncthreads();

    const float scale = 0.17677669529663689f * 1.4426950408889634f;  // log2e/sqrt(32)
    const int wr = (t >> 5) * 25, lane = t & 31;
    const float bqv = bqs[lane], bkv = bks[lane], bvv = bvs[lane];
#pragma unroll 5
    for (int r = 0; r < 25; r++) {
        int s = wr + r;
        if (s >= SEQ) break;
        const float* xp = xr + s * 33;
        float aq = bqv, ak = bkv, av = bvv;
#pragma unroll
        for (int d = 0; d < 32; d++) {
            float xv = xp[d];
            aq += xv * wqs[lane * 33 + d];
            ak += xv * wks[lane * 33 + d];
            av += xv * wvs[lane * 33 + d];
        }
        size_t oidx = ((size_t)nh * SEQ + s) * DH + lane;
        q[oidx] = __float2bfloat16(aq * scale);
        k[oidx] = __float2bfloat16(ak);
        v[oidx] = __float2bfloat16(av);
    }
}

// ---------------- tensor-core flash attention per (n,h), base-2 softmax -----
#define SPAD 224
#define NKT  7
#define KSTR 20
#define VSTR 116

__global__ void __launch_bounds__(224) attn_tc(const bf16* __restrict__ q,
                                               const bf16* __restrict__ k,
                                               const bf16* __restrict__ v,
                                               bf16* __restrict__ o)
{
    __shared__ uint32_t Ks[SPAD * KSTR];
    __shared__ uint32_t VT[32 * VSTR];

    const int nh = blockIdx.x;
    const int n = nh / NHEAD, h = nh % NHEAD;
    const int t = threadIdx.x, warp = t >> 5, lane = t & 31;
    const int g = lane >> 2, q4 = lane & 3;
    const size_t base = (size_t)nh * SEQ * DH;
    const uint32_t* q32 = (const uint32_t*)(q + base);
    const uint32_t* k32 = (const uint32_t*)(k + base);
    const uint32_t* v32 = (const uint32_t*)(v + base);

    for (int i = t; i < SPAD * 16; i += 224) {
        int r = i >> 4, c = i & 15;
        Ks[r * KSTR + c] = (r < SEQ) ? k32[r * 16 + c] : 0u;
    }
    bf16* VT16 = (bf16*)VT;
    for (int i = t; i < SPAD * 16; i += 224) {
        int tt = i >> 4, c = i & 15;
        uint32_t val = (tt < SEQ) ? v32[tt * 16 + c] : 0u;
        __nv_bfloat162 pr = *reinterpret_cast<__nv_bfloat162*>(&val);
        VT16[(2 * c)     * (VSTR * 2) + tt] = pr.x;
        VT16[(2 * c + 1) * (VSTR * 2) + tt] = pr.y;
    }
    __syncthreads();

    const int qbase = warp * 32;
    uint32_t qf[2][2][4];
#pragma unroll
    for (int mi = 0; mi < 2; mi++) {
        int r0 = qbase + mi * 16 + g, r1 = r0 + 8;
        bool v0 = r0 < SEQ, v1 = r1 < SEQ;
#pragma unroll
        for (int ks = 0; ks < 2; ks++) {
            qf[mi][ks][0] = v0 ? q32[r0 * 16 + ks * 8 + q4]     : 0u;
            qf[mi][ks][1] = v1 ? q32[r1 * 16 + ks * 8 + q4]     : 0u;
            qf[mi][ks][2] = v0 ? q32[r0 * 16 + ks * 8 + q4 + 4] : 0u;
            qf[mi][ks][3] = v1 ? q32[r1 * 16 + ks * 8 + q4 + 4] : 0u;
        }
    }

    float Oa[2][4][4];
#pragma unroll
    for (int mi = 0; mi < 2; mi++)
#pragma unroll
        for (int ne = 0; ne < 4; ne++)
#pragma unroll
            for (int e = 0; e < 4; e++) Oa[mi][ne][e] = 0.f;
    float m_[2][2] = {{-1e30f, -1e30f}, {-1e30f, -1e30f}};
    float l_[2][2] = {{0.f, 0.f}, {0.f, 0.f}};

    auto body = [&](int kt, bool last_mask) {
        float sc[2][4][4];
#pragma unroll
        for (int mi = 0; mi < 2; mi++)
#pragma unroll
            for (int ni = 0; ni < 4; ni++)
#pragma unroll
                for (int e = 0; e < 4; e++) sc[mi][ni][e] = 0.f;

        uint32_t kf[2][4][2];
#pragma unroll
        for (int ks = 0; ks < 2; ks++)
#pragma unroll
            for (int ni = 0; ni < 4; ni++) {
                int r = kt * 32 + ni * 8 + g;
                kf[ks][ni][0] = Ks[r * KSTR + ks * 8 + q4];
                kf[ks][ni][1] = Ks[r * KSTR + ks * 8 + q4 + 4];
            }
#pragma unroll
        for (int mi = 0; mi < 2; mi++)
#pragma unroll
            for (int ni = 0; ni < 4; ni++)
#pragma unroll
                for (int ks = 0; ks < 2; ks++)
                    mma_bf16(sc[mi][ni], qf[mi][ks], kf[ks][ni]);

        if (last_mask) {
#pragma unroll
            for (int mi = 0; mi < 2; mi++)
#pragma unroll
                for (int ni = 0; ni < 4; ni++) {
                    int col = kt * 32 + ni * 8 + q4 * 2;
#pragma unroll
                    for (int hf = 0; hf < 2; hf++) {
                        if (col     >= SEQ) sc[mi][ni][hf * 2]     = -1e30f;
                        if (col + 1 >= SEQ) sc[mi][ni][hf * 2 + 1] = -1e30f;
                    }
                }
        }

#pragma unroll
        for (int mi = 0; mi < 2; mi++) {
#pragma unroll
            for (int hf = 0; hf < 2; hf++) {
                float mx = fmaxf(fmaxf(sc[mi][0][hf * 2], sc[mi][0][hf * 2 + 1]),
                                 fmaxf(sc[mi][1][hf * 2], sc[mi][1][hf * 2 + 1]));
                mx = fmaxf(mx, fmaxf(fmaxf(sc[mi][2][hf * 2], sc[mi][2][hf * 2 + 1]),
                                     fmaxf(sc[mi][3][hf * 2], sc[mi][3][hf * 2 + 1])));
                mx = fmaxf(mx, __shfl_xor_sync(0xffffffffu, mx, 1));
                mx = fmaxf(mx, __shfl_xor_sync(0xffffffffu, mx, 2));
                float mnew = fmaxf(m_[mi][hf], mx);
                float f = ex2f(m_[mi][hf] - mnew);
                m_[mi][hf] = mnew;
                float rs = 0.f;
#pragma unroll
                for (int ni = 0; ni < 4; ni++) {
                    float p0 = ex2f(sc[mi][ni][hf * 2]     - mnew);
                    float p1 = ex2f(sc[mi][ni][hf * 2 + 1] - mnew);
                    sc[mi][ni][hf * 2]     = p0;
                    sc[mi][ni][hf * 2 + 1] = p1;
                    rs += p0 + p1;
                }
                rs += __shfl_xor_sync(0xffffffffu, rs, 1);
                rs += __shfl_xor_sync(0xffffffffu, rs, 2);
                l_[mi][hf] = l_[mi][hf] * f + rs;
#pragma unroll
                for (int ne = 0; ne < 4; ne++) {
                    Oa[mi][ne][hf * 2]     *= f;
                    Oa[mi][ne][hf * 2 + 1] *= f;
                }
            }
        }

        uint32_t pa[2][2][4];
#pragma unroll
        for (int mi = 0; mi < 2; mi++)
#pragma unroll
            for (int ks = 0; ks < 2; ks++) {
                __nv_bfloat162 t0 = __floats2bfloat162_rn(sc[mi][2 * ks][0],     sc[mi][2 * ks][1]);
                __nv_bfloat162 t1 = __floats2bfloat162_rn(sc[mi][2 * ks][2],     sc[mi][2 * ks][3]);
                __nv_bfloat162 t2 = __floats2bfloat162_rn(sc[mi][2 * ks + 1][0], sc[mi][2 * ks + 1][1]);
                __nv_bfloat162 t3 = __floats2bfloat162_rn(sc[mi][2 * ks + 1][2], sc[mi][2 * ks + 1][3]);
                pa[mi][ks][0] = *reinterpret_cast<uint32_t*>(&t0);
                pa[mi][ks][1] = *reinterpret_cast<uint32_t*>(&t1);
                pa[mi][ks][2] = *reinterpret_cast<uint32_t*>(&t2);
                pa[mi][ks][3] = *reinterpret_cast<uint32_t*>(&t3);
            }

        uint32_t vf[2][4][2];
#pragma unroll
        for (int ks = 0; ks < 2; ks++)
#pragma unroll
            for (int ne = 0; ne < 4; ne++) {
                int r = ne * 8 + g;
                int cu = kt * 16 + ks * 8 + q4;
                vf[ks][ne][0] = VT[r * VSTR + cu];
                vf[ks][ne][1] = VT[r * VSTR + cu + 4];
            }
#pragma unroll
        for (int mi = 0; mi < 2; mi++)
#pragma unroll
            for (int ne = 0; ne < 4; ne++)
#pragma unroll
                for (int ks = 0; ks < 2; ks++)
                    mma_bf16(Oa[mi][ne], pa[mi][ks], vf[ks][ne]);
    };

    for (int kt = 0; kt < NKT - 1; kt++) body(kt, false);
    body(NKT - 1, true);

#pragma unroll
    for (int mi = 0; mi < 2; mi++) {
#pragma unroll
        for (int hf = 0; hf < 2; hf++) {
            int row = qbase + mi * 16 + hf * 8 + g;
            if (row >= SEQ) continue;
            float inv = 1.f / l_[mi][hf];
            bf16* op = o + ((size_t)n * SEQ + row) * DMODEL + h * DH;
#pragma unroll
            for (int ne = 0; ne < 4; ne++) {
                __nv_bfloat162 p = __floats2bfloat162_rn(Oa[mi][ne][hf * 2] * inv,
                                                         Oa[mi][ne][hf * 2 + 1] * inv);
                *reinterpret_cast<uint32_t*>(op + ne * 8 + q4 * 2) = *reinterpret_cast<uint32_t*>(&p);
            }
        }
    }
}

// ---------------- softmax over precomputed logits ---------------------------
__global__ void softmax_head_kernel(const float* __restrict__ logits_in,
                                    float* __restrict__ out)
{
    __shared__ float logits[OUTC];
    __shared__ float red[8];
    const int n = blockIdx.x;
    const int t = threadIdx.x, wid = t >> 5, lane = t & 31;

    for (int j = t; j < OUTC; j += 256) logits[j] = logits_in[(size_t)n * OUTP + j];
    __syncthreads();

    float mx = -1e30f;
    for (int j = t; j < OUTC; j += 256) mx = fmaxf(mx, logits[j]);
#pragma unroll
    for (int off = 16; off; off >>= 1) mx = fmaxf(mx, __shfl_xor_sync(0xffffffffu, mx, off));
    if (lane == 0) red[wid] = mx;
    __syncthreads();
    float bm = -1e30f;
#pragma unroll
    for (int i = 0; i < 8; i++) bm = fmaxf(bm, red[i]);
    __syncthreads();

    float sum = 0.f;
    for (int j = t; j < OUTC; j += 256) {
        float e = __expf(logits[j] - bm);
        logits[j] = e;
        sum += e;
    }
#pragma unroll
    for (int off = 16; off; off >>= 1) sum += __shfl_xor_sync(0xffffffffu, sum, off);
    if (lane == 0) red[wid] = sum;
    __syncthreads();
    float bs = 0.f;
#pragma unroll
    for (int i = 0; i < 8; i++) bs += red[i];
    float inv = 1.f / bs;
    __syncthreads();
    for (int j = t; j < OUTC; j += 256) out[(size_t)n * OUTC + j] = logits[j] * inv;
}

// ---------------- launcher ----------------
extern "C" void kernel_launch(void* const* d_in, const int* in_sizes, int n_in,
                              void* d_out, int out_size)
{
    const float* images  = (const float*)d_in[0];
    const float* w_map   = (const float*)d_in[1];
    const float* b_map   = (const float*)d_in[2];
    const float* cls_tok = (const float*)d_in[3];
    const float* norm1_g = (const float*)d_in[4];
    const float* norm1_b = (const float*)d_in[5];
    const float* wq      = (const float*)d_in[6];
    const float* bq      = (const float*)d_in[7];
    const float* wk      = (const float*)d_in[8];
    const float* bk      = (const float*)d_in[9];
    const float* wv      = (const float*)d_in[10];
    const float* bv      = (const float*)d_in[11];
    const float* w_last  = (const float*)d_in[12];
    const float* b_last  = (const float*)d_in[13];
    const float* norm2_g = (const float*)d_in[14];
    const float* norm2_b = (const float*)d_in[15];
    const float* w_mlp1  = (const float*)d_in[16];
    const float* b_mlp1  = (const float*)d_in[17];
    const float* w_mlp2  = (const float*)d_in[18];
    const float* b_mlp2  = (const float*)d_in[19];
    const float* w_out   = (const float*)d_in[20];
    const float* b_out   = (const float*)d_in[21];
    float* out = (float*)d_out;

    bf16 *patches, *x1b, *qb, *kb, *vb, *ob, *h1b;
    bf16 *wmapb, *wlastb, *wmlp1b, *wmlp2b, *wcat, *ccat;
    float *X, *pe, *bout_pad, *logits;
    cudaGetSymbolAddress((void**)&patches, g_patches_b);
    cudaGetSymbolAddress((void**)&X,   g_X);
    cudaGetSymbolAddress((void**)&x1b, g_x1b);
    cudaGetSymbolAddress((void**)&qb,  g_qb);
    cudaGetSymbolAddress((void**)&kb,  g_kb);
    cudaGetSymbolAddress((void**)&vb,  g_vb);
    cudaGetSymbolAddress((void**)&ob,  g_ob);
    cudaGetSymbolAddress((void**)&h1b, g_h1b);
    cudaGetSymbolAddress((void**)&pe,  g_pe);
    cudaGetSymbolAddress((void**)&wmapb,  g_wmapb);
    cudaGetSymbolAddress((void**)&wlastb, g_wlastb);
    cudaGetSymbolAddress((void**)&wmlp1b, g_wmlp1b);
    cudaGetSymbolAddress((void**)&wmlp2b, g_wmlp2b);
    cudaGetSymbolAddress((void**)&wcat, g_wout_cat);
    cudaGetSymbolAddress((void**)&ccat, g_cls_cat);
    cudaGetSymbolAddress((void**)&bout_pad, g_bout_pad);
    cudaGetSymbolAddress((void**)&logits,   g_logits);

    cudaFuncSetAttribute(gemm_bf<0, false, false, true >, cudaFuncAttributeMaxDynamicSharedMemorySize, GEMM_SMEM);
    cudaFuncSetAttribute(gemm_bf<0, true,  false, false>, cudaFuncAttributeMaxDynamicSharedMemorySize, GEMM_SMEM);
    cudaFuncSetAttribute(gemm_bf<1, false, true,  false>, cudaFuncAttributeMaxDynamicSharedMemorySize, GEMM_SMEM);
    cudaFuncSetAttribute(gemm_bf<0, false, false, false>, cudaFuncAttributeMaxDynamicSharedMemorySize, GEMM_SMEM);

    // 0) weight conversion to bf16 (+ concatenated head weights)
    {
        int n0 = DMODEL * IN_D;
        int n1 = NLAYER * DMODEL * DMODEL;
        int n3 = NLAYER * 4 * DMODEL * DMODEL;
        int totf4 = (n0 + n1 + 2 * n3) / 4;
        cvt_all_kernel<<<(totf4 + 255) / 256, 256>>>(
            w_map, wmapb, n0, w_last, wlastb, n1,
            w_mlp1, wmlp1b, n3, w_mlp2, wmlp2b, n3);
        int hw = OUTP * DMODEL / 4;
        cvt_head_kernel<<<(hw + 255) / 256, 256>>>(w_out, b_out, wcat, bout_pad);
    }

    // 1) patches + PE table
    {
        int tot = BATCH * NP * IN_D / 4;
        patch_kernel<<<(tot + 255) / 256, 256>>>(images, patches);
        int pt = SEQ * DMODEL;
        pe_kernel<<<(pt + 255) / 256, 256>>>(pe);
    }

    // 2) patch-embed GEMM fused with assemble
    gemm_bf<0, false, false, true><<<dim3(DMODEL / 128, (BATCH * NP) / 128), 256, GEMM_SMEM>>>(
        patches, wmapb, b_map, nullptr, pe, X, BATCH * NP, DMODEL, IN_D);

    // 2b) cls rows
    cls_kernel<<<(BATCH * DMODEL + 255) / 256, 256>>>(cls_tok, pe, X);

    const int MROWS = BATCH * SEQ;   // 25216 = 16*1576

    for (int l = 0; l < NLAYER; l++) {
        ln_kernel<<<MROWS / 16, 256>>>(X, norm1_g + l * DMODEL, norm1_b + l * DMODEL, x1b);

        qkv_kernel<<<BATCH * NHEAD, 256>>>(
            x1b,
            wq + (size_t)l * NHEAD * DH * DH, bq + (size_t)l * NHEAD * DH,
            wk + (size_t)l * NHEAD * DH * DH, bk + (size_t)l * NHEAD * DH,
            wv + (size_t)l * NHEAD * DH * DH, bv + (size_t)l * NHEAD * DH,
            qb, kb, vb);

        attn_tc<<<BATCH * NHEAD, 224>>>(qb, kb, vb, ob);

        gemm_bf<0, true, false, false><<<dim3(DMODEL / 128, MROWS / 128), 256, GEMM_SMEM>>>(
            ob, wlastb + (size_t)l * DMODEL * DMODEL, b_last + l * DMODEL, X, nullptr, X,
            MROWS, DMODEL, DMODEL);

        ln_kernel<<<MROWS / 16, 256>>>(X, norm2_g + l * DMODEL, norm2_b + l * DMODEL, x1b);

        gemm_bf<1, false, true, false><<<dim3((4 * DMODEL) / 128, MROWS / 128), 256, GEMM_SMEM>>>(
            x1b, wmlp1b + (size_t)l * 4 * DMODEL * DMODEL, b_mlp1 + l * 4 * DMODEL,
            nullptr, nullptr, h1b, MROWS, 4 * DMODEL, DMODEL);

        gemm_bf<0, true, false, false><<<dim3(DMODEL / 128, MROWS / 128), 256, GEMM_SMEM>>>(
            h1b, wmlp2b + (size_t)l * 4 * DMODEL * DMODEL, b_mlp2 + l * DMODEL, X, nullptr, X,
            MROWS, DMODEL, 4 * DMODEL);
    }

    // head: cls concat extraction -> single compensated bf16 GEMM (K=768) -> softmax
    cls_extract_kernel<<<(BATCH * DMODEL / 4 + 255) / 256, 256>>>(X, ccat);
    gemm_bf<0, false, false, false><<<dim3(OUTP / 128, BATCH / 128), 256, GEMM_SMEM>>>(
        ccat, wcat, bout_pad, nullptr, nullptr, logits, BATCH, OUTP, HKDIM);
    softmax_head_kernel<<<BATCH, 256>>>(logits, out);
}